// round 3
// baseline (speedup 1.0000x reference)
#include <cuda_runtime.h>
#include <cstdint>

#define T_TOK 16384
#define H_DIM 1024
#define I_DIM 2048
#define N_EXP 16
#define TOPK  2
#define NROWS (T_TOK * TOPK)

// ---------------- scratch (static __device__; no allocations allowed) ----------------
__device__ int   g_count[N_EXP];
__device__ int   g_cursor[N_EXP];
__device__ int   g_offset[N_EXP + 1];
__device__ int   g_e0[T_TOK];
__device__ int   g_e1[T_TOK];
__device__ float g_w0[T_TOK];
__device__ float g_w1[T_TOK];
__device__ int   g_token_of_row[NROWS];
__device__ float g_w_of_row[NROWS];
__device__ int   g_rows_of_token[NROWS];          // [t][k]
__device__ float g_xg[(size_t)NROWS * H_DIM];     // gathered inputs   134 MB
__device__ float g_g [(size_t)NROWS * I_DIM];     // gate out -> h     268 MB
__device__ float g_u [(size_t)NROWS * I_DIM];     // up out            268 MB
__device__ float g_y [(size_t)NROWS * H_DIM];     // down out          134 MB

// ---------------- kernel 0: zero counters (graph replays need re-init) ----------------
__global__ void zero_kernel() {
    int i = threadIdx.x;
    if (i < N_EXP) { g_count[i] = 0; g_cursor[i] = 0; }
}

// ---------------- router: one warp per token ----------------
// logits = x @ w_gate; top-2; weights = renormalized softmax over top-2
// (softmax denominator cancels: w0 = 1/(1+e^{l2-l1}))
__global__ void router_kernel(const float* __restrict__ x, const float* __restrict__ wg) {
    int warp = (blockIdx.x * blockDim.x + threadIdx.x) >> 5;
    int lane = threadIdx.x & 31;
    if (warp >= T_TOK) return;
    int t = warp;
    const float* xr = x + (size_t)t * H_DIM;
    int e  = lane & 15;
    int k0 = (lane >> 4) * (H_DIM / 2);

    float acc = 0.f;
    for (int k = k0; k < k0 + H_DIM / 2; k++)
        acc = fmaf(xr[k], wg[k * N_EXP + e], acc);
    acc += __shfl_xor_sync(0xffffffffu, acc, 16);   // full logit on all lanes

    // top-1 (value, index) butterfly; ties -> lower index (matches top_k)
    float v = acc; int idx = e;
    #pragma unroll
    for (int s = 16; s; s >>= 1) {
        float ov = __shfl_xor_sync(0xffffffffu, v, s);
        int   oi = __shfl_xor_sync(0xffffffffu, idx, s);
        if (ov > v || (ov == v && oi < idx)) { v = ov; idx = oi; }
    }
    float l1 = v; int i1 = idx;

    // top-2: mask out winner, reduce again
    v = (e == i1) ? -1e30f : acc; idx = e;
    #pragma unroll
    for (int s = 16; s; s >>= 1) {
        float ov = __shfl_xor_sync(0xffffffffu, v, s);
        int   oi = __shfl_xor_sync(0xffffffffu, idx, s);
        if (ov > v || (ov == v && oi < idx)) { v = ov; idx = oi; }
    }
    float l2 = v; int i2 = idx;

    if (lane == 0) {
        float r  = __expf(l2 - l1);        // <= 1
        float w0 = 1.f / (1.f + r);
        g_e0[t] = i1; g_e1[t] = i2;
        g_w0[t] = w0; g_w1[t] = 1.f - w0;
        atomicAdd(&g_count[i1], 1);
        atomicAdd(&g_count[i2], 1);
    }
}

// ---------------- exclusive scan over 16 expert counts ----------------
__global__ void scan_kernel() {
    if (threadIdx.x == 0) {
        int o = 0;
        for (int e = 0; e < N_EXP; e++) { g_offset[e] = o; o += g_count[e]; }
        g_offset[N_EXP] = o;   // == NROWS always
    }
}

// ---------------- assign rows (expert-major, order-irrelevant) ----------------
__global__ void assign_kernel() {
    int t = blockIdx.x * blockDim.x + threadIdx.x;
    if (t >= T_TOK) return;
    int e0 = g_e0[t];
    int r0 = g_offset[e0] + atomicAdd(&g_cursor[e0], 1);
    g_token_of_row[r0] = t; g_w_of_row[r0] = g_w0[t]; g_rows_of_token[2 * t] = r0;
    int e1 = g_e1[t];
    int r1 = g_offset[e1] + atomicAdd(&g_cursor[e1], 1);
    g_token_of_row[r1] = t; g_w_of_row[r1] = g_w1[t]; g_rows_of_token[2 * t + 1] = r1;
}

// ---------------- gather token rows into expert-contiguous buffer ----------------
__global__ void gather_kernel(const float* __restrict__ x) {
    int row = blockIdx.x;
    int t = g_token_of_row[row];
    const float4* src = (const float4*)(x + (size_t)t * H_DIM);
    float4* dst = (float4*)(g_xg + (size_t)row * H_DIM);
    for (int i = threadIdx.x; i < H_DIM / 4; i += blockDim.x) dst[i] = src[i];
}

// ---------------- grouped SGEMM: 128x128 tile, BK=8, 8x8/thread, packed f32x2 FMA ----
// MODE 0: g_g = g_xg @ w_gate_proj[e]   (KD=1024, N=2048)
// MODE 1: g_u = g_xg @ w_up_proj[e]     (KD=1024, N=2048)
// MODE 2: g_y = h    @ w_down_proj[e]   (KD=2048, N=1024), row-scaled by routing wt
template <int MODE>
__global__ __launch_bounds__(256, 2) void sgemm_kernel(const float* __restrict__ Ball) {
    constexpr int KD = (MODE == 2) ? I_DIM : H_DIM;
    constexpr int N  = (MODE == 2) ? H_DIM : I_DIM;

    const int e    = blockIdx.z;
    const int m0   = g_offset[e];
    const int rows = g_offset[e + 1] - m0;
    const int bm   = blockIdx.y * 128;
    if (bm >= rows) return;
    const int bn = blockIdx.x * 128;

    const float* A = (MODE == 2) ? g_g : g_xg;
    float*       C = (MODE == 0) ? g_g : (MODE == 1) ? g_u : g_y;
    const float* B = Ball + (size_t)e * KD * N;

    __shared__ __align__(16) float sA[8][128];   // transposed A tile
    __shared__ __align__(16) float sB[8][128];

    const int tid  = threadIdx.x;
    const int arow = tid >> 1;            // 0..127
    const int acol = (tid & 1) << 2;      // 0 or 4
    const int brow = tid >> 5;            // 0..7
    const int bcol = (tid & 31) << 2;     // 0..124
    const int tm   = (tid >> 4) << 3;     // 0..120
    const int tn   = (tid & 15) << 3;     // 0..120

    const bool aval = (bm + arow) < rows;
    const float* Aptr = A + (size_t)(m0 + bm + arow) * KD + acol;
    const float* Bptr = B + (size_t)brow * N + bn + bcol;

    unsigned long long acc[8][4];
    #pragma unroll
    for (int i = 0; i < 8; i++)
        #pragma unroll
        for (int j = 0; j < 4; j++) acc[i][j] = 0ull;

    for (int k0 = 0; k0 < KD; k0 += 8) {
        float4 av = make_float4(0.f, 0.f, 0.f, 0.f);
        if (aval) av = *(const float4*)(Aptr + k0);
        float4 bv = *(const float4*)(Bptr + (size_t)k0 * N);
        sA[acol + 0][arow] = av.x;
        sA[acol + 1][arow] = av.y;
        sA[acol + 2][arow] = av.z;
        sA[acol + 3][arow] = av.w;
        *(float4*)&sB[brow][bcol] = bv;
        __syncthreads();

        #pragma unroll
        for (int kk = 0; kk < 8; kk++) {
            unsigned long long b2[4];
            const unsigned long long* bp = (const unsigned long long*)&sB[kk][tn];
            b2[0] = bp[0]; b2[1] = bp[1]; b2[2] = bp[2]; b2[3] = bp[3];
            #pragma unroll
            for (int i = 0; i < 8; i++) {
                unsigned int au = __float_as_uint(sA[kk][tm + i]);
                unsigned long long a2;
                asm("mov.b64 %0, {%1, %1};" : "=l"(a2) : "r"(au));
                #pragma unroll
                for (int jp = 0; jp < 4; jp++)
                    asm("fma.rn.f32x2 %0, %1, %2, %3;"
                        : "=l"(acc[i][jp])
                        : "l"(a2), "l"(b2[jp]), "l"(acc[i][jp]));
            }
        }
        __syncthreads();
    }

    #pragma unroll
    for (int i = 0; i < 8; i++) {
        int gr = bm + tm + i;
        if (gr < rows) {
            float scale = 1.f;
            if (MODE == 2) scale = g_w_of_row[m0 + gr];
            float out[8];
            #pragma unroll
            for (int jp = 0; jp < 4; jp++) {
                unsigned int lo, hi;
                asm("mov.b64 {%0, %1}, %2;" : "=r"(lo), "=r"(hi) : "l"(acc[i][jp]));
                out[2 * jp]     = __uint_as_float(lo) * scale;
                out[2 * jp + 1] = __uint_as_float(hi) * scale;
            }
            float* cp = C + (size_t)(m0 + gr) * N + bn + tn;
            *(float4*)cp       = make_float4(out[0], out[1], out[2], out[3]);
            *(float4*)(cp + 4) = make_float4(out[4], out[5], out[6], out[7]);
        }
    }
}

// ---------------- h = u * silu(g), in place into g_g ----------------
__global__ void silu_mul_kernel() {
    size_t n      = (size_t)NROWS * I_DIM / 4;
    size_t idx    = (size_t)blockIdx.x * blockDim.x + threadIdx.x;
    size_t stride = (size_t)gridDim.x * blockDim.x;
    float4*       gg = (float4*)g_g;
    const float4* gu = (const float4*)g_u;
    for (; idx < n; idx += stride) {
        float4 g = gg[idx];
        float4 u = gu[idx];
        g.x = u.x * g.x / (1.f + __expf(-g.x));
        g.y = u.y * g.y / (1.f + __expf(-g.y));
        g.z = u.z * g.z / (1.f + __expf(-g.z));
        g.w = u.w * g.w / (1.f + __expf(-g.w));
        gg[idx] = g;
    }
}

// ---------------- combine: out[t] = y[row(t,0)] + y[row(t,1)] (weights pre-applied) --
__global__ void combine_kernel(float* __restrict__ out) {
    int t  = blockIdx.x;
    int r0 = g_rows_of_token[2 * t];
    int r1 = g_rows_of_token[2 * t + 1];
    const float4* y0 = (const float4*)(g_y + (size_t)r0 * H_DIM);
    const float4* y1 = (const float4*)(g_y + (size_t)r1 * H_DIM);
    float4* o = (float4*)(out + (size_t)t * H_DIM);
    for (int i = threadIdx.x; i < H_DIM / 4; i += blockDim.x) {
        float4 a = y0[i], b = y1[i];
        o[i] = make_float4(a.x + b.x, a.y + b.y, a.z + b.z, a.w + b.w);
    }
}

// ---------------- launch ----------------
extern "C" void kernel_launch(void* const* d_in, const int* in_sizes, int n_in,
                              void* d_out, int out_size) {
    const float* x   = (const float*)d_in[0];  // [T, H]
    const float* wg  = (const float*)d_in[1];  // [H, E]
    const float* wgp = (const float*)d_in[2];  // [E, H, I]
    const float* wup = (const float*)d_in[3];  // [E, H, I]
    const float* wdp = (const float*)d_in[4];  // [E, I, H]
    float* out = (float*)d_out;                // [T, H]

    zero_kernel<<<1, 32>>>();
    router_kernel<<<T_TOK / 8, 256>>>(x, wg);
    scan_kernel<<<1, 1>>>();
    assign_kernel<<<T_TOK / 256, 256>>>();
    gather_kernel<<<NROWS, 128>>>(x);

    dim3 g1(I_DIM / 128, 128, N_EXP);   // grid.y covers worst-case M=16384
    sgemm_kernel<0><<<g1, 256>>>(wgp);
    sgemm_kernel<1><<<g1, 256>>>(wup);
    silu_mul_kernel<<<8192, 256>>>();

    dim3 g2(H_DIM / 128, 128, N_EXP);
    sgemm_kernel<2><<<g2, 256>>>(wdp);
    combine_kernel<<<T_TOK, 256>>>(out);
}

// round 5
// speedup vs baseline: 2.3293x; 2.3293x over previous
#include <cuda_runtime.h>
#include <cuda_bf16.h>
#include <cstdint>

#define T_TOK 16384
#define H_DIM 1024
#define I_DIM 2048
#define N_EXP 16
#define NROWS (T_TOK * 2)

// ---------------- routing scratch ----------------
__device__ int   g_count[N_EXP];
__device__ int   g_cursor[N_EXP];
__device__ int   g_offset[N_EXP + 1];
__device__ int   g_e0[T_TOK];
__device__ int   g_e1[T_TOK];
__device__ float g_w0[T_TOK];
__device__ float g_w1[T_TOK];
__device__ int   g_token_of_row[NROWS];
__device__ float g_w_of_row[NROWS];
__device__ int   g_rows_of_token[NROWS];

// ---------------- data buffers ----------------
__device__ __nv_bfloat16 g_xh[(size_t)NROWS * H_DIM];            // gathered x hi
__device__ __nv_bfloat16 g_xl[(size_t)NROWS * H_DIM];            // gathered x lo
__device__ __nv_bfloat16 g_wgh[(size_t)N_EXP * I_DIM * H_DIM];   // gate_proj^T hi [e][n][k]
__device__ __nv_bfloat16 g_wgl[(size_t)N_EXP * I_DIM * H_DIM];
__device__ __nv_bfloat16 g_wuh[(size_t)N_EXP * I_DIM * H_DIM];   // up_proj^T
__device__ __nv_bfloat16 g_wul[(size_t)N_EXP * I_DIM * H_DIM];
__device__ __nv_bfloat16 g_wdh[(size_t)N_EXP * H_DIM * I_DIM];   // down_proj^T
__device__ __nv_bfloat16 g_wdl[(size_t)N_EXP * H_DIM * I_DIM];
__device__ float         g_gf[(size_t)NROWS * I_DIM];            // gate GEMM out (fp32)
__device__ __nv_bfloat16 g_hh[(size_t)NROWS * I_DIM];            // h = u*silu(g) hi
__device__ __nv_bfloat16 g_hl[(size_t)NROWS * I_DIM];            // h lo
__device__ float         g_y[(size_t)NROWS * H_DIM];             // down out (weighted)

// ---------------- ptx helpers ----------------
__device__ __forceinline__ uint32_t smem_u32(const void* p) {
    uint32_t a;
    asm("{ .reg .u64 t; cvta.to.shared.u64 t, %1; cvt.u32.u64 %0, t; }" : "=r"(a) : "l"(p));
    return a;
}
__device__ __forceinline__ void cp16(uint32_t dst, const void* src, uint32_t sz) {
    asm volatile("cp.async.cg.shared.global [%0], [%1], 16, %2;"
                 :: "r"(dst), "l"(src), "r"(sz));
}
__device__ __forceinline__ void ldm_x4(uint32_t a, uint32_t r[4]) {
    asm volatile("ldmatrix.sync.aligned.m8n8.x4.shared.b16 {%0,%1,%2,%3}, [%4];"
                 : "=r"(r[0]), "=r"(r[1]), "=r"(r[2]), "=r"(r[3]) : "r"(a));
}
__device__ __forceinline__ void ldm_x2(uint32_t a, uint32_t r[2]) {
    asm volatile("ldmatrix.sync.aligned.m8n8.x2.shared.b16 {%0,%1}, [%2];"
                 : "=r"(r[0]), "=r"(r[1]) : "r"(a));
}
__device__ __forceinline__ void mma_bf16(float* c, const uint32_t* a, const uint32_t* b) {
    asm volatile(
        "mma.sync.aligned.m16n8k16.row.col.f32.bf16.bf16.f32 "
        "{%0,%1,%2,%3}, {%4,%5,%6,%7}, {%8,%9}, {%0,%1,%2,%3};"
        : "+f"(c[0]), "+f"(c[1]), "+f"(c[2]), "+f"(c[3])
        : "r"(a[0]), "r"(a[1]), "r"(a[2]), "r"(a[3]), "r"(b[0]), "r"(b[1]));
}

// ---------------- small kernels (routing path) ----------------
__global__ void zero_kernel() {
    int i = threadIdx.x;
    if (i < N_EXP) { g_count[i] = 0; g_cursor[i] = 0; }
}

__global__ void router_kernel(const float* __restrict__ x, const float* __restrict__ wg) {
    int warp = (blockIdx.x * blockDim.x + threadIdx.x) >> 5;
    int lane = threadIdx.x & 31;
    if (warp >= T_TOK) return;
    int t = warp;
    const float* xr = x + (size_t)t * H_DIM;
    int e  = lane & 15;
    int k0 = (lane >> 4) * (H_DIM / 2);

    float acc = 0.f;
    for (int k = k0; k < k0 + H_DIM / 2; k++)
        acc = fmaf(xr[k], wg[k * N_EXP + e], acc);
    acc += __shfl_xor_sync(0xffffffffu, acc, 16);

    float v = acc; int idx = e;
    #pragma unroll
    for (int s = 16; s; s >>= 1) {
        float ov = __shfl_xor_sync(0xffffffffu, v, s);
        int   oi = __shfl_xor_sync(0xffffffffu, idx, s);
        if (ov > v || (ov == v && oi < idx)) { v = ov; idx = oi; }
    }
    float l1 = v; int i1 = idx;

    v = (e == i1) ? -1e30f : acc; idx = e;
    #pragma unroll
    for (int s = 16; s; s >>= 1) {
        float ov = __shfl_xor_sync(0xffffffffu, v, s);
        int   oi = __shfl_xor_sync(0xffffffffu, idx, s);
        if (ov > v || (ov == v && oi < idx)) { v = ov; idx = oi; }
    }
    float l2 = v; int i2 = idx;

    if (lane == 0) {
        float r  = __expf(l2 - l1);
        float w0 = 1.f / (1.f + r);
        g_e0[t] = i1; g_e1[t] = i2;
        g_w0[t] = w0; g_w1[t] = 1.f - w0;
        atomicAdd(&g_count[i1], 1);
        atomicAdd(&g_count[i2], 1);
    }
}

__global__ void scan_kernel() {
    if (threadIdx.x == 0) {
        int o = 0;
        for (int e = 0; e < N_EXP; e++) { g_offset[e] = o; o += g_count[e]; }
        g_offset[N_EXP] = o;
    }
}

__global__ void assign_kernel() {
    int t = blockIdx.x * blockDim.x + threadIdx.x;
    if (t >= T_TOK) return;
    int e0 = g_e0[t];
    int r0 = g_offset[e0] + atomicAdd(&g_cursor[e0], 1);
    g_token_of_row[r0] = t; g_w_of_row[r0] = g_w0[t]; g_rows_of_token[2 * t] = r0;
    int e1 = g_e1[t];
    int r1 = g_offset[e1] + atomicAdd(&g_cursor[e1], 1);
    g_token_of_row[r1] = t; g_w_of_row[r1] = g_w1[t]; g_rows_of_token[2 * t + 1] = r1;
}

// gather + split x into bf16 hi/lo, expert-sorted rows
__global__ void gather_kernel(const float* __restrict__ x) {
    int row = blockIdx.x;
    int t = g_token_of_row[row];
    const float4* src = (const float4*)(x + (size_t)t * H_DIM);
    __nv_bfloat16* dh = g_xh + (size_t)row * H_DIM;
    __nv_bfloat16* dl = g_xl + (size_t)row * H_DIM;
    for (int i = threadIdx.x; i < H_DIM / 4; i += 128) {
        float4 v = src[i];
        __nv_bfloat16 h0 = __float2bfloat16(v.x);
        __nv_bfloat16 h1 = __float2bfloat16(v.y);
        __nv_bfloat16 h2 = __float2bfloat16(v.z);
        __nv_bfloat16 h3 = __float2bfloat16(v.w);
        __nv_bfloat16 l0 = __float2bfloat16(v.x - __bfloat162float(h0));
        __nv_bfloat16 l1 = __float2bfloat16(v.y - __bfloat162float(h1));
        __nv_bfloat16 l2 = __float2bfloat16(v.z - __bfloat162float(h2));
        __nv_bfloat16 l3 = __float2bfloat16(v.w - __bfloat162float(h3));
        __nv_bfloat162* ph = (__nv_bfloat162*)(dh + i * 4);
        __nv_bfloat162* pl = (__nv_bfloat162*)(dl + i * 4);
        ph[0] = __nv_bfloat162(h0, h1); ph[1] = __nv_bfloat162(h2, h3);
        pl[0] = __nv_bfloat162(l0, l1); pl[1] = __nv_bfloat162(l2, l3);
    }
}

// transpose + split weights: src [E][K][N] fp32 -> dh/dl [E][N][K] bf16
__global__ void convert_w_kernel(const float* __restrict__ src,
                                 __nv_bfloat16* __restrict__ dh,
                                 __nv_bfloat16* __restrict__ dl, int K, int N) {
    __shared__ float t[32][33];
    int e = blockIdx.z, n0 = blockIdx.x * 32, k0 = blockIdx.y * 32;
    int tx = threadIdx.x, ty = threadIdx.y;
    const float* S = src + (size_t)e * K * N;
    #pragma unroll
    for (int i = 0; i < 4; i++)
        t[ty + i * 8][tx] = S[(size_t)(k0 + ty + i * 8) * N + n0 + tx];
    __syncthreads();
    size_t ob = (size_t)e * N * K;
    #pragma unroll
    for (int i = 0; i < 4; i++) {
        int n = n0 + ty + i * 8;
        float v = t[tx][ty + i * 8];
        __nv_bfloat16 h = __float2bfloat16(v);
        float lo = v - __bfloat162float(h);
        dh[ob + (size_t)n * K + k0 + tx] = h;
        dl[ob + (size_t)n * K + k0 + tx] = __float2bfloat16(lo);
    }
}

// ---------------- bf16x3 grouped GEMM on mma.sync (legacy HMMA) ----------------
// CTA tile 128x128, BK=32, 8 warps (warp tile 64x32), cp.async double buffer.
// Stage layout (32 KB): Ah[128x32] @0, Al @8192, Bh[128x32] @16384, Bl @24576.
// SMEM swizzle: 16B chunk c of row r stored at r*64 + ((c ^ ((r>>1)&3))<<4).
// MODE 0: C = x @ wg^T          -> g_gf (fp32)
// MODE 1: u = x @ wu^T; h = u*silu(g) -> g_hh/g_hl (bf16 hi/lo)   [reads g_gf]
// MODE 2: y = h @ wd^T, row-scaled by routing weight -> g_y (fp32)
#define GSMEM 65536

template <int KD>
__device__ __forceinline__ void load_stage(uint32_t sb, int tid,
                                           const __nv_bfloat16* Ah, const __nv_bfloat16* Al,
                                           const __nv_bfloat16* Bh, const __nv_bfloat16* Bl,
                                           int k0, int va) {
    #pragma unroll
    for (int j = 0; j < 2; j++) {
        int u = tid + j * 256;
        int r = u >> 2, c = u & 3;
        uint32_t off  = (uint32_t)(r * 64 + ((c ^ ((r >> 1) & 3)) << 4));
        size_t   gs   = (size_t)r * KD + k0 + c * 8;
        uint32_t asz  = (r < va) ? 16u : 0u;
        cp16(sb + off,         Ah + gs, asz);
        cp16(sb + 8192 + off,  Al + gs, asz);
        cp16(sb + 16384 + off, Bh + gs, 16u);
        cp16(sb + 24576 + off, Bl + gs, 16u);
    }
}

template <int MODE>
__global__ __launch_bounds__(256, 1) void mma_gemm_kernel() {
    constexpr int KD  = (MODE == 2) ? I_DIM : H_DIM;
    constexpr int ND  = (MODE == 2) ? H_DIM : I_DIM;
    constexpr int NCH = KD / 32;

    const int e    = blockIdx.z;
    const int m0   = g_offset[e];
    const int rows = g_offset[e + 1] - m0;
    const int bm   = blockIdx.y * 128;
    if (bm >= rows) return;
    const int bn = blockIdx.x * 128;
    const int va = min(rows - bm, 128);

    extern __shared__ char smem[];
    const uint32_t sbase = smem_u32(smem);
    const int tid  = threadIdx.x;
    const int lane = tid & 31, wid = tid >> 5;
    const int wm = wid >> 2, wn = wid & 3;       // 2 x 4 warp grid

    const __nv_bfloat16 *Ah, *Al, *Bh, *Bl;
    if (MODE == 2) {
        Ah = g_hh + (size_t)(m0 + bm) * KD;  Al = g_hl + (size_t)(m0 + bm) * KD;
        Bh = g_wdh + ((size_t)e * ND + bn) * KD;
        Bl = g_wdl + ((size_t)e * ND + bn) * KD;
    } else {
        Ah = g_xh + (size_t)(m0 + bm) * KD;  Al = g_xl + (size_t)(m0 + bm) * KD;
        if (MODE == 0) {
            Bh = g_wgh + ((size_t)e * ND + bn) * KD;
            Bl = g_wgl + ((size_t)e * ND + bn) * KD;
        } else {
            Bh = g_wuh + ((size_t)e * ND + bn) * KD;
            Bl = g_wul + ((size_t)e * ND + bn) * KD;
        }
    }

    float acc[4][4][4];
    #pragma unroll
    for (int i = 0; i < 4; i++)
        #pragma unroll
        for (int j = 0; j < 4; j++)
            #pragma unroll
            for (int k = 0; k < 4; k++) acc[i][j][k] = 0.f;

    // per-thread ldmatrix address components
    uint32_t a_off[4], a_x[4], b_off[4], b_x[4];
    #pragma unroll
    for (int mt = 0; mt < 4; mt++) {
        int row = wm * 64 + mt * 16 + (lane & 15);
        a_off[mt] = (uint32_t)(row * 64);
        a_x[mt]   = (uint32_t)((row >> 1) & 3);
    }
    #pragma unroll
    for (int nt = 0; nt < 4; nt++) {
        int row = wn * 32 + nt * 8 + (lane & 7);
        b_off[nt] = (uint32_t)(row * 64);
        b_x[nt]   = (uint32_t)((row >> 1) & 3);
    }
    const uint32_t acb = (uint32_t)(lane >> 4);
    const uint32_t bcb = (uint32_t)((lane >> 3) & 1);

    load_stage<KD>(sbase, tid, Ah, Al, Bh, Bl, 0, va);
    asm volatile("cp.async.commit_group;");

    for (int c = 0; c < NCH; c++) {
        if (c + 1 < NCH) {
            load_stage<KD>(sbase + ((c + 1) & 1) * 32768, tid, Ah, Al, Bh, Bl, (c + 1) * 32, va);
            asm volatile("cp.async.commit_group;");
            asm volatile("cp.async.wait_group 1;");
        } else {
            asm volatile("cp.async.wait_group 0;");
        }
        __syncthreads();

        const uint32_t sb = sbase + (c & 1) * 32768;
        #pragma unroll
        for (int s16 = 0; s16 < 2; s16++) {
            uint32_t af[2][4][4], bfr[2][4][2];
            #pragma unroll
            for (int mt = 0; mt < 4; mt++) {
                uint32_t ch = (uint32_t)(2 * s16 + acb) ^ a_x[mt];
                uint32_t ad = sb + a_off[mt] + (ch << 4);
                ldm_x4(ad,        af[0][mt]);
                ldm_x4(ad + 8192, af[1][mt]);
            }
            #pragma unroll
            for (int nt = 0; nt < 4; nt++) {
                uint32_t ch = (uint32_t)(2 * s16 + bcb) ^ b_x[nt];
                uint32_t bd = sb + 16384 + b_off[nt] + (ch << 4);
                ldm_x2(bd,        bfr[0][nt]);
                ldm_x2(bd + 8192, bfr[1][nt]);
            }
            #pragma unroll
            for (int mt = 0; mt < 4; mt++)
                #pragma unroll
                for (int nt = 0; nt < 4; nt++) {
                    mma_bf16(acc[mt][nt], af[0][mt], bfr[0][nt]);  // Ah*Bh
                    mma_bf16(acc[mt][nt], af[0][mt], bfr[1][nt]);  // Ah*Bl
                    mma_bf16(acc[mt][nt], af[1][mt], bfr[0][nt]);  // Al*Bh
                }
        }
        __syncthreads();
    }

    // ---------------- epilogue ----------------
    const int lr = lane >> 2;            // row within 8-row group
    const int lc = (lane & 3) * 2;       // col pair base
    #pragma unroll
    for (int mt = 0; mt < 4; mt++) {
        #pragma unroll
        for (int h2 = 0; h2 < 2; h2++) {
            int r = wm * 64 + mt * 16 + lr + h2 * 8;
            if (r < va) {
                size_t grow = (size_t)(m0 + bm + r);
                if (MODE == 0) {
                    float* C = g_gf + grow * I_DIM + bn;
                    #pragma unroll
                    for (int nt = 0; nt < 4; nt++) {
                        int col = wn * 32 + nt * 8 + lc;
                        float2 v = make_float2(acc[mt][nt][h2 * 2], acc[mt][nt][h2 * 2 + 1]);
                        *(float2*)(C + col) = v;
                    }
                } else if (MODE == 1) {
                    const float* G = g_gf + grow * I_DIM + bn;
                    #pragma unroll
                    for (int nt = 0; nt < 4; nt++) {
                        int col = wn * 32 + nt * 8 + lc;
                        float2 g2 = *(const float2*)(G + col);
                        float u0 = acc[mt][nt][h2 * 2], u1 = acc[mt][nt][h2 * 2 + 1];
                        float hv0 = u0 * g2.x / (1.f + __expf(-g2.x));
                        float hv1 = u1 * g2.y / (1.f + __expf(-g2.y));
                        __nv_bfloat16 hh0 = __float2bfloat16(hv0);
                        __nv_bfloat16 hh1 = __float2bfloat16(hv1);
                        __nv_bfloat16 hl0 = __float2bfloat16(hv0 - __bfloat162float(hh0));
                        __nv_bfloat16 hl1 = __float2bfloat16(hv1 - __bfloat162float(hh1));
                        *(__nv_bfloat162*)(g_hh + grow * I_DIM + bn + col) = __nv_bfloat162(hh0, hh1);
                        *(__nv_bfloat162*)(g_hl + grow * I_DIM + bn + col) = __nv_bfloat162(hl0, hl1);
                    }
                } else {
                    float scale = g_w_of_row[grow];
                    float* C = g_y + grow * H_DIM + bn;
                    #pragma unroll
                    for (int nt = 0; nt < 4; nt++) {
                        int col = wn * 32 + nt * 8 + lc;
                        float2 v = make_float2(acc[mt][nt][h2 * 2] * scale,
                                               acc[mt][nt][h2 * 2 + 1] * scale);
                        *(float2*)(C + col) = v;
                    }
                }
            }
        }
    }
}

// ---------------- combine: out[t] = y[row0] + y[row1] ----------------
__global__ void combine_kernel(float* __restrict__ out) {
    int t  = blockIdx.x;
    int r0 = g_rows_of_token[2 * t];
    int r1 = g_rows_of_token[2 * t + 1];
    const float4* y0 = (const float4*)(g_y + (size_t)r0 * H_DIM);
    const float4* y1 = (const float4*)(g_y + (size_t)r1 * H_DIM);
    float4* o = (float4*)(out + (size_t)t * H_DIM);
    for (int i = threadIdx.x; i < H_DIM / 4; i += blockDim.x) {
        float4 a = y0[i], b = y1[i];
        o[i] = make_float4(a.x + b.x, a.y + b.y, a.z + b.z, a.w + b.w);
    }
}

// ---------------- launch ----------------
extern "C" void kernel_launch(void* const* d_in, const int* in_sizes, int n_in,
                              void* d_out, int out_size) {
    const float* x   = (const float*)d_in[0];  // [T, H]
    const float* wg  = (const float*)d_in[1];  // [H, E]
    const float* wgp = (const float*)d_in[2];  // [E, H, I]
    const float* wup = (const float*)d_in[3];  // [E, H, I]
    const float* wdp = (const float*)d_in[4];  // [E, I, H]
    float* out = (float*)d_out;                // [T, H]

    cudaFuncSetAttribute(mma_gemm_kernel<0>, cudaFuncAttributeMaxDynamicSharedMemorySize, GSMEM);
    cudaFuncSetAttribute(mma_gemm_kernel<1>, cudaFuncAttributeMaxDynamicSharedMemorySize, GSMEM);
    cudaFuncSetAttribute(mma_gemm_kernel<2>, cudaFuncAttributeMaxDynamicSharedMemorySize, GSMEM);

    __nv_bfloat16 *wgh, *wgl, *wuh, *wul, *wdh, *wdl;
    cudaGetSymbolAddress((void**)&wgh, g_wgh);
    cudaGetSymbolAddress((void**)&wgl, g_wgl);
    cudaGetSymbolAddress((void**)&wuh, g_wuh);
    cudaGetSymbolAddress((void**)&wul, g_wul);
    cudaGetSymbolAddress((void**)&wdh, g_wdh);
    cudaGetSymbolAddress((void**)&wdl, g_wdl);

    zero_kernel<<<1, 32>>>();
    router_kernel<<<T_TOK / 8, 256>>>(x, wg);
    scan_kernel<<<1, 1>>>();
    assign_kernel<<<T_TOK / 256, 256>>>();
    gather_kernel<<<NROWS, 128>>>(x);

    dim3 cb(32, 8);
    convert_w_kernel<<<dim3(I_DIM / 32, H_DIM / 32, N_EXP), cb>>>(wgp, wgh, wgl, H_DIM, I_DIM);
    convert_w_kernel<<<dim3(I_DIM / 32, H_DIM / 32, N_EXP), cb>>>(wup, wuh, wul, H_DIM, I_DIM);
    convert_w_kernel<<<dim3(H_DIM / 32, I_DIM / 32, N_EXP), cb>>>(wdp, wdh, wdl, I_DIM, H_DIM);

    mma_gemm_kernel<0><<<dim3(I_DIM / 128, 128, N_EXP), 256, GSMEM>>>();
    mma_gemm_kernel<1><<<dim3(I_DIM / 128, 128, N_EXP), 256, GSMEM>>>();
    mma_gemm_kernel<2><<<dim3(H_DIM / 128, 128, N_EXP), 256, GSMEM>>>();

    combine_kernel<<<T_TOK, 256>>>(out);
}

// round 7
// speedup vs baseline: 2.7030x; 1.1604x over previous
#include <cuda_runtime.h>
#include <cuda_bf16.h>
#include <cstdint>

#define T_TOK 16384
#define H_DIM 1024
#define I_DIM 2048
#define N_EXP 16
#define NROWS (T_TOK * 2)

// ---------------- routing scratch ----------------
__device__ int   g_count[N_EXP];
__device__ int   g_cursor[N_EXP];
__device__ int   g_offset[N_EXP + 1];
__device__ int   g_e0[T_TOK];
__device__ int   g_e1[T_TOK];
__device__ float g_w0[T_TOK];
__device__ float g_w1[T_TOK];
__device__ int   g_token_of_row[NROWS];
__device__ float g_w_of_row[NROWS];
__device__ int   g_rows_of_token[NROWS];

// ---------------- data buffers ----------------
__device__ __nv_bfloat16 g_xh[(size_t)NROWS * H_DIM];
__device__ __nv_bfloat16 g_xl[(size_t)NROWS * H_DIM];
__device__ __nv_bfloat16 g_wgh[(size_t)N_EXP * I_DIM * H_DIM];   // gate^T hi [e][n][k]
__device__ __nv_bfloat16 g_wgl[(size_t)N_EXP * I_DIM * H_DIM];
__device__ __nv_bfloat16 g_wuh[(size_t)N_EXP * I_DIM * H_DIM];   // up^T
__device__ __nv_bfloat16 g_wul[(size_t)N_EXP * I_DIM * H_DIM];
__device__ __nv_bfloat16 g_wdh[(size_t)N_EXP * H_DIM * I_DIM];   // down^T
__device__ __nv_bfloat16 g_wdl[(size_t)N_EXP * H_DIM * I_DIM];
__device__ __nv_bfloat16 g_hh[(size_t)NROWS * I_DIM];
__device__ __nv_bfloat16 g_hl[(size_t)NROWS * I_DIM];
__device__ float         g_y[(size_t)NROWS * H_DIM];

// ---------------- ptx helpers ----------------
__device__ __forceinline__ uint32_t smem_u32(const void* p) {
    uint32_t a;
    asm("{ .reg .u64 t; cvta.to.shared.u64 t, %1; cvt.u32.u64 %0, t; }" : "=r"(a) : "l"(p));
    return a;
}
__device__ __forceinline__ void cp16(uint32_t dst, const void* src, uint32_t sz) {
    asm volatile("cp.async.cg.shared.global [%0], [%1], 16, %2;"
                 :: "r"(dst), "l"(src), "r"(sz));
}
__device__ __forceinline__ void ldm_x4(uint32_t a, uint32_t r[4]) {
    asm volatile("ldmatrix.sync.aligned.m8n8.x4.shared.b16 {%0,%1,%2,%3}, [%4];"
                 : "=r"(r[0]), "=r"(r[1]), "=r"(r[2]), "=r"(r[3]) : "r"(a));
}
__device__ __forceinline__ void ldm_x2(uint32_t a, uint32_t r[2]) {
    asm volatile("ldmatrix.sync.aligned.m8n8.x2.shared.b16 {%0,%1}, [%2];"
                 : "=r"(r[0]), "=r"(r[1]) : "r"(a));
}
__device__ __forceinline__ void mma_bf16(float* c, const uint32_t* a, const uint32_t* b) {
    asm volatile(
        "mma.sync.aligned.m16n8k16.row.col.f32.bf16.bf16.f32 "
        "{%0,%1,%2,%3}, {%4,%5,%6,%7}, {%8,%9}, {%0,%1,%2,%3};"
        : "+f"(c[0]), "+f"(c[1]), "+f"(c[2]), "+f"(c[3])
        : "r"(a[0]), "r"(a[1]), "r"(a[2]), "r"(a[3]), "r"(b[0]), "r"(b[1]));
}

// ---------------- small kernels (routing path) ----------------
__global__ void zero_kernel() {
    int i = threadIdx.x;
    if (i < N_EXP) { g_count[i] = 0; g_cursor[i] = 0; }
}

__global__ void router_kernel(const float* __restrict__ x, const float* __restrict__ wg) {
    int warp = (blockIdx.x * blockDim.x + threadIdx.x) >> 5;
    int lane = threadIdx.x & 31;
    if (warp >= T_TOK) return;
    int t = warp;
    const float* xr = x + (size_t)t * H_DIM;
    int e  = lane & 15;
    int k0 = (lane >> 4) * (H_DIM / 2);

    float acc = 0.f;
    for (int k = k0; k < k0 + H_DIM / 2; k++)
        acc = fmaf(xr[k], wg[k * N_EXP + e], acc);
    acc += __shfl_xor_sync(0xffffffffu, acc, 16);

    float v = acc; int idx = e;
    #pragma unroll
    for (int s = 16; s; s >>= 1) {
        float ov = __shfl_xor_sync(0xffffffffu, v, s);
        int   oi = __shfl_xor_sync(0xffffffffu, idx, s);
        if (ov > v || (ov == v && oi < idx)) { v = ov; idx = oi; }
    }
    float l1 = v; int i1 = idx;

    v = (e == i1) ? -1e30f : acc; idx = e;
    #pragma unroll
    for (int s = 16; s; s >>= 1) {
        float ov = __shfl_xor_sync(0xffffffffu, v, s);
        int   oi = __shfl_xor_sync(0xffffffffu, idx, s);
        if (ov > v || (ov == v && oi < idx)) { v = ov; idx = oi; }
    }
    float l2 = v; int i2 = idx;

    if (lane == 0) {
        float r  = __expf(l2 - l1);
        float w0 = 1.f / (1.f + r);
        g_e0[t] = i1; g_e1[t] = i2;
        g_w0[t] = w0; g_w1[t] = 1.f - w0;
        atomicAdd(&g_count[i1], 1);
        atomicAdd(&g_count[i2], 1);
    }
}

__global__ void scan_kernel() {
    if (threadIdx.x == 0) {
        int o = 0;
        for (int e = 0; e < N_EXP; e++) { g_offset[e] = o; o += g_count[e]; }
        g_offset[N_EXP] = o;
    }
}

__global__ void assign_kernel() {
    int t = blockIdx.x * blockDim.x + threadIdx.x;
    if (t >= T_TOK) return;
    int e0 = g_e0[t];
    int r0 = g_offset[e0] + atomicAdd(&g_cursor[e0], 1);
    g_token_of_row[r0] = t; g_w_of_row[r0] = g_w0[t]; g_rows_of_token[2 * t] = r0;
    int e1 = g_e1[t];
    int r1 = g_offset[e1] + atomicAdd(&g_cursor[e1], 1);
    g_token_of_row[r1] = t; g_w_of_row[r1] = g_w1[t]; g_rows_of_token[2 * t + 1] = r1;
}

__global__ void gather_kernel(const float* __restrict__ x) {
    int row = blockIdx.x;
    int t = g_token_of_row[row];
    const float4* src = (const float4*)(x + (size_t)t * H_DIM);
    __nv_bfloat16* dh = g_xh + (size_t)row * H_DIM;
    __nv_bfloat16* dl = g_xl + (size_t)row * H_DIM;
    for (int i = threadIdx.x; i < H_DIM / 4; i += 128) {
        float4 v = src[i];
        __nv_bfloat16 h0 = __float2bfloat16(v.x);
        __nv_bfloat16 h1 = __float2bfloat16(v.y);
        __nv_bfloat16 h2 = __float2bfloat16(v.z);
        __nv_bfloat16 h3 = __float2bfloat16(v.w);
        __nv_bfloat16 l0 = __float2bfloat16(v.x - __bfloat162float(h0));
        __nv_bfloat16 l1 = __float2bfloat16(v.y - __bfloat162float(h1));
        __nv_bfloat16 l2 = __float2bfloat16(v.z - __bfloat162float(h2));
        __nv_bfloat16 l3 = __float2bfloat16(v.w - __bfloat162float(h3));
        __nv_bfloat162* ph = (__nv_bfloat162*)(dh + i * 4);
        __nv_bfloat162* pl = (__nv_bfloat162*)(dl + i * 4);
        ph[0] = __nv_bfloat162(h0, h1); ph[1] = __nv_bfloat162(h2, h3);
        pl[0] = __nv_bfloat162(l0, l1); pl[1] = __nv_bfloat162(l2, l3);
    }
}

__global__ void convert_w_kernel(const float* __restrict__ src,
                                 __nv_bfloat16* __restrict__ dh,
                                 __nv_bfloat16* __restrict__ dl, int K, int N) {
    __shared__ float t[32][33];
    int e = blockIdx.z, n0 = blockIdx.x * 32, k0 = blockIdx.y * 32;
    int tx = threadIdx.x, ty = threadIdx.y;
    const float* S = src + (size_t)e * K * N;
    #pragma unroll
    for (int i = 0; i < 4; i++)
        t[ty + i * 8][tx] = S[(size_t)(k0 + ty + i * 8) * N + n0 + tx];
    __syncthreads();
    size_t ob = (size_t)e * N * K;
    #pragma unroll
    for (int i = 0; i < 4; i++) {
        int n = n0 + ty + i * 8;
        float v = t[tx][ty + i * 8];
        __nv_bfloat16 h = __float2bfloat16(v);
        float lo = v - __bfloat162float(h);
        dh[ob + (size_t)n * K + k0 + tx] = h;
        dl[ob + (size_t)n * K + k0 + tx] = __float2bfloat16(lo);
    }
}

// ============================================================================
// bf16x3 grouped GEMMs on mma.sync, 3-stage cp.async, 1 sync/chunk.
// SMEM swizzle: 16B chunk c of row r at r*64 + ((c ^ ((r>>1)&3))<<4)  (conflict-free).
// ============================================================================
#define STAGE_F 49152   // fused: Ah,Al,Gh,Gl,Uh,Ul  (6 x 8KB)
#define STAGE_D 32768   // down:  Ah,Al,Bh,Bl        (4 x 8KB)
#define SMEM_F  (3 * STAGE_F)
#define SMEM_D  (3 * STAGE_D)

// copy one 128x32 bf16 sub-tile (8KB) into swizzled SMEM; 2 cp16/thread
__device__ __forceinline__ void load_sub(uint32_t sb, int tid, const __nv_bfloat16* src,
                                         size_t rstride, int k0, int valid) {
    #pragma unroll
    for (int j = 0; j < 2; j++) {
        int u = tid + j * 256;
        int r = u >> 2, c = u & 3;
        uint32_t off = (uint32_t)(r * 64 + ((c ^ ((r >> 1) & 3)) << 4));
        cp16(sb + off, src + (size_t)r * rstride + k0 + c * 8, (r < valid) ? 16u : 0u);
    }
}

// ---------------- fused gate+up: h = up(x) * silu(gate(x)) -> bf16 hi/lo ----------------
__global__ __launch_bounds__(256, 1) void moe_gateup_kernel() {
    constexpr int KD = H_DIM, NCH = KD / 32;

    const int e    = blockIdx.z;
    const int m0   = g_offset[e];
    const int rows = g_offset[e + 1] - m0;
    const int bm   = blockIdx.y * 128;
    if (bm >= rows) return;
    const int bn = blockIdx.x * 128;
    const int va = min(rows - bm, 128);

    extern __shared__ char smem[];
    const uint32_t sbase = smem_u32(smem);
    const int tid = threadIdx.x;
    const int lane = tid & 31, wid = tid >> 5;
    const int wm = wid >> 2, wn = wid & 3;

    const __nv_bfloat16* Ah = g_xh + (size_t)(m0 + bm) * KD;
    const __nv_bfloat16* Al = g_xl + (size_t)(m0 + bm) * KD;
    const __nv_bfloat16* Gh = g_wgh + ((size_t)e * I_DIM + bn) * KD;
    const __nv_bfloat16* Gl = g_wgl + ((size_t)e * I_DIM + bn) * KD;
    const __nv_bfloat16* Uh = g_wuh + ((size_t)e * I_DIM + bn) * KD;
    const __nv_bfloat16* Ul = g_wul + ((size_t)e * I_DIM + bn) * KD;

    float accg[4][4][4], accu[4][4][4];
    #pragma unroll
    for (int i = 0; i < 4; i++)
        #pragma unroll
        for (int j = 0; j < 4; j++)
            #pragma unroll
            for (int k = 0; k < 4; k++) { accg[i][j][k] = 0.f; accu[i][j][k] = 0.f; }

    uint32_t a_off[4], a_x[4], b_off[4], b_x[4];
    #pragma unroll
    for (int mt = 0; mt < 4; mt++) {
        int row = wm * 64 + mt * 16 + (lane & 15);
        a_off[mt] = (uint32_t)(row * 64);
        a_x[mt]   = (uint32_t)((row >> 1) & 3);
    }
    #pragma unroll
    for (int nt = 0; nt < 4; nt++) {
        int row = wn * 32 + nt * 8 + (lane & 7);
        b_off[nt] = (uint32_t)(row * 64);
        b_x[nt]   = (uint32_t)((row >> 1) & 3);
    }
    const uint32_t acb = (uint32_t)(lane >> 4);
    const uint32_t bcb = (uint32_t)((lane >> 3) & 1);

    auto issue = [&](int c) {
        uint32_t sb = sbase + (uint32_t)(c % 3) * STAGE_F;
        int k0 = c * 32;
        load_sub(sb,         tid, Ah, KD, k0, va);
        load_sub(sb + 8192,  tid, Al, KD, k0, va);
        load_sub(sb + 16384, tid, Gh, KD, k0, 128);
        load_sub(sb + 24576, tid, Gl, KD, k0, 128);
        load_sub(sb + 32768, tid, Uh, KD, k0, 128);
        load_sub(sb + 40960, tid, Ul, KD, k0, 128);
        asm volatile("cp.async.commit_group;");
    };

    issue(0);
    issue(1);

    for (int c = 0; c < NCH; c++) {
        if (c + 1 < NCH) asm volatile("cp.async.wait_group 1;");
        else             asm volatile("cp.async.wait_group 0;");
        __syncthreads();
        if (c + 2 < NCH) issue(c + 2);

        const uint32_t sb = sbase + (uint32_t)(c % 3) * STAGE_F;
        #pragma unroll
        for (int s16 = 0; s16 < 2; s16++) {
            uint32_t af[2][4][4], bfr[2][4][2];
            #pragma unroll
            for (int mt = 0; mt < 4; mt++) {
                uint32_t ch = (uint32_t)(2 * s16 + acb) ^ a_x[mt];
                uint32_t ad = sb + a_off[mt] + (ch << 4);
                ldm_x4(ad,        af[0][mt]);
                ldm_x4(ad + 8192, af[1][mt]);
            }
            // gate
            #pragma unroll
            for (int nt = 0; nt < 4; nt++) {
                uint32_t ch = (uint32_t)(2 * s16 + bcb) ^ b_x[nt];
                uint32_t bd = sb + 16384 + b_off[nt] + (ch << 4);
                ldm_x2(bd,        bfr[0][nt]);
                ldm_x2(bd + 8192, bfr[1][nt]);
            }
            #pragma unroll
            for (int mt = 0; mt < 4; mt++)
                #pragma unroll
                for (int nt = 0; nt < 4; nt++) {
                    mma_bf16(accg[mt][nt], af[0][mt], bfr[0][nt]);
                    mma_bf16(accg[mt][nt], af[0][mt], bfr[1][nt]);
                    mma_bf16(accg[mt][nt], af[1][mt], bfr[0][nt]);
                }
            // up
            #pragma unroll
            for (int nt = 0; nt < 4; nt++) {
                uint32_t ch = (uint32_t)(2 * s16 + bcb) ^ b_x[nt];
                uint32_t bd = sb + 32768 + b_off[nt] + (ch << 4);
                ldm_x2(bd,        bfr[0][nt]);
                ldm_x2(bd + 8192, bfr[1][nt]);
            }
            #pragma unroll
            for (int mt = 0; mt < 4; mt++)
                #pragma unroll
                for (int nt = 0; nt < 4; nt++) {
                    mma_bf16(accu[mt][nt], af[0][mt], bfr[0][nt]);
                    mma_bf16(accu[mt][nt], af[0][mt], bfr[1][nt]);
                    mma_bf16(accu[mt][nt], af[1][mt], bfr[0][nt]);
                }
        }
    }

    // epilogue: h = u*silu(g) in registers -> bf16 hi/lo
    const int lr = lane >> 2;
    const int lc = (lane & 3) * 2;
    #pragma unroll
    for (int mt = 0; mt < 4; mt++) {
        #pragma unroll
        for (int h2 = 0; h2 < 2; h2++) {
            int r = wm * 64 + mt * 16 + lr + h2 * 8;
            if (r < va) {
                size_t grow = (size_t)(m0 + bm + r);
                #pragma unroll
                for (int nt = 0; nt < 4; nt++) {
                    int col = wn * 32 + nt * 8 + lc;
                    float g0 = accg[mt][nt][h2 * 2], g1 = accg[mt][nt][h2 * 2 + 1];
                    float u0 = accu[mt][nt][h2 * 2], u1 = accu[mt][nt][h2 * 2 + 1];
                    float hv0 = u0 * g0 / (1.f + __expf(-g0));
                    float hv1 = u1 * g1 / (1.f + __expf(-g1));
                    __nv_bfloat16 hh0 = __float2bfloat16(hv0);
                    __nv_bfloat16 hh1 = __float2bfloat16(hv1);
                    __nv_bfloat16 hl0 = __float2bfloat16(hv0 - __bfloat162float(hh0));
                    __nv_bfloat16 hl1 = __float2bfloat16(hv1 - __bfloat162float(hh1));
                    *(__nv_bfloat162*)(g_hh + grow * I_DIM + bn + col) = __nv_bfloat162(hh0, hh1);
                    *(__nv_bfloat162*)(g_hl + grow * I_DIM + bn + col) = __nv_bfloat162(hl0, hl1);
                }
            }
        }
    }
}

// ---------------- down-proj: y = (h @ wd^T) * routing_weight ----------------
__global__ __launch_bounds__(256, 1) void moe_down_kernel() {
    constexpr int KD = I_DIM, ND = H_DIM, NCH = KD / 32;

    const int e    = blockIdx.z;
    const int m0   = g_offset[e];
    const int rows = g_offset[e + 1] - m0;
    const int bm   = blockIdx.y * 128;
    if (bm >= rows) return;
    const int bn = blockIdx.x * 128;
    const int va = min(rows - bm, 128);

    extern __shared__ char smem[];
    const uint32_t sbase = smem_u32(smem);
    const int tid = threadIdx.x;
    const int lane = tid & 31, wid = tid >> 5;
    const int wm = wid >> 2, wn = wid & 3;

    const __nv_bfloat16* Ah = g_hh + (size_t)(m0 + bm) * KD;
    const __nv_bfloat16* Al = g_hl + (size_t)(m0 + bm) * KD;
    const __nv_bfloat16* Bh = g_wdh + ((size_t)e * ND + bn) * KD;
    const __nv_bfloat16* Bl = g_wdl + ((size_t)e * ND + bn) * KD;

    float acc[4][4][4];
    #pragma unroll
    for (int i = 0; i < 4; i++)
        #pragma unroll
        for (int j = 0; j < 4; j++)
            #pragma unroll
            for (int k = 0; k < 4; k++) acc[i][j][k] = 0.f;

    uint32_t a_off[4], a_x[4], b_off[4], b_x[4];
    #pragma unroll
    for (int mt = 0; mt < 4; mt++) {
        int row = wm * 64 + mt * 16 + (lane & 15);
        a_off[mt] = (uint32_t)(row * 64);
        a_x[mt]   = (uint32_t)((row >> 1) & 3);
    }
    #pragma unroll
    for (int nt = 0; nt < 4; nt++) {
        int row = wn * 32 + nt * 8 + (lane & 7);
        b_off[nt] = (uint32_t)(row * 64);
        b_x[nt]   = (uint32_t)((row >> 1) & 3);
    }
    const uint32_t acb = (uint32_t)(lane >> 4);
    const uint32_t bcb = (uint32_t)((lane >> 3) & 1);

    auto issue = [&](int c) {
        uint32_t sb = sbase + (uint32_t)(c % 3) * STAGE_D;
        int k0 = c * 32;
        load_sub(sb,         tid, Ah, KD, k0, va);
        load_sub(sb + 8192,  tid, Al, KD, k0, va);
        load_sub(sb + 16384, tid, Bh, KD, k0, 128);
        load_sub(sb + 24576, tid, Bl, KD, k0, 128);
        asm volatile("cp.async.commit_group;");
    };

    issue(0);
    issue(1);

    for (int c = 0; c < NCH; c++) {
        if (c + 1 < NCH) asm volatile("cp.async.wait_group 1;");
        else             asm volatile("cp.async.wait_group 0;");
        __syncthreads();
        if (c + 2 < NCH) issue(c + 2);

        const uint32_t sb = sbase + (uint32_t)(c % 3) * STAGE_D;
        #pragma unroll
        for (int s16 = 0; s16 < 2; s16++) {
            uint32_t af[2][4][4], bfr[2][4][2];
            #pragma unroll
            for (int mt = 0; mt < 4; mt++) {
                uint32_t ch = (uint32_t)(2 * s16 + acb) ^ a_x[mt];
                uint32_t ad = sb + a_off[mt] + (ch << 4);
                ldm_x4(ad,        af[0][mt]);
                ldm_x4(ad + 8192, af[1][mt]);
            }
            #pragma unroll
            for (int nt = 0; nt < 4; nt++) {
                uint32_t ch = (uint32_t)(2 * s16 + bcb) ^ b_x[nt];
                uint32_t bd = sb + 16384 + b_off[nt] + (ch << 4);
                ldm_x2(bd,        bfr[0][nt]);
                ldm_x2(bd + 8192, bfr[1][nt]);
            }
            #pragma unroll
            for (int mt = 0; mt < 4; mt++)
                #pragma unroll
                for (int nt = 0; nt < 4; nt++) {
                    mma_bf16(acc[mt][nt], af[0][mt], bfr[0][nt]);
                    mma_bf16(acc[mt][nt], af[0][mt], bfr[1][nt]);
                    mma_bf16(acc[mt][nt], af[1][mt], bfr[0][nt]);
                }
        }
    }

    const int lr = lane >> 2;
    const int lc = (lane & 3) * 2;
    #pragma unroll
    for (int mt = 0; mt < 4; mt++) {
        #pragma unroll
        for (int h2 = 0; h2 < 2; h2++) {
            int r = wm * 64 + mt * 16 + lr + h2 * 8;
            if (r < va) {
                size_t grow = (size_t)(m0 + bm + r);
                float scale = g_w_of_row[grow];
                float* C = g_y + grow * ND + bn;
                #pragma unroll
                for (int nt = 0; nt < 4; nt++) {
                    int col = wn * 32 + nt * 8 + lc;
                    *(float2*)(C + col) = make_float2(acc[mt][nt][h2 * 2] * scale,
                                                      acc[mt][nt][h2 * 2 + 1] * scale);
                }
            }
        }
    }
}

// ---------------- combine ----------------
__global__ void combine_kernel(float* __restrict__ out) {
    int t  = blockIdx.x;
    int r0 = g_rows_of_token[2 * t];
    int r1 = g_rows_of_token[2 * t + 1];
    const float4* y0 = (const float4*)(g_y + (size_t)r0 * H_DIM);
    const float4* y1 = (const float4*)(g_y + (size_t)r1 * H_DIM);
    float4* o = (float4*)(out + (size_t)t * H_DIM);
    for (int i = threadIdx.x; i < H_DIM / 4; i += blockDim.x) {
        float4 a = y0[i], b = y1[i];
        o[i] = make_float4(a.x + b.x, a.y + b.y, a.z + b.z, a.w + b.w);
    }
}

// ---------------- launch ----------------
extern "C" void kernel_launch(void* const* d_in, const int* in_sizes, int n_in,
                              void* d_out, int out_size) {
    const float* x   = (const float*)d_in[0];
    const float* wg  = (const float*)d_in[1];
    const float* wgp = (const float*)d_in[2];
    const float* wup = (const float*)d_in[3];
    const float* wdp = (const float*)d_in[4];
    float* out = (float*)d_out;

    cudaFuncSetAttribute(moe_gateup_kernel, cudaFuncAttributeMaxDynamicSharedMemorySize, SMEM_F);
    cudaFuncSetAttribute(moe_down_kernel,   cudaFuncAttributeMaxDynamicSharedMemorySize, SMEM_D);

    __nv_bfloat16 *wgh, *wgl, *wuh, *wul, *wdh, *wdl;
    cudaGetSymbolAddress((void**)&wgh, g_wgh);
    cudaGetSymbolAddress((void**)&wgl, g_wgl);
    cudaGetSymbolAddress((void**)&wuh, g_wuh);
    cudaGetSymbolAddress((void**)&wul, g_wul);
    cudaGetSymbolAddress((void**)&wdh, g_wdh);
    cudaGetSymbolAddress((void**)&wdl, g_wdl);

    zero_kernel<<<1, 32>>>();
    router_kernel<<<T_TOK / 8, 256>>>(x, wg);
    scan_kernel<<<1, 1>>>();
    assign_kernel<<<T_TOK / 256, 256>>>();
    gather_kernel<<<NROWS, 128>>>(x);

    dim3 cb(32, 8);
    convert_w_kernel<<<dim3(I_DIM / 32, H_DIM / 32, N_EXP), cb>>>(wgp, wgh, wgl, H_DIM, I_DIM);
    convert_w_kernel<<<dim3(I_DIM / 32, H_DIM / 32, N_EXP), cb>>>(wup, wuh, wul, H_DIM, I_DIM);
    convert_w_kernel<<<dim3(H_DIM / 32, I_DIM / 32, N_EXP), cb>>>(wdp, wdh, wdl, I_DIM, H_DIM);

    moe_gateup_kernel<<<dim3(I_DIM / 128, 128, N_EXP), 256, SMEM_F>>>();
    moe_down_kernel<<<dim3(H_DIM / 128, 128, N_EXP), 256, SMEM_D>>>();

    combine_kernel<<<T_TOK, 256>>>(out);
}

// round 9
// speedup vs baseline: 3.0918x; 1.1438x over previous
#include <cuda_runtime.h>
#include <cuda_bf16.h>
#include <cstdint>

#define T_TOK 16384
#define H_DIM 1024
#define I_DIM 2048
#define N_EXP 16
#define NROWS (T_TOK * 2)

// ---------------- routing scratch ----------------
__device__ int   g_count[N_EXP];
__device__ int   g_cursor[N_EXP];
__device__ int   g_offset[N_EXP + 1];
__device__ int   g_e0[T_TOK];
__device__ int   g_e1[T_TOK];
__device__ float g_w0[T_TOK];
__device__ float g_w1[T_TOK];
__device__ int   g_token_of_row[NROWS];
__device__ float g_w_of_row[NROWS];
__device__ int   g_rows_of_token[NROWS];

// ---------------- data buffers ----------------
// weights kept in NATIVE [E][K][N] layout, split hi/lo (no transpose)
__device__ __nv_bfloat16 g_xh[(size_t)NROWS * H_DIM];
__device__ __nv_bfloat16 g_xl[(size_t)NROWS * H_DIM];
__device__ __nv_bfloat16 g_wgh[(size_t)N_EXP * H_DIM * I_DIM];
__device__ __nv_bfloat16 g_wgl[(size_t)N_EXP * H_DIM * I_DIM];
__device__ __nv_bfloat16 g_wuh[(size_t)N_EXP * H_DIM * I_DIM];
__device__ __nv_bfloat16 g_wul[(size_t)N_EXP * H_DIM * I_DIM];
__device__ __nv_bfloat16 g_wdh[(size_t)N_EXP * I_DIM * H_DIM];
__device__ __nv_bfloat16 g_wdl[(size_t)N_EXP * I_DIM * H_DIM];
__device__ __nv_bfloat16 g_hh[(size_t)NROWS * I_DIM];
__device__ __nv_bfloat16 g_hl[(size_t)NROWS * I_DIM];
__device__ float         g_y[(size_t)NROWS * H_DIM];

// ---------------- ptx helpers ----------------
__device__ __forceinline__ uint32_t smem_u32(const void* p) {
    uint32_t a;
    asm("{ .reg .u64 t; cvta.to.shared.u64 t, %1; cvt.u32.u64 %0, t; }" : "=r"(a) : "l"(p));
    return a;
}
__device__ __forceinline__ void cp16(uint32_t dst, const void* src, uint32_t sz) {
    asm volatile("cp.async.cg.shared.global [%0], [%1], 16, %2;"
                 :: "r"(dst), "l"(src), "r"(sz));
}
__device__ __forceinline__ void ldm_x4(uint32_t a, uint32_t r[4]) {
    asm volatile("ldmatrix.sync.aligned.m8n8.x4.shared.b16 {%0,%1,%2,%3}, [%4];"
                 : "=r"(r[0]), "=r"(r[1]), "=r"(r[2]), "=r"(r[3]) : "r"(a));
}
__device__ __forceinline__ void ldm_x2t(uint32_t a, uint32_t r[2]) {
    asm volatile("ldmatrix.sync.aligned.m8n8.x2.trans.shared.b16 {%0,%1}, [%2];"
                 : "=r"(r[0]), "=r"(r[1]) : "r"(a));
}
__device__ __forceinline__ void mma_bf16(float* c, const uint32_t* a, const uint32_t* b) {
    asm volatile(
        "mma.sync.aligned.m16n8k16.row.col.f32.bf16.bf16.f32 "
        "{%0,%1,%2,%3}, {%4,%5,%6,%7}, {%8,%9}, {%0,%1,%2,%3};"
        : "+f"(c[0]), "+f"(c[1]), "+f"(c[2]), "+f"(c[3])
        : "r"(a[0]), "r"(a[1]), "r"(a[2]), "r"(a[3]), "r"(b[0]), "r"(b[1]));
}

// ---------------- small kernels (routing path) ----------------
__global__ void zero_kernel() {
    int i = threadIdx.x;
    if (i < N_EXP) { g_count[i] = 0; g_cursor[i] = 0; }
}

__global__ void router_kernel(const float* __restrict__ x, const float* __restrict__ wg) {
    int warp = (blockIdx.x * blockDim.x + threadIdx.x) >> 5;
    int lane = threadIdx.x & 31;
    if (warp >= T_TOK) return;
    int t = warp;
    const float* xr = x + (size_t)t * H_DIM;
    int e  = lane & 15;
    int k0 = (lane >> 4) * (H_DIM / 2);

    float acc = 0.f;
    for (int k = k0; k < k0 + H_DIM / 2; k++)
        acc = fmaf(xr[k], wg[k * N_EXP + e], acc);
    acc += __shfl_xor_sync(0xffffffffu, acc, 16);

    float v = acc; int idx = e;
    #pragma unroll
    for (int s = 16; s; s >>= 1) {
        float ov = __shfl_xor_sync(0xffffffffu, v, s);
        int   oi = __shfl_xor_sync(0xffffffffu, idx, s);
        if (ov > v || (ov == v && oi < idx)) { v = ov; idx = oi; }
    }
    float l1 = v; int i1 = idx;

    v = (e == i1) ? -1e30f : acc; idx = e;
    #pragma unroll
    for (int s = 16; s; s >>= 1) {
        float ov = __shfl_xor_sync(0xffffffffu, v, s);
        int   oi = __shfl_xor_sync(0xffffffffu, idx, s);
        if (ov > v || (ov == v && oi < idx)) { v = ov; idx = oi; }
    }
    float l2 = v; int i2 = idx;

    if (lane == 0) {
        float r  = __expf(l2 - l1);
        float w0 = 1.f / (1.f + r);
        g_e0[t] = i1; g_e1[t] = i2;
        g_w0[t] = w0; g_w1[t] = 1.f - w0;
        atomicAdd(&g_count[i1], 1);
        atomicAdd(&g_count[i2], 1);
    }
}

__global__ void scan_kernel() {
    if (threadIdx.x == 0) {
        int o = 0;
        for (int e = 0; e < N_EXP; e++) { g_offset[e] = o; o += g_count[e]; }
        g_offset[N_EXP] = o;
    }
}

__global__ void assign_kernel() {
    int t = blockIdx.x * blockDim.x + threadIdx.x;
    if (t >= T_TOK) return;
    int e0 = g_e0[t];
    int r0 = g_offset[e0] + atomicAdd(&g_cursor[e0], 1);
    g_token_of_row[r0] = t; g_w_of_row[r0] = g_w0[t]; g_rows_of_token[2 * t] = r0;
    int e1 = g_e1[t];
    int r1 = g_offset[e1] + atomicAdd(&g_cursor[e1], 1);
    g_token_of_row[r1] = t; g_w_of_row[r1] = g_w1[t]; g_rows_of_token[2 * t + 1] = r1;
}

__global__ void gather_kernel(const float* __restrict__ x) {
    int row = blockIdx.x;
    int t = g_token_of_row[row];
    const float4* src = (const float4*)(x + (size_t)t * H_DIM);
    __nv_bfloat16* dh = g_xh + (size_t)row * H_DIM;
    __nv_bfloat16* dl = g_xl + (size_t)row * H_DIM;
    for (int i = threadIdx.x; i < H_DIM / 4; i += 128) {
        float4 v = src[i];
        __nv_bfloat16 h0 = __float2bfloat16(v.x);
        __nv_bfloat16 h1 = __float2bfloat16(v.y);
        __nv_bfloat16 h2 = __float2bfloat16(v.z);
        __nv_bfloat16 h3 = __float2bfloat16(v.w);
        __nv_bfloat16 l0 = __float2bfloat16(v.x - __bfloat162float(h0));
        __nv_bfloat16 l1 = __float2bfloat16(v.y - __bfloat162float(h1));
        __nv_bfloat16 l2 = __float2bfloat16(v.z - __bfloat162float(h2));
        __nv_bfloat16 l3 = __float2bfloat16(v.w - __bfloat162float(h3));
        __nv_bfloat162* ph = (__nv_bfloat162*)(dh + i * 4);
        __nv_bfloat162* pl = (__nv_bfloat162*)(dl + i * 4);
        ph[0] = __nv_bfloat162(h0, h1); ph[1] = __nv_bfloat162(h2, h3);
        pl[0] = __nv_bfloat162(l0, l1); pl[1] = __nv_bfloat162(l2, l3);
    }
}

// streaming hi/lo split, NO transpose (weights stay [E][K][N])
__global__ void split_w_kernel(const float4* __restrict__ src,
                               uint2* __restrict__ dh, uint2* __restrict__ dl, int n4) {
    int i = blockIdx.x * blockDim.x + threadIdx.x;
    int stride = gridDim.x * blockDim.x;
    for (; i < n4; i += stride) {
        float4 v = src[i];
        __nv_bfloat16 h0 = __float2bfloat16(v.x);
        __nv_bfloat16 h1 = __float2bfloat16(v.y);
        __nv_bfloat16 h2 = __float2bfloat16(v.z);
        __nv_bfloat16 h3 = __float2bfloat16(v.w);
        __nv_bfloat162 ph0(h0, h1), ph1(h2, h3);
        __nv_bfloat162 pl0(__float2bfloat16(v.x - __bfloat162float(h0)),
                           __float2bfloat16(v.y - __bfloat162float(h1)));
        __nv_bfloat162 pl1(__float2bfloat16(v.z - __bfloat162float(h2)),
                           __float2bfloat16(v.w - __bfloat162float(h3)));
        uint2 uh, ul;
        uh.x = *(uint32_t*)&ph0; uh.y = *(uint32_t*)&ph1;
        ul.x = *(uint32_t*)&pl0; ul.y = *(uint32_t*)&pl1;
        dh[i] = uh; dl[i] = ul;
    }
}

// ============================================================================
// bf16x3 grouped GEMMs on mma.sync. BK=64, 2-stage cp.async, 1 sync/chunk.
// A tiles: [128 m][64 k], 128B rows, swizzle: chunk c of row r at r*128+((c^(r&7))<<4)
// B tiles: [64 k][128 n], 256B rows, swizzle: chunk c of row r at r*256+((c^(r&7))<<4)
// B consumed with ldmatrix.x2.trans (weights in native [K][N] layout).
// ============================================================================
#define STAGE_F  98304   // Ah,Al (16K ea) + Gh,Gl,Uh,Ul (16K ea)
#define STAGE_D  65536   // Ah,Al,Bh,Bl
#define SMEM_F   (2 * STAGE_F)
#define SMEM_D   (2 * STAGE_D)

__device__ __forceinline__ void load_A(uint32_t sb, int tid, const __nv_bfloat16* src,
                                       size_t rstride, int k0, int valid) {
    #pragma unroll
    for (int j = 0; j < 4; j++) {
        int u = tid + j * 256;              // 0..1023
        int r = u >> 3, c = u & 7;
        uint32_t off = (uint32_t)(r * 128 + ((c ^ (r & 7)) << 4));
        cp16(sb + off, src + (size_t)r * rstride + k0 + c * 8, (r < valid) ? 16u : 0u);
    }
}
__device__ __forceinline__ void load_B(uint32_t sb, int tid, const __nv_bfloat16* src,
                                       size_t N, int k0) {
    #pragma unroll
    for (int j = 0; j < 4; j++) {
        int u = tid + j * 256;
        int r = u >> 4, c = u & 15;         // r: 0..63 (k), c: 16B n-chunk
        uint32_t off = (uint32_t)(r * 256 + ((c ^ (r & 7)) << 4));
        cp16(sb + off, src + (size_t)(k0 + r) * N + c * 8, 16u);
    }
}

// ---------------- fused gate+up: h = up(x) * silu(gate(x)) -> bf16 hi/lo ----------------
__global__ __launch_bounds__(256, 1) void moe_gateup_kernel() {
    constexpr int KD = H_DIM, NCH = KD / 64;

    const int e    = blockIdx.z;
    const int m0   = g_offset[e];
    const int rows = g_offset[e + 1] - m0;
    const int bm   = blockIdx.y * 128;
    if (bm >= rows) return;
    const int bn = blockIdx.x * 128;
    const int va = min(rows - bm, 128);

    extern __shared__ char smem[];
    const uint32_t sbase = smem_u32(smem);
    const int tid = threadIdx.x;
    const int lane = tid & 31, wid = tid >> 5;
    const int wm = wid >> 2, wn = wid & 3;

    const __nv_bfloat16* Ah = g_xh + (size_t)(m0 + bm) * KD;
    const __nv_bfloat16* Al = g_xl + (size_t)(m0 + bm) * KD;
    const __nv_bfloat16* Gh = g_wgh + (size_t)e * KD * I_DIM + bn;
    const __nv_bfloat16* Gl = g_wgl + (size_t)e * KD * I_DIM + bn;
    const __nv_bfloat16* Uh = g_wuh + (size_t)e * KD * I_DIM + bn;
    const __nv_bfloat16* Ul = g_wul + (size_t)e * KD * I_DIM + bn;

    float accg[4][4][4], accu[4][4][4];
    #pragma unroll
    for (int i = 0; i < 4; i++)
        #pragma unroll
        for (int j = 0; j < 4; j++)
            #pragma unroll
            for (int k = 0; k < 4; k++) { accg[i][j][k] = 0.f; accu[i][j][k] = 0.f; }

    auto issue = [&](int c) {
        uint32_t sb = sbase + (uint32_t)(c & 1) * STAGE_F;
        int k0 = c * 64;
        load_A(sb,         tid, Ah, KD, k0, va);
        load_A(sb + 16384, tid, Al, KD, k0, va);
        load_B(sb + 32768, tid, Gh, I_DIM, k0);
        load_B(sb + 49152, tid, Gl, I_DIM, k0);
        load_B(sb + 65536, tid, Uh, I_DIM, k0);
        load_B(sb + 81920, tid, Ul, I_DIM, k0);
        asm volatile("cp.async.commit_group;");
    };

    issue(0);

    for (int c = 0; c < NCH; c++) {
        asm volatile("cp.async.wait_group 0;");
        __syncthreads();
        if (c + 1 < NCH) issue(c + 1);

        const uint32_t sb = sbase + (uint32_t)(c & 1) * STAGE_F;
        #pragma unroll
        for (int s16 = 0; s16 < 4; s16++) {
            // A fragments (hi, lo)
            uint32_t af[2][4][4];
            #pragma unroll
            for (int mt = 0; mt < 4; mt++) {
                int row = wm * 64 + mt * 16 + (lane & 15);
                uint32_t ch = (uint32_t)(2 * s16 + (lane >> 4)) ^ (uint32_t)(row & 7);
                uint32_t ad = sb + (uint32_t)(row * 128) + (ch << 4);
                ldm_x4(ad,         af[0][mt]);
                ldm_x4(ad + 16384, af[1][mt]);
            }
            const int rowb = s16 * 16 + (lane & 15);
            const uint32_t broff = (uint32_t)(rowb * 256);
            const uint32_t bxor  = (uint32_t)(rowb & 7);

            uint32_t bh[4][2], bl[4][2];
            // ---- gate ----
            #pragma unroll
            for (int nt = 0; nt < 4; nt++) {
                uint32_t ch = (uint32_t)(wn * 4 + nt) ^ bxor;
                uint32_t ad = sb + 32768 + broff + (ch << 4);
                ldm_x2t(ad,         bh[nt]);
                ldm_x2t(ad + 16384, bl[nt]);
            }
            #pragma unroll
            for (int mt = 0; mt < 4; mt++)
                #pragma unroll
                for (int nt = 0; nt < 4; nt++) mma_bf16(accg[mt][nt], af[0][mt], bh[nt]);
            #pragma unroll
            for (int mt = 0; mt < 4; mt++)
                #pragma unroll
                for (int nt = 0; nt < 4; nt++) mma_bf16(accg[mt][nt], af[0][mt], bl[nt]);
            #pragma unroll
            for (int mt = 0; mt < 4; mt++)
                #pragma unroll
                for (int nt = 0; nt < 4; nt++) mma_bf16(accg[mt][nt], af[1][mt], bh[nt]);
            // ---- up ----
            #pragma unroll
            for (int nt = 0; nt < 4; nt++) {
                uint32_t ch = (uint32_t)(wn * 4 + nt) ^ bxor;
                uint32_t ad = sb + 65536 + broff + (ch << 4);
                ldm_x2t(ad,         bh[nt]);
                ldm_x2t(ad + 16384, bl[nt]);
            }
            #pragma unroll
            for (int mt = 0; mt < 4; mt++)
                #pragma unroll
                for (int nt = 0; nt < 4; nt++) mma_bf16(accu[mt][nt], af[0][mt], bh[nt]);
            #pragma unroll
            for (int mt = 0; mt < 4; mt++)
                #pragma unroll
                for (int nt = 0; nt < 4; nt++) mma_bf16(accu[mt][nt], af[0][mt], bl[nt]);
            #pragma unroll
            for (int mt = 0; mt < 4; mt++)
                #pragma unroll
                for (int nt = 0; nt < 4; nt++) mma_bf16(accu[mt][nt], af[1][mt], bh[nt]);
        }
    }

    // epilogue: h = u*silu(g) in registers -> bf16 hi/lo
    const int lr = lane >> 2;
    const int lc = (lane & 3) * 2;
    #pragma unroll
    for (int mt = 0; mt < 4; mt++) {
        #pragma unroll
        for (int h2 = 0; h2 < 2; h2++) {
            int r = wm * 64 + mt * 16 + lr + h2 * 8;
            if (r < va) {
                size_t grow = (size_t)(m0 + bm + r);
                #pragma unroll
                for (int nt = 0; nt < 4; nt++) {
                    int col = wn * 32 + nt * 8 + lc;
                    float g0 = accg[mt][nt][h2 * 2], g1 = accg[mt][nt][h2 * 2 + 1];
                    float u0 = accu[mt][nt][h2 * 2], u1 = accu[mt][nt][h2 * 2 + 1];
                    float hv0 = u0 * g0 / (1.f + __expf(-g0));
                    float hv1 = u1 * g1 / (1.f + __expf(-g1));
                    __nv_bfloat16 hh0 = __float2bfloat16(hv0);
                    __nv_bfloat16 hh1 = __float2bfloat16(hv1);
                    __nv_bfloat16 hl0 = __float2bfloat16(hv0 - __bfloat162float(hh0));
                    __nv_bfloat16 hl1 = __float2bfloat16(hv1 - __bfloat162float(hh1));
                    *(__nv_bfloat162*)(g_hh + grow * I_DIM + bn + col) = __nv_bfloat162(hh0, hh1);
                    *(__nv_bfloat162*)(g_hl + grow * I_DIM + bn + col) = __nv_bfloat162(hl0, hl1);
                }
            }
        }
    }
}

// ---------------- down-proj: y = (h @ wd) * routing_weight ----------------
__global__ __launch_bounds__(256, 1) void moe_down_kernel() {
    constexpr int KD = I_DIM, ND = H_DIM, NCH = KD / 64;

    const int e    = blockIdx.z;
    const int m0   = g_offset[e];
    const int rows = g_offset[e + 1] - m0;
    const int bm   = blockIdx.y * 128;
    if (bm >= rows) return;
    const int bn = blockIdx.x * 128;
    const int va = min(rows - bm, 128);

    extern __shared__ char smem[];
    const uint32_t sbase = smem_u32(smem);
    const int tid = threadIdx.x;
    const int lane = tid & 31, wid = tid >> 5;
    const int wm = wid >> 2, wn = wid & 3;

    const __nv_bfloat16* Ah = g_hh + (size_t)(m0 + bm) * KD;
    const __nv_bfloat16* Al = g_hl + (size_t)(m0 + bm) * KD;
    const __nv_bfloat16* Bh = g_wdh + (size_t)e * KD * ND + bn;
    const __nv_bfloat16* Bl = g_wdl + (size_t)e * KD * ND + bn;

    float acc[4][4][4];
    #pragma unroll
    for (int i = 0; i < 4; i++)
        #pragma unroll
        for (int j = 0; j < 4; j++)
            #pragma unroll
            for (int k = 0; k < 4; k++) acc[i][j][k] = 0.f;

    auto issue = [&](int c) {
        uint32_t sb = sbase + (uint32_t)(c & 1) * STAGE_D;
        int k0 = c * 64;
        load_A(sb,         tid, Ah, KD, k0, va);
        load_A(sb + 16384, tid, Al, KD, k0, va);
        load_B(sb + 32768, tid, Bh, ND, k0);
        load_B(sb + 49152, tid, Bl, ND, k0);
        asm volatile("cp.async.commit_group;");
    };

    issue(0);

    for (int c = 0; c < NCH; c++) {
        asm volatile("cp.async.wait_group 0;");
        __syncthreads();
        if (c + 1 < NCH) issue(c + 1);

        const uint32_t sb = sbase + (uint32_t)(c & 1) * STAGE_D;
        #pragma unroll
        for (int s16 = 0; s16 < 4; s16++) {
            uint32_t af[2][4][4];
            #pragma unroll
            for (int mt = 0; mt < 4; mt++) {
                int row = wm * 64 + mt * 16 + (lane & 15);
                uint32_t ch = (uint32_t)(2 * s16 + (lane >> 4)) ^ (uint32_t)(row & 7);
                uint32_t ad = sb + (uint32_t)(row * 128) + (ch << 4);
                ldm_x4(ad,         af[0][mt]);
                ldm_x4(ad + 16384, af[1][mt]);
            }
            const int rowb = s16 * 16 + (lane & 15);
            const uint32_t broff = (uint32_t)(rowb * 256);
            const uint32_t bxor  = (uint32_t)(rowb & 7);

            uint32_t bh[4][2], bl[4][2];
            #pragma unroll
            for (int nt = 0; nt < 4; nt++) {
                uint32_t ch = (uint32_t)(wn * 4 + nt) ^ bxor;
                uint32_t ad = sb + 32768 + broff + (ch << 4);
                ldm_x2t(ad,         bh[nt]);
                ldm_x2t(ad + 16384, bl[nt]);
            }
            #pragma unroll
            for (int mt = 0; mt < 4; mt++)
                #pragma unroll
                for (int nt = 0; nt < 4; nt++) mma_bf16(acc[mt][nt], af[0][mt], bh[nt]);
            #pragma unroll
            for (int mt = 0; mt < 4; mt++)
                #pragma unroll
                for (int nt = 0; nt < 4; nt++) mma_bf16(acc[mt][nt], af[0][mt], bl[nt]);
            #pragma unroll
            for (int mt = 0; mt < 4; mt++)
                #pragma unroll
                for (int nt = 0; nt < 4; nt++) mma_bf16(acc[mt][nt], af[1][mt], bh[nt]);
        }
    }

    const int lr = lane >> 2;
    const int lc = (lane & 3) * 2;
    #pragma unroll
    for (int mt = 0; mt < 4; mt++) {
        #pragma unroll
        for (int h2 = 0; h2 < 2; h2++) {
            int r = wm * 64 + mt * 16 + lr + h2 * 8;
            if (r < va) {
                size_t grow = (size_t)(m0 + bm + r);
                float scale = g_w_of_row[grow];
                float* C = g_y + grow * ND + bn;
                #pragma unroll
                for (int nt = 0; nt < 4; nt++) {
                    int col = wn * 32 + nt * 8 + lc;
                    *(float2*)(C + col) = make_float2(acc[mt][nt][h2 * 2] * scale,
                                                      acc[mt][nt][h2 * 2 + 1] * scale);
                }
            }
        }
    }
}

// ---------------- combine ----------------
__global__ void combine_kernel(float* __restrict__ out) {
    int t  = blockIdx.x;
    int r0 = g_rows_of_token[2 * t];
    int r1 = g_rows_of_token[2 * t + 1];
    const float4* y0 = (const float4*)(g_y + (size_t)r0 * H_DIM);
    const float4* y1 = (const float4*)(g_y + (size_t)r1 * H_DIM);
    float4* o = (float4*)(out + (size_t)t * H_DIM);
    for (int i = threadIdx.x; i < H_DIM / 4; i += blockDim.x) {
        float4 a = y0[i], b = y1[i];
        o[i] = make_float4(a.x + b.x, a.y + b.y, a.z + b.z, a.w + b.w);
    }
}

// ---------------- launch ----------------
extern "C" void kernel_launch(void* const* d_in, const int* in_sizes, int n_in,
                              void* d_out, int out_size) {
    const float* x   = (const float*)d_in[0];
    const float* wg  = (const float*)d_in[1];
    const float* wgp = (const float*)d_in[2];
    const float* wup = (const float*)d_in[3];
    const float* wdp = (const float*)d_in[4];
    float* out = (float*)d_out;

    cudaFuncSetAttribute(moe_gateup_kernel, cudaFuncAttributeMaxDynamicSharedMemorySize, SMEM_F);
    cudaFuncSetAttribute(moe_down_kernel,   cudaFuncAttributeMaxDynamicSharedMemorySize, SMEM_D);

    __nv_bfloat16 *wgh, *wgl, *wuh, *wul, *wdh, *wdl;
    cudaGetSymbolAddress((void**)&wgh, g_wgh);
    cudaGetSymbolAddress((void**)&wgl, g_wgl);
    cudaGetSymbolAddress((void**)&wuh, g_wuh);
    cudaGetSymbolAddress((void**)&wul, g_wul);
    cudaGetSymbolAddress((void**)&wdh, g_wdh);
    cudaGetSymbolAddress((void**)&wdl, g_wdl);

    zero_kernel<<<1, 32>>>();
    router_kernel<<<T_TOK / 8, 256>>>(x, wg);
    scan_kernel<<<1, 1>>>();
    assign_kernel<<<T_TOK / 256, 256>>>();
    gather_kernel<<<NROWS, 128>>>(x);

    const int n4 = N_EXP * H_DIM * I_DIM / 4;
    split_w_kernel<<<4096, 256>>>((const float4*)wgp, (uint2*)wgh, (uint2*)wgl, n4);
    split_w_kernel<<<4096, 256>>>((const float4*)wup, (uint2*)wuh, (uint2*)wul, n4);
    split_w_kernel<<<4096, 256>>>((const float4*)wdp, (uint2*)wdh, (uint2*)wdl, n4);

    moe_gateup_kernel<<<dim3(I_DIM / 128, 128, N_EXP), 256, SMEM_F>>>();
    moe_down_kernel<<<dim3(H_DIM / 128, 128, N_EXP), 256, SMEM_D>>>();

    combine_kernel<<<T_TOK, 256>>>(out);
}

// round 11
// speedup vs baseline: 3.1294x; 1.0122x over previous
#include <cuda_runtime.h>
#include <cuda_bf16.h>
#include <cstdint>

#define T_TOK 16384
#define H_DIM 1024
#define I_DIM 2048
#define N_EXP 16
#define NROWS (T_TOK * 2)
#define MAXTILES 288

// ---------------- routing scratch ----------------
__device__ int   g_count[N_EXP];
__device__ int   g_cursor[N_EXP];
__device__ int   g_offset[N_EXP + 1];
__device__ int   g_ntiles;
__device__ int   g_tile_e[MAXTILES];
__device__ int   g_tile_bm[MAXTILES];
__device__ int   g_e0[T_TOK];
__device__ int   g_e1[T_TOK];
__device__ float g_w0[T_TOK];
__device__ float g_w1[T_TOK];
__device__ int   g_token_of_row[NROWS];
__device__ float g_w_of_row[NROWS];
__device__ int   g_rows_of_token[NROWS];

// ---------------- data buffers ----------------
// weights kept in NATIVE [E][K][N] layout, split hi/lo (no transpose)
__device__ __nv_bfloat16 g_xh[(size_t)NROWS * H_DIM];
__device__ __nv_bfloat16 g_xl[(size_t)NROWS * H_DIM];
__device__ __nv_bfloat16 g_wgh[(size_t)N_EXP * H_DIM * I_DIM];
__device__ __nv_bfloat16 g_wgl[(size_t)N_EXP * H_DIM * I_DIM];
__device__ __nv_bfloat16 g_wuh[(size_t)N_EXP * H_DIM * I_DIM];
__device__ __nv_bfloat16 g_wul[(size_t)N_EXP * H_DIM * I_DIM];
__device__ __nv_bfloat16 g_wdh[(size_t)N_EXP * I_DIM * H_DIM];
__device__ __nv_bfloat16 g_wdl[(size_t)N_EXP * I_DIM * H_DIM];
__device__ __nv_bfloat16 g_hh[(size_t)NROWS * I_DIM];
__device__ __nv_bfloat16 g_hl[(size_t)NROWS * I_DIM];
__device__ float         g_y[(size_t)NROWS * H_DIM];

// ---------------- ptx helpers ----------------
__device__ __forceinline__ uint32_t smem_u32(const void* p) {
    uint32_t a;
    asm("{ .reg .u64 t; cvta.to.shared.u64 t, %1; cvt.u32.u64 %0, t; }" : "=r"(a) : "l"(p));
    return a;
}
__device__ __forceinline__ void cp16(uint32_t dst, const void* src, uint32_t sz) {
    asm volatile("cp.async.cg.shared.global [%0], [%1], 16, %2;"
                 :: "r"(dst), "l"(src), "r"(sz));
}
__device__ __forceinline__ void ldm_x4(uint32_t a, uint32_t r[4]) {
    asm volatile("ldmatrix.sync.aligned.m8n8.x4.shared.b16 {%0,%1,%2,%3}, [%4];"
                 : "=r"(r[0]), "=r"(r[1]), "=r"(r[2]), "=r"(r[3]) : "r"(a));
}
__device__ __forceinline__ void ldm_x4t(uint32_t a, uint32_t r[4]) {
    asm volatile("ldmatrix.sync.aligned.m8n8.x4.trans.shared.b16 {%0,%1,%2,%3}, [%4];"
                 : "=r"(r[0]), "=r"(r[1]), "=r"(r[2]), "=r"(r[3]) : "r"(a));
}
__device__ __forceinline__ void mma_bf16(float* c, const uint32_t* a, const uint32_t* b) {
    asm volatile(
        "mma.sync.aligned.m16n8k16.row.col.f32.bf16.bf16.f32 "
        "{%0,%1,%2,%3}, {%4,%5,%6,%7}, {%8,%9}, {%0,%1,%2,%3};"
        : "+f"(c[0]), "+f"(c[1]), "+f"(c[2]), "+f"(c[3])
        : "r"(a[0]), "r"(a[1]), "r"(a[2]), "r"(a[3]), "r"(b[0]), "r"(b[1]));
}

// ---------------- small kernels (routing path) ----------------
__global__ void zero_kernel() {
    int i = threadIdx.x;
    if (i < N_EXP) { g_count[i] = 0; g_cursor[i] = 0; }
}

__global__ void router_kernel(const float* __restrict__ x, const float* __restrict__ wg) {
    int warp = (blockIdx.x * blockDim.x + threadIdx.x) >> 5;
    int lane = threadIdx.x & 31;
    if (warp >= T_TOK) return;
    int t = warp;
    const float* xr = x + (size_t)t * H_DIM;
    int e  = lane & 15;
    int k0 = (lane >> 4) * (H_DIM / 2);

    float acc = 0.f;
    for (int k = k0; k < k0 + H_DIM / 2; k++)
        acc = fmaf(xr[k], wg[k * N_EXP + e], acc);
    acc += __shfl_xor_sync(0xffffffffu, acc, 16);

    float v = acc; int idx = e;
    #pragma unroll
    for (int s = 16; s; s >>= 1) {
        float ov = __shfl_xor_sync(0xffffffffu, v, s);
        int   oi = __shfl_xor_sync(0xffffffffu, idx, s);
        if (ov > v || (ov == v && oi < idx)) { v = ov; idx = oi; }
    }
    float l1 = v; int i1 = idx;

    v = (e == i1) ? -1e30f : acc; idx = e;
    #pragma unroll
    for (int s = 16; s; s >>= 1) {
        float ov = __shfl_xor_sync(0xffffffffu, v, s);
        int   oi = __shfl_xor_sync(0xffffffffu, idx, s);
        if (ov > v || (ov == v && oi < idx)) { v = ov; idx = oi; }
    }
    float l2 = v; int i2 = idx;

    if (lane == 0) {
        float r  = __expf(l2 - l1);
        float w0 = 1.f / (1.f + r);
        g_e0[t] = i1; g_e1[t] = i2;
        g_w0[t] = w0; g_w1[t] = 1.f - w0;
        atomicAdd(&g_count[i1], 1);
        atomicAdd(&g_count[i2], 1);
    }
}

// scan + build exact tile map (<= 272 live m-tiles)
__global__ void scan_kernel() {
    if (threadIdx.x == 0) {
        int o = 0, tt = 0;
        for (int e = 0; e < N_EXP; e++) {
            g_offset[e] = o;
            int cnt = g_count[e];
            for (int bm = 0; bm < cnt; bm += 128) {
                g_tile_e[tt] = e; g_tile_bm[tt] = bm; tt++;
            }
            o += cnt;
        }
        g_offset[N_EXP] = o;
        g_ntiles = tt;
    }
}

__global__ void assign_kernel() {
    int t = blockIdx.x * blockDim.x + threadIdx.x;
    if (t >= T_TOK) return;
    int e0 = g_e0[t];
    int r0 = g_offset[e0] + atomicAdd(&g_cursor[e0], 1);
    g_token_of_row[r0] = t; g_w_of_row[r0] = g_w0[t]; g_rows_of_token[2 * t] = r0;
    int e1 = g_e1[t];
    int r1 = g_offset[e1] + atomicAdd(&g_cursor[e1], 1);
    g_token_of_row[r1] = t; g_w_of_row[r1] = g_w1[t]; g_rows_of_token[2 * t + 1] = r1;
}

__global__ void gather_kernel(const float* __restrict__ x) {
    int row = blockIdx.x;
    int t = g_token_of_row[row];
    const float4* src = (const float4*)(x + (size_t)t * H_DIM);
    __nv_bfloat16* dh = g_xh + (size_t)row * H_DIM;
    __nv_bfloat16* dl = g_xl + (size_t)row * H_DIM;
    for (int i = threadIdx.x; i < H_DIM / 4; i += 128) {
        float4 v = src[i];
        __nv_bfloat16 h0 = __float2bfloat16(v.x);
        __nv_bfloat16 h1 = __float2bfloat16(v.y);
        __nv_bfloat16 h2 = __float2bfloat16(v.z);
        __nv_bfloat16 h3 = __float2bfloat16(v.w);
        __nv_bfloat16 l0 = __float2bfloat16(v.x - __bfloat162float(h0));
        __nv_bfloat16 l1 = __float2bfloat16(v.y - __bfloat162float(h1));
        __nv_bfloat16 l2 = __float2bfloat16(v.z - __bfloat162float(h2));
        __nv_bfloat16 l3 = __float2bfloat16(v.w - __bfloat162float(h3));
        __nv_bfloat162* ph = (__nv_bfloat162*)(dh + i * 4);
        __nv_bfloat162* pl = (__nv_bfloat162*)(dl + i * 4);
        ph[0] = __nv_bfloat162(h0, h1); ph[1] = __nv_bfloat162(h2, h3);
        pl[0] = __nv_bfloat162(l0, l1); pl[1] = __nv_bfloat162(l2, l3);
    }
}

// streaming hi/lo split of all 3 weight tensors in one launch (grid.z selects tensor)
__global__ void split_w_all(const float4* __restrict__ w0, const float4* __restrict__ w1,
                            const float4* __restrict__ w2, int n4) {
    int z = blockIdx.z;
    const float4* src = (z == 0) ? w0 : (z == 1) ? w1 : w2;
    uint2* dh = (z == 0) ? (uint2*)g_wgh : (z == 1) ? (uint2*)g_wuh : (uint2*)g_wdh;
    uint2* dl = (z == 0) ? (uint2*)g_wgl : (z == 1) ? (uint2*)g_wul : (uint2*)g_wdl;
    int i = blockIdx.x * blockDim.x + threadIdx.x;
    int stride = gridDim.x * blockDim.x;
    for (; i < n4; i += stride) {
        float4 v = src[i];
        __nv_bfloat16 h0 = __float2bfloat16(v.x);
        __nv_bfloat16 h1 = __float2bfloat16(v.y);
        __nv_bfloat16 h2 = __float2bfloat16(v.z);
        __nv_bfloat16 h3 = __float2bfloat16(v.w);
        __nv_bfloat162 ph0(h0, h1), ph1(h2, h3);
        __nv_bfloat162 pl0(__float2bfloat16(v.x - __bfloat162float(h0)),
                           __float2bfloat16(v.y - __bfloat162float(h1)));
        __nv_bfloat162 pl1(__float2bfloat16(v.z - __bfloat162float(h2)),
                           __float2bfloat16(v.w - __bfloat162float(h3)));
        uint2 uh, ul;
        uh.x = *(uint32_t*)&ph0; uh.y = *(uint32_t*)&ph1;
        ul.x = *(uint32_t*)&pl0; ul.y = *(uint32_t*)&pl1;
        dh[i] = uh; dl[i] = ul;
    }
}

// ============================================================================
// bf16x3 grouped GEMMs on mma.sync. BK=64. Flattened tile-map grid.
// A tiles: [128 m][64 k], 128B rows, swizzle: chunk c of row r at r*128+((c^(r&7))<<4)
// B tiles: [64 k][128 n], 256B rows, swizzle: chunk c of row r at r*256+((c^(r&7))<<4)
// B consumed with ldmatrix.x4.trans (two n8 frags per instruction).
// ============================================================================
#define STAGE_F  98304   // Ah,Al (16K ea) + Gh,Gl,Uh,Ul (16K ea); 2 stages
#define STAGE_D  65536   // Ah,Al,Bh,Bl; 3 stages
#define SMEM_F   (2 * STAGE_F)
#define SMEM_D   (3 * STAGE_D)

__device__ __forceinline__ void load_A(uint32_t sb, int tid, const __nv_bfloat16* src,
                                       size_t rstride, int k0, int valid) {
    #pragma unroll
    for (int j = 0; j < 4; j++) {
        int u = tid + j * 256;              // 0..1023
        int r = u >> 3, c = u & 7;
        uint32_t off = (uint32_t)(r * 128 + ((c ^ (r & 7)) << 4));
        cp16(sb + off, src + (size_t)r * rstride + k0 + c * 8, (r < valid) ? 16u : 0u);
    }
}
__device__ __forceinline__ void load_B(uint32_t sb, int tid, const __nv_bfloat16* src,
                                       size_t N, int k0) {
    #pragma unroll
    for (int j = 0; j < 4; j++) {
        int u = tid + j * 256;
        int r = u >> 4, c = u & 15;         // r: 0..63 (k), c: 16B n-chunk
        uint32_t off = (uint32_t)(r * 256 + ((c ^ (r & 7)) << 4));
        cp16(sb + off, src + (size_t)(k0 + r) * N + c * 8, 16u);
    }
}

// load hi+lo B fragments for 4 n8-tiles via 4 x ldmatrix.x4.trans
__device__ __forceinline__ void load_bfrags(uint32_t sb, uint32_t boff, int wn,
                                            uint32_t broff, uint32_t bxor,
                                            int lane, uint32_t bh[4][2], uint32_t bl[4][2]) {
    #pragma unroll
    for (int ntp = 0; ntp < 2; ntp++) {
        uint32_t ch = (uint32_t)(wn * 4 + ntp * 2 + (lane >> 4)) ^ bxor;
        uint32_t ad = sb + boff + broff + (ch << 4);
        uint32_t r4[4];
        ldm_x4t(ad, r4);
        bh[2 * ntp][0] = r4[0]; bh[2 * ntp][1] = r4[1];
        bh[2 * ntp + 1][0] = r4[2]; bh[2 * ntp + 1][1] = r4[3];
        ldm_x4t(ad + 16384, r4);
        bl[2 * ntp][0] = r4[0]; bl[2 * ntp][1] = r4[1];
        bl[2 * ntp + 1][0] = r4[2]; bl[2 * ntp + 1][1] = r4[3];
    }
}

// ---------------- fused gate+up: h = up(x) * silu(gate(x)) -> bf16 hi/lo ----------------
__global__ __launch_bounds__(256, 1) void moe_gateup_kernel() {
    constexpr int KD = H_DIM, NCH = KD / 64;

    const int tile = blockIdx.y;
    if (tile >= g_ntiles) return;
    const int e    = g_tile_e[tile];
    const int bm   = g_tile_bm[tile];
    const int m0   = g_offset[e];
    const int rows = g_offset[e + 1] - m0;
    const int bn   = blockIdx.x * 128;
    const int va   = min(rows - bm, 128);

    extern __shared__ char smem[];
    const uint32_t sbase = smem_u32(smem);
    const int tid = threadIdx.x;
    const int lane = tid & 31, wid = tid >> 5;
    const int wm = wid >> 2, wn = wid & 3;

    const __nv_bfloat16* Ah = g_xh + (size_t)(m0 + bm) * KD;
    const __nv_bfloat16* Al = g_xl + (size_t)(m0 + bm) * KD;
    const __nv_bfloat16* Gh = g_wgh + (size_t)e * KD * I_DIM + bn;
    const __nv_bfloat16* Gl = g_wgl + (size_t)e * KD * I_DIM + bn;
    const __nv_bfloat16* Uh = g_wuh + (size_t)e * KD * I_DIM + bn;
    const __nv_bfloat16* Ul = g_wul + (size_t)e * KD * I_DIM + bn;

    float accg[4][4][4], accu[4][4][4];
    #pragma unroll
    for (int i = 0; i < 4; i++)
        #pragma unroll
        for (int j = 0; j < 4; j++)
            #pragma unroll
            for (int k = 0; k < 4; k++) { accg[i][j][k] = 0.f; accu[i][j][k] = 0.f; }

    auto issue = [&](int c) {
        uint32_t sb = sbase + (uint32_t)(c & 1) * STAGE_F;
        int k0 = c * 64;
        load_A(sb,         tid, Ah, KD, k0, va);
        load_A(sb + 16384, tid, Al, KD, k0, va);
        load_B(sb + 32768, tid, Gh, I_DIM, k0);
        load_B(sb + 49152, tid, Gl, I_DIM, k0);
        load_B(sb + 65536, tid, Uh, I_DIM, k0);
        load_B(sb + 81920, tid, Ul, I_DIM, k0);
        asm volatile("cp.async.commit_group;");
    };

    issue(0);

    for (int c = 0; c < NCH; c++) {
        asm volatile("cp.async.wait_group 0;");
        __syncthreads();
        if (c + 1 < NCH) issue(c + 1);

        const uint32_t sb = sbase + (uint32_t)(c & 1) * STAGE_F;
        #pragma unroll
        for (int s16 = 0; s16 < 4; s16++) {
            // A fragments (hi, lo)
            uint32_t af[2][4][4];
            #pragma unroll
            for (int mt = 0; mt < 4; mt++) {
                int row = wm * 64 + mt * 16 + (lane & 15);
                uint32_t ch = (uint32_t)(2 * s16 + (lane >> 4)) ^ (uint32_t)(row & 7);
                uint32_t ad = sb + (uint32_t)(row * 128) + (ch << 4);
                ldm_x4(ad,         af[0][mt]);
                ldm_x4(ad + 16384, af[1][mt]);
            }
            const int rowb = s16 * 16 + (lane & 15);
            const uint32_t broff = (uint32_t)(rowb * 256);
            const uint32_t bxor  = (uint32_t)(rowb & 7);

            uint32_t bh[4][2], bl[4][2];
            // ---- gate ----
            load_bfrags(sb, 32768, wn, broff, bxor, lane, bh, bl);
            #pragma unroll
            for (int mt = 0; mt < 4; mt++)
                #pragma unroll
                for (int nt = 0; nt < 4; nt++) mma_bf16(accg[mt][nt], af[0][mt], bh[nt]);
            #pragma unroll
            for (int mt = 0; mt < 4; mt++)
                #pragma unroll
                for (int nt = 0; nt < 4; nt++) mma_bf16(accg[mt][nt], af[0][mt], bl[nt]);
            #pragma unroll
            for (int mt = 0; mt < 4; mt++)
                #pragma unroll
                for (int nt = 0; nt < 4; nt++) mma_bf16(accg[mt][nt], af[1][mt], bh[nt]);
            // ---- up ----
            load_bfrags(sb, 65536, wn, broff, bxor, lane, bh, bl);
            #pragma unroll
            for (int mt = 0; mt < 4; mt++)
                #pragma unroll
                for (int nt = 0; nt < 4; nt++) mma_bf16(accu[mt][nt], af[0][mt], bh[nt]);
            #pragma unroll
            for (int mt = 0; mt < 4; mt++)
                #pragma unroll
                for (int nt = 0; nt < 4; nt++) mma_bf16(accu[mt][nt], af[0][mt], bl[nt]);
            #pragma unroll
            for (int mt = 0; mt < 4; mt++)
                #pragma unroll
                for (int nt = 0; nt < 4; nt++) mma_bf16(accu[mt][nt], af[1][mt], bh[nt]);
        }
    }

    // epilogue: h = u*silu(g) in registers -> bf16 hi/lo
    const int lr = lane >> 2;
    const int lc = (lane & 3) * 2;
    #pragma unroll
    for (int mt = 0; mt < 4; mt++) {
        #pragma unroll
        for (int h2 = 0; h2 < 2; h2++) {
            int r = wm * 64 + mt * 16 + lr + h2 * 8;
            if (r < va) {
                size_t grow = (size_t)(m0 + bm + r);
                #pragma unroll
                for (int nt = 0; nt < 4; nt++) {
                    int col = wn * 32 + nt * 8 + lc;
                    float g0 = accg[mt][nt][h2 * 2], g1 = accg[mt][nt][h2 * 2 + 1];
                    float u0 = accu[mt][nt][h2 * 2], u1 = accu[mt][nt][h2 * 2 + 1];
                    float hv0 = u0 * g0 / (1.f + __expf(-g0));
                    float hv1 = u1 * g1 / (1.f + __expf(-g1));
                    __nv_bfloat16 hh0 = __float2bfloat16(hv0);
                    __nv_bfloat16 hh1 = __float2bfloat16(hv1);
                    __nv_bfloat16 hl0 = __float2bfloat16(hv0 - __bfloat162float(hh0));
                    __nv_bfloat16 hl1 = __float2bfloat16(hv1 - __bfloat162float(hh1));
                    *(__nv_bfloat162*)(g_hh + grow * I_DIM + bn + col) = __nv_bfloat162(hh0, hh1);
                    *(__nv_bfloat162*)(g_hl + grow * I_DIM + bn + col) = __nv_bfloat162(hl0, hl1);
                }
            }
        }
    }
}

// ---------------- down-proj: y = (h @ wd) * routing_weight ----------------
__global__ __launch_bounds__(256, 1) void moe_down_kernel() {
    constexpr int KD = I_DIM, ND = H_DIM, NCH = KD / 64;

    const int tile = blockIdx.y;
    if (tile >= g_ntiles) return;
    const int e    = g_tile_e[tile];
    const int bm   = g_tile_bm[tile];
    const int m0   = g_offset[e];
    const int rows = g_offset[e + 1] - m0;
    const int bn   = blockIdx.x * 128;
    const int va   = min(rows - bm, 128);

    extern __shared__ char smem[];
    const uint32_t sbase = smem_u32(smem);
    const int tid = threadIdx.x;
    const int lane = tid & 31, wid = tid >> 5;
    const int wm = wid >> 2, wn = wid & 3;

    const __nv_bfloat16* Ah = g_hh + (size_t)(m0 + bm) * KD;
    const __nv_bfloat16* Al = g_hl + (size_t)(m0 + bm) * KD;
    const __nv_bfloat16* Bh = g_wdh + (size_t)e * KD * ND + bn;
    const __nv_bfloat16* Bl = g_wdl + (size_t)e * KD * ND + bn;

    float acc[4][4][4];
    #pragma unroll
    for (int i = 0; i < 4; i++)
        #pragma unroll
        for (int j = 0; j < 4; j++)
            #pragma unroll
            for (int k = 0; k < 4; k++) acc[i][j][k] = 0.f;

    auto issue = [&](int c) {
        uint32_t sb = sbase + (uint32_t)(c % 3) * STAGE_D;
        int k0 = c * 64;
        load_A(sb,         tid, Ah, KD, k0, va);
        load_A(sb + 16384, tid, Al, KD, k0, va);
        load_B(sb + 32768, tid, Bh, ND, k0);
        load_B(sb + 49152, tid, Bl, ND, k0);
        asm volatile("cp.async.commit_group;");
    };

    issue(0);
    issue(1);

    for (int c = 0; c < NCH; c++) {
        if (c + 1 < NCH) asm volatile("cp.async.wait_group 1;");
        else             asm volatile("cp.async.wait_group 0;");
        __syncthreads();
        if (c + 2 < NCH) issue(c + 2);

        const uint32_t sb = sbase + (uint32_t)(c % 3) * STAGE_D;
        #pragma unroll
        for (int s16 = 0; s16 < 4; s16++) {
            uint32_t af[2][4][4];
            #pragma unroll
            for (int mt = 0; mt < 4; mt++) {
                int row = wm * 64 + mt * 16 + (lane & 15);
                uint32_t ch = (uint32_t)(2 * s16 + (lane >> 4)) ^ (uint32_t)(row & 7);
                uint32_t ad = sb + (uint32_t)(row * 128) + (ch << 4);
                ldm_x4(ad,         af[0][mt]);
                ldm_x4(ad + 16384, af[1][mt]);
            }
            const int rowb = s16 * 16 + (lane & 15);
            const uint32_t broff = (uint32_t)(rowb * 256);
            const uint32_t bxor  = (uint32_t)(rowb & 7);

            uint32_t bh[4][2], bl[4][2];
            load_bfrags(sb, 32768, wn, broff, bxor, lane, bh, bl);
            #pragma unroll
            for (int mt = 0; mt < 4; mt++)
                #pragma unroll
                for (int nt = 0; nt < 4; nt++) mma_bf16(acc[mt][nt], af[0][mt], bh[nt]);
            #pragma unroll
            for (int mt = 0; mt < 4; mt++)
                #pragma unroll
                for (int nt = 0; nt < 4; nt++) mma_bf16(acc[mt][nt], af[0][mt], bl[nt]);
            #pragma unroll
            for (int mt = 0; mt < 4; mt++)
                #pragma unroll
                for (int nt = 0; nt < 4; nt++) mma_bf16(acc[mt][nt], af[1][mt], bh[nt]);
        }
    }

    const int lr = lane >> 2;
    const int lc = (lane & 3) * 2;
    #pragma unroll
    for (int mt = 0; mt < 4; mt++) {
        #pragma unroll
        for (int h2 = 0; h2 < 2; h2++) {
            int r = wm * 64 + mt * 16 + lr + h2 * 8;
            if (r < va) {
                size_t grow = (size_t)(m0 + bm + r);
                float scale = g_w_of_row[grow];
                float* C = g_y + grow * ND + bn;
                #pragma unroll
                for (int nt = 0; nt < 4; nt++) {
                    int col = wn * 32 + nt * 8 + lc;
                    *(float2*)(C + col) = make_float2(acc[mt][nt][h2 * 2] * scale,
                                                      acc[mt][nt][h2 * 2 + 1] * scale);
                }
            }
        }
    }
}

// ---------------- combine ----------------
__global__ void combine_kernel(float* __restrict__ out) {
    int t  = blockIdx.x;
    int r0 = g_rows_of_token[2 * t];
    int r1 = g_rows_of_token[2 * t + 1];
    const float4* y0 = (const float4*)(g_y + (size_t)r0 * H_DIM);
    const float4* y1 = (const float4*)(g_y + (size_t)r1 * H_DIM);
    float4* o = (float4*)(out + (size_t)t * H_DIM);
    for (int i = threadIdx.x; i < H_DIM / 4; i += blockDim.x) {
        float4 a = y0[i], b = y1[i];
        o[i] = make_float4(a.x + b.x, a.y + b.y, a.z + b.z, a.w + b.w);
    }
}

// ---------------- launch ----------------
extern "C" void kernel_launch(void* const* d_in, const int* in_sizes, int n_in,
                              void* d_out, int out_size) {
    const float* x   = (const float*)d_in[0];
    const float* wg  = (const float*)d_in[1];
    const float* wgp = (const float*)d_in[2];
    const float* wup = (const float*)d_in[3];
    const float* wdp = (const float*)d_in[4];
    float* out = (float*)d_out;

    cudaFuncSetAttribute(moe_gateup_kernel, cudaFuncAttributeMaxDynamicSharedMemorySize, SMEM_F);
    cudaFuncSetAttribute(moe_down_kernel,   cudaFuncAttributeMaxDynamicSharedMemorySize, SMEM_D);

    zero_kernel<<<1, 32>>>();
    router_kernel<<<T_TOK / 8, 256>>>(x, wg);
    scan_kernel<<<1, 1>>>();
    assign_kernel<<<T_TOK / 256, 256>>>();
    gather_kernel<<<NROWS, 128>>>(x);

    const int n4 = N_EXP * H_DIM * I_DIM / 4;
    split_w_all<<<dim3(2048, 1, 3), 256>>>((const float4*)wgp, (const float4*)wup,
                                           (const float4*)wdp, n4);

    moe_gateup_kernel<<<dim3(I_DIM / 128, 272), 256, SMEM_F>>>();
    moe_down_kernel<<<dim3(H_DIM / 128, 272), 256, SMEM_D>>>();

    combine_kernel<<<T_TOK, 256>>>(out);
}

// round 13
// speedup vs baseline: 3.2287x; 1.0317x over previous
#include <cuda_runtime.h>
#include <cuda_bf16.h>
#include <cstdint>

#define T_TOK 16384
#define H_DIM 1024
#define I_DIM 2048
#define N_EXP 16
#define NROWS (T_TOK * 2)
#define MAXTILES 288

// ---------------- routing scratch ----------------
__device__ int   g_count[N_EXP];
__device__ int   g_cursor[N_EXP];
__device__ int   g_offset[N_EXP + 1];
__device__ int   g_ntiles;
__device__ int   g_tile_e[MAXTILES];
__device__ int   g_tile_bm[MAXTILES];
__device__ int   g_e0[T_TOK];
__device__ int   g_e1[T_TOK];
__device__ float g_w0[T_TOK];
__device__ float g_w1[T_TOK];
__device__ int   g_token_of_row[NROWS];
__device__ float g_w_of_row[NROWS];
__device__ int   g_rows_of_token[NROWS];

// ---------------- data buffers ----------------
// weights kept in NATIVE [E][K][N] layout, split hi/lo (no transpose)
__device__ __nv_bfloat16 g_xh[(size_t)NROWS * H_DIM];
__device__ __nv_bfloat16 g_xl[(size_t)NROWS * H_DIM];
__device__ __nv_bfloat16 g_wgh[(size_t)N_EXP * H_DIM * I_DIM];
__device__ __nv_bfloat16 g_wgl[(size_t)N_EXP * H_DIM * I_DIM];
__device__ __nv_bfloat16 g_wuh[(size_t)N_EXP * H_DIM * I_DIM];
__device__ __nv_bfloat16 g_wul[(size_t)N_EXP * H_DIM * I_DIM];
__device__ __nv_bfloat16 g_wdh[(size_t)N_EXP * I_DIM * H_DIM];
__device__ __nv_bfloat16 g_wdl[(size_t)N_EXP * I_DIM * H_DIM];
__device__ __nv_bfloat16 g_hh[(size_t)NROWS * I_DIM];
__device__ __nv_bfloat16 g_hl[(size_t)NROWS * I_DIM];
__device__ float         g_y[(size_t)NROWS * H_DIM];

// ---------------- ptx helpers ----------------
__device__ __forceinline__ uint32_t smem_u32(const void* p) {
    uint32_t a;
    asm("{ .reg .u64 t; cvta.to.shared.u64 t, %1; cvt.u32.u64 %0, t; }" : "=r"(a) : "l"(p));
    return a;
}
__device__ __forceinline__ void cp16(uint32_t dst, const void* src, uint32_t sz) {
    asm volatile("cp.async.cg.shared.global [%0], [%1], 16, %2;"
                 :: "r"(dst), "l"(src), "r"(sz));
}
__device__ __forceinline__ void ldm_x4(uint32_t a, uint32_t r[4]) {
    asm volatile("ldmatrix.sync.aligned.m8n8.x4.shared.b16 {%0,%1,%2,%3}, [%4];"
                 : "=r"(r[0]), "=r"(r[1]), "=r"(r[2]), "=r"(r[3]) : "r"(a));
}
__device__ __forceinline__ void ldm_x4t(uint32_t a, uint32_t r[4]) {
    asm volatile("ldmatrix.sync.aligned.m8n8.x4.trans.shared.b16 {%0,%1,%2,%3}, [%4];"
                 : "=r"(r[0]), "=r"(r[1]), "=r"(r[2]), "=r"(r[3]) : "r"(a));
}
__device__ __forceinline__ void mma_bf16(float* c, const uint32_t* a, const uint32_t* b) {
    asm volatile(
        "mma.sync.aligned.m16n8k16.row.col.f32.bf16.bf16.f32 "
        "{%0,%1,%2,%3}, {%4,%5,%6,%7}, {%8,%9}, {%0,%1,%2,%3};"
        : "+f"(c[0]), "+f"(c[1]), "+f"(c[2]), "+f"(c[3])
        : "r"(a[0]), "r"(a[1]), "r"(a[2]), "r"(a[3]), "r"(b[0]), "r"(b[1]));
}

// ---------------- small kernels (routing path) ----------------
__global__ void zero_kernel() {
    int i = threadIdx.x;
    if (i < N_EXP) { g_count[i] = 0; g_cursor[i] = 0; }
}

__global__ void router_kernel(const float* __restrict__ x, const float* __restrict__ wg) {
    int warp = (blockIdx.x * blockDim.x + threadIdx.x) >> 5;
    int lane = threadIdx.x & 31;
    if (warp >= T_TOK) return;
    int t = warp;
    const float* xr = x + (size_t)t * H_DIM;
    int e  = lane & 15;
    int k0 = (lane >> 4) * (H_DIM / 2);

    float acc = 0.f;
    for (int k = k0; k < k0 + H_DIM / 2; k++)
        acc = fmaf(xr[k], wg[k * N_EXP + e], acc);
    acc += __shfl_xor_sync(0xffffffffu, acc, 16);

    float v = acc; int idx = e;
    #pragma unroll
    for (int s = 16; s; s >>= 1) {
        float ov = __shfl_xor_sync(0xffffffffu, v, s);
        int   oi = __shfl_xor_sync(0xffffffffu, idx, s);
        if (ov > v || (ov == v && oi < idx)) { v = ov; idx = oi; }
    }
    float l1 = v; int i1 = idx;

    v = (e == i1) ? -1e30f : acc; idx = e;
    #pragma unroll
    for (int s = 16; s; s >>= 1) {
        float ov = __shfl_xor_sync(0xffffffffu, v, s);
        int   oi = __shfl_xor_sync(0xffffffffu, idx, s);
        if (ov > v || (ov == v && oi < idx)) { v = ov; idx = oi; }
    }
    float l2 = v; int i2 = idx;

    if (lane == 0) {
        float r  = __expf(l2 - l1);
        float w0 = 1.f / (1.f + r);
        g_e0[t] = i1; g_e1[t] = i2;
        g_w0[t] = w0; g_w1[t] = 1.f - w0;
        atomicAdd(&g_count[i1], 1);
        atomicAdd(&g_count[i2], 1);
    }
}

// scan + build exact tile map (<= 272 live m-tiles)
__global__ void scan_kernel() {
    if (threadIdx.x == 0) {
        int o = 0, tt = 0;
        for (int e = 0; e < N_EXP; e++) {
            g_offset[e] = o;
            int cnt = g_count[e];
            for (int bm = 0; bm < cnt; bm += 128) {
                g_tile_e[tt] = e; g_tile_bm[tt] = bm; tt++;
            }
            o += cnt;
        }
        g_offset[N_EXP] = o;
        g_ntiles = tt;
    }
}

__global__ void assign_kernel() {
    int t = blockIdx.x * blockDim.x + threadIdx.x;
    if (t >= T_TOK) return;
    int e0 = g_e0[t];
    int r0 = g_offset[e0] + atomicAdd(&g_cursor[e0], 1);
    g_token_of_row[r0] = t; g_w_of_row[r0] = g_w0[t]; g_rows_of_token[2 * t] = r0;
    int e1 = g_e1[t];
    int r1 = g_offset[e1] + atomicAdd(&g_cursor[e1], 1);
    g_token_of_row[r1] = t; g_w_of_row[r1] = g_w1[t]; g_rows_of_token[2 * t + 1] = r1;
}

__global__ void gather_kernel(const float* __restrict__ x) {
    int row = blockIdx.x;
    int t = g_token_of_row[row];
    const float4* src = (const float4*)(x + (size_t)t * H_DIM);
    __nv_bfloat16* dh = g_xh + (size_t)row * H_DIM;
    __nv_bfloat16* dl = g_xl + (size_t)row * H_DIM;
    for (int i = threadIdx.x; i < H_DIM / 4; i += 128) {
        float4 v = src[i];
        __nv_bfloat16 h0 = __float2bfloat16(v.x);
        __nv_bfloat16 h1 = __float2bfloat16(v.y);
        __nv_bfloat16 h2 = __float2bfloat16(v.z);
        __nv_bfloat16 h3 = __float2bfloat16(v.w);
        __nv_bfloat16 l0 = __float2bfloat16(v.x - __bfloat162float(h0));
        __nv_bfloat16 l1 = __float2bfloat16(v.y - __bfloat162float(h1));
        __nv_bfloat16 l2 = __float2bfloat16(v.z - __bfloat162float(h2));
        __nv_bfloat16 l3 = __float2bfloat16(v.w - __bfloat162float(h3));
        __nv_bfloat162* ph = (__nv_bfloat162*)(dh + i * 4);
        __nv_bfloat162* pl = (__nv_bfloat162*)(dl + i * 4);
        ph[0] = __nv_bfloat162(h0, h1); ph[1] = __nv_bfloat162(h2, h3);
        pl[0] = __nv_bfloat162(l0, l1); pl[1] = __nv_bfloat162(l2, l3);
    }
}

// streaming hi/lo split of all 3 weight tensors in one launch (grid.z selects tensor)
__global__ void split_w_all(const float4* __restrict__ w0, const float4* __restrict__ w1,
                            const float4* __restrict__ w2, int n4) {
    int z = blockIdx.z;
    const float4* src = (z == 0) ? w0 : (z == 1) ? w1 : w2;
    uint2* dh = (z == 0) ? (uint2*)g_wgh : (z == 1) ? (uint2*)g_wuh : (uint2*)g_wdh;
    uint2* dl = (z == 0) ? (uint2*)g_wgl : (z == 1) ? (uint2*)g_wul : (uint2*)g_wdl;
    int i = blockIdx.x * blockDim.x + threadIdx.x;
    int stride = gridDim.x * blockDim.x;
    for (; i < n4; i += stride) {
        float4 v = src[i];
        __nv_bfloat16 h0 = __float2bfloat16(v.x);
        __nv_bfloat16 h1 = __float2bfloat16(v.y);
        __nv_bfloat16 h2 = __float2bfloat16(v.z);
        __nv_bfloat16 h3 = __float2bfloat16(v.w);
        __nv_bfloat162 ph0(h0, h1), ph1(h2, h3);
        __nv_bfloat162 pl0(__float2bfloat16(v.x - __bfloat162float(h0)),
                           __float2bfloat16(v.y - __bfloat162float(h1)));
        __nv_bfloat162 pl1(__float2bfloat16(v.z - __bfloat162float(h2)),
                           __float2bfloat16(v.w - __bfloat162float(h3)));
        uint2 uh, ul;
        uh.x = *(uint32_t*)&ph0; uh.y = *(uint32_t*)&ph1;
        ul.x = *(uint32_t*)&pl0; ul.y = *(uint32_t*)&pl1;
        dh[i] = uh; dl[i] = ul;
    }
}

// ============================================================================
// bf16x3 grouped GEMMs on mma.sync. Flattened tile-map grid.
// A tiles: 128B rows, swizzle: chunk c of row r at r*128+((c^(r&7))<<4)
// B tiles: 256B rows, swizzle: chunk c of row r at r*256+((c^(r&7))<<4)
// B consumed with ldmatrix.x4.trans (weights in native [K][N] layout).
// ============================================================================
#define STAGE_F  98304   // gateup BK=64: Ah,Al (16K) + Gh,Gl,Uh,Ul (16K); 2 stages, occ 1
#define STAGE_D  49152   // down  BK=32: Ah,Al (16K, half-filled rows) + Bh,Bl (8K); 2 stages, occ 2
#define SMEM_F   (2 * STAGE_F)
#define SMEM_D   (2 * STAGE_D)

__device__ __forceinline__ void load_A(uint32_t sb, int tid, const __nv_bfloat16* src,
                                       size_t rstride, int k0, int valid) {
    #pragma unroll
    for (int j = 0; j < 4; j++) {
        int u = tid + j * 256;              // 0..1023
        int r = u >> 3, c = u & 7;
        uint32_t off = (uint32_t)(r * 128 + ((c ^ (r & 7)) << 4));
        cp16(sb + off, src + (size_t)r * rstride + k0 + c * 8, (r < valid) ? 16u : 0u);
    }
}
// BK=32 A loader: 128B rows, only chunks 0..3 live (k 0..31)
__device__ __forceinline__ void load_A32(uint32_t sb, int tid, const __nv_bfloat16* src,
                                         size_t rstride, int k0, int valid) {
    #pragma unroll
    for (int j = 0; j < 2; j++) {
        int u = tid + j * 256;              // 0..511
        int r = u >> 2, c = u & 3;
        uint32_t off = (uint32_t)(r * 128 + ((c ^ (r & 7)) << 4));
        cp16(sb + off, src + (size_t)r * rstride + k0 + c * 8, (r < valid) ? 16u : 0u);
    }
}
__device__ __forceinline__ void load_B(uint32_t sb, int tid, const __nv_bfloat16* src,
                                       size_t N, int k0) {
    #pragma unroll
    for (int j = 0; j < 4; j++) {
        int u = tid + j * 256;
        int r = u >> 4, c = u & 15;         // r: 0..63 (k), c: 16B n-chunk
        uint32_t off = (uint32_t)(r * 256 + ((c ^ (r & 7)) << 4));
        cp16(sb + off, src + (size_t)(k0 + r) * N + c * 8, 16u);
    }
}
// BK=32 B loader: 32 k-rows
__device__ __forceinline__ void load_B32(uint32_t sb, int tid, const __nv_bfloat16* src,
                                         size_t N, int k0) {
    #pragma unroll
    for (int j = 0; j < 2; j++) {
        int u = tid + j * 256;              // 0..511
        int r = u >> 4, c = u & 15;         // r: 0..31
        uint32_t off = (uint32_t)(r * 256 + ((c ^ (r & 7)) << 4));
        cp16(sb + off, src + (size_t)(k0 + r) * N + c * 8, 16u);
    }
}

// load hi+lo B fragments for 4 n8-tiles via 4 x ldmatrix.x4.trans
__device__ __forceinline__ void load_bfrags(uint32_t sb, uint32_t boff, uint32_t lo_delta,
                                            int wn, uint32_t broff, uint32_t bxor,
                                            int lane, uint32_t bh[4][2], uint32_t bl[4][2]) {
    #pragma unroll
    for (int ntp = 0; ntp < 2; ntp++) {
        uint32_t ch = (uint32_t)(wn * 4 + ntp * 2 + (lane >> 4)) ^ bxor;
        uint32_t ad = sb + boff + broff + (ch << 4);
        uint32_t r4[4];
        ldm_x4t(ad, r4);
        bh[2 * ntp][0] = r4[0]; bh[2 * ntp][1] = r4[1];
        bh[2 * ntp + 1][0] = r4[2]; bh[2 * ntp + 1][1] = r4[3];
        ldm_x4t(ad + lo_delta, r4);
        bl[2 * ntp][0] = r4[0]; bl[2 * ntp][1] = r4[1];
        bl[2 * ntp + 1][0] = r4[2]; bl[2 * ntp + 1][1] = r4[3];
    }
}

// ---------------- fused gate+up: h = up(x) * silu(gate(x)) -> bf16 hi/lo ----------------
__global__ __launch_bounds__(256, 1) void moe_gateup_kernel() {
    constexpr int KD = H_DIM, NCH = KD / 64;

    const int tile = blockIdx.y;
    if (tile >= g_ntiles) return;
    const int e    = g_tile_e[tile];
    const int bm   = g_tile_bm[tile];
    const int m0   = g_offset[e];
    const int rows = g_offset[e + 1] - m0;
    const int bn   = blockIdx.x * 128;
    const int va   = min(rows - bm, 128);

    extern __shared__ char smem[];
    const uint32_t sbase = smem_u32(smem);
    const int tid = threadIdx.x;
    const int lane = tid & 31, wid = tid >> 5;
    const int wm = wid >> 2, wn = wid & 3;

    const __nv_bfloat16* Ah = g_xh + (size_t)(m0 + bm) * KD;
    const __nv_bfloat16* Al = g_xl + (size_t)(m0 + bm) * KD;
    const __nv_bfloat16* Gh = g_wgh + (size_t)e * KD * I_DIM + bn;
    const __nv_bfloat16* Gl = g_wgl + (size_t)e * KD * I_DIM + bn;
    const __nv_bfloat16* Uh = g_wuh + (size_t)e * KD * I_DIM + bn;
    const __nv_bfloat16* Ul = g_wul + (size_t)e * KD * I_DIM + bn;

    float accg[4][4][4], accu[4][4][4];
    #pragma unroll
    for (int i = 0; i < 4; i++)
        #pragma unroll
        for (int j = 0; j < 4; j++)
            #pragma unroll
            for (int k = 0; k < 4; k++) { accg[i][j][k] = 0.f; accu[i][j][k] = 0.f; }

    auto issue = [&](int c) {
        uint32_t sb = sbase + (uint32_t)(c & 1) * STAGE_F;
        int k0 = c * 64;
        load_A(sb,         tid, Ah, KD, k0, va);
        load_A(sb + 16384, tid, Al, KD, k0, va);
        load_B(sb + 32768, tid, Gh, I_DIM, k0);
        load_B(sb + 49152, tid, Gl, I_DIM, k0);
        load_B(sb + 65536, tid, Uh, I_DIM, k0);
        load_B(sb + 81920, tid, Ul, I_DIM, k0);
        asm volatile("cp.async.commit_group;");
    };

    issue(0);

    for (int c = 0; c < NCH; c++) {
        asm volatile("cp.async.wait_group 0;");
        __syncthreads();
        if (c + 1 < NCH) issue(c + 1);

        const uint32_t sb = sbase + (uint32_t)(c & 1) * STAGE_F;
        #pragma unroll
        for (int s16 = 0; s16 < 4; s16++) {
            // A fragments (hi, lo)
            uint32_t af[2][4][4];
            #pragma unroll
            for (int mt = 0; mt < 4; mt++) {
                int row = wm * 64 + mt * 16 + (lane & 15);
                uint32_t ch = (uint32_t)(2 * s16 + (lane >> 4)) ^ (uint32_t)(row & 7);
                uint32_t ad = sb + (uint32_t)(row * 128) + (ch << 4);
                ldm_x4(ad,         af[0][mt]);
                ldm_x4(ad + 16384, af[1][mt]);
            }
            const int rowb = s16 * 16 + (lane & 15);
            const uint32_t broff = (uint32_t)(rowb * 256);
            const uint32_t bxor  = (uint32_t)(rowb & 7);

            uint32_t bh[4][2], bl[4][2];
            // ---- gate ----
            load_bfrags(sb, 32768, 16384, wn, broff, bxor, lane, bh, bl);
            #pragma unroll
            for (int mt = 0; mt < 4; mt++)
                #pragma unroll
                for (int nt = 0; nt < 4; nt++) mma_bf16(accg[mt][nt], af[0][mt], bh[nt]);
            #pragma unroll
            for (int mt = 0; mt < 4; mt++)
                #pragma unroll
                for (int nt = 0; nt < 4; nt++) mma_bf16(accg[mt][nt], af[0][mt], bl[nt]);
            #pragma unroll
            for (int mt = 0; mt < 4; mt++)
                #pragma unroll
                for (int nt = 0; nt < 4; nt++) mma_bf16(accg[mt][nt], af[1][mt], bh[nt]);
            // ---- up ----
            load_bfrags(sb, 65536, 16384, wn, broff, bxor, lane, bh, bl);
            #pragma unroll
            for (int mt = 0; mt < 4; mt++)
                #pragma unroll
                for (int nt = 0; nt < 4; nt++) mma_bf16(accu[mt][nt], af[0][mt], bh[nt]);
            #pragma unroll
            for (int mt = 0; mt < 4; mt++)
                #pragma unroll
                for (int nt = 0; nt < 4; nt++) mma_bf16(accu[mt][nt], af[0][mt], bl[nt]);
            #pragma unroll
            for (int mt = 0; mt < 4; mt++)
                #pragma unroll
                for (int nt = 0; nt < 4; nt++) mma_bf16(accu[mt][nt], af[1][mt], bh[nt]);
        }
    }

    // epilogue: h = u*silu(g) in registers -> bf16 hi/lo
    const int lr = lane >> 2;
    const int lc = (lane & 3) * 2;
    #pragma unroll
    for (int mt = 0; mt < 4; mt++) {
        #pragma unroll
        for (int h2 = 0; h2 < 2; h2++) {
            int r = wm * 64 + mt * 16 + lr + h2 * 8;
            if (r < va) {
                size_t grow = (size_t)(m0 + bm + r);
                #pragma unroll
                for (int nt = 0; nt < 4; nt++) {
                    int col = wn * 32 + nt * 8 + lc;
                    float g0 = accg[mt][nt][h2 * 2], g1 = accg[mt][nt][h2 * 2 + 1];
                    float u0 = accu[mt][nt][h2 * 2], u1 = accu[mt][nt][h2 * 2 + 1];
                    float hv0 = u0 * g0 * __frcp_rn(1.f + __expf(-g0));
                    float hv1 = u1 * g1 * __frcp_rn(1.f + __expf(-g1));
                    __nv_bfloat16 hh0 = __float2bfloat16(hv0);
                    __nv_bfloat16 hh1 = __float2bfloat16(hv1);
                    __nv_bfloat16 hl0 = __float2bfloat16(hv0 - __bfloat162float(hh0));
                    __nv_bfloat16 hl1 = __float2bfloat16(hv1 - __bfloat162float(hh1));
                    *(__nv_bfloat162*)(g_hh + grow * I_DIM + bn + col) = __nv_bfloat162(hh0, hh1);
                    *(__nv_bfloat162*)(g_hl + grow * I_DIM + bn + col) = __nv_bfloat162(hl0, hl1);
                }
            }
        }
    }
}

// ---------------- down-proj: y = (h @ wd) * routing_weight  [BK=32, occ 2] ----------------
__global__ __launch_bounds__(256, 2) void moe_down_kernel() {
    constexpr int KD = I_DIM, ND = H_DIM, NCH = KD / 32;

    const int tile = blockIdx.y;
    if (tile >= g_ntiles) return;
    const int e    = g_tile_e[tile];
    const int bm   = g_tile_bm[tile];
    const int m0   = g_offset[e];
    const int rows = g_offset[e + 1] - m0;
    const int bn   = blockIdx.x * 128;
    const int va   = min(rows - bm, 128);

    extern __shared__ char smem[];
    const uint32_t sbase = smem_u32(smem);
    const int tid = threadIdx.x;
    const int lane = tid & 31, wid = tid >> 5;
    const int wm = wid >> 2, wn = wid & 3;

    const __nv_bfloat16* Ah = g_hh + (size_t)(m0 + bm) * KD;
    const __nv_bfloat16* Al = g_hl + (size_t)(m0 + bm) * KD;
    const __nv_bfloat16* Bh = g_wdh + (size_t)e * KD * ND + bn;
    const __nv_bfloat16* Bl = g_wdl + (size_t)e * KD * ND + bn;

    float acc[4][4][4];
    #pragma unroll
    for (int i = 0; i < 4; i++)
        #pragma unroll
        for (int j = 0; j < 4; j++)
            #pragma unroll
            for (int k = 0; k < 4; k++) acc[i][j][k] = 0.f;

    auto issue = [&](int c) {
        uint32_t sb = sbase + (uint32_t)(c & 1) * STAGE_D;
        int k0 = c * 32;
        load_A32(sb,         tid, Ah, KD, k0, va);
        load_A32(sb + 16384, tid, Al, KD, k0, va);
        load_B32(sb + 32768, tid, Bh, ND, k0);
        load_B32(sb + 40960, tid, Bl, ND, k0);
        asm volatile("cp.async.commit_group;");
    };

    issue(0);

    for (int c = 0; c < NCH; c++) {
        asm volatile("cp.async.wait_group 0;");
        __syncthreads();
        if (c + 1 < NCH) issue(c + 1);

        const uint32_t sb = sbase + (uint32_t)(c & 1) * STAGE_D;
        #pragma unroll
        for (int s16 = 0; s16 < 2; s16++) {
            // single A-frag buffer, reused hi -> lo (register diet for occ 2)
            uint32_t af[4][4];
            #pragma unroll
            for (int mt = 0; mt < 4; mt++) {
                int row = wm * 64 + mt * 16 + (lane & 15);
                uint32_t ch = (uint32_t)(2 * s16 + (lane >> 4)) ^ (uint32_t)(row & 7);
                ldm_x4(sb + (uint32_t)(row * 128) + (ch << 4), af[mt]);
            }
            const int rowb = s16 * 16 + (lane & 15);
            const uint32_t broff = (uint32_t)(rowb * 256);
            const uint32_t bxor  = (uint32_t)(rowb & 7);

            uint32_t bh[4][2], bl[4][2];
            load_bfrags(sb, 32768, 8192, wn, broff, bxor, lane, bh, bl);
            #pragma unroll
            for (int mt = 0; mt < 4; mt++)
                #pragma unroll
                for (int nt = 0; nt < 4; nt++) mma_bf16(acc[mt][nt], af[mt], bh[nt]);
            #pragma unroll
            for (int mt = 0; mt < 4; mt++)
                #pragma unroll
                for (int nt = 0; nt < 4; nt++) mma_bf16(acc[mt][nt], af[mt], bl[nt]);
            // overwrite A-frags with lo
            #pragma unroll
            for (int mt = 0; mt < 4; mt++) {
                int row = wm * 64 + mt * 16 + (lane & 15);
                uint32_t ch = (uint32_t)(2 * s16 + (lane >> 4)) ^ (uint32_t)(row & 7);
                ldm_x4(sb + 16384 + (uint32_t)(row * 128) + (ch << 4), af[mt]);
            }
            #pragma unroll
            for (int mt = 0; mt < 4; mt++)
                #pragma unroll
                for (int nt = 0; nt < 4; nt++) mma_bf16(acc[mt][nt], af[mt], bh[nt]);
        }
    }

    const int lr = lane >> 2;
    const int lc = (lane & 3) * 2;
    #pragma unroll
    for (int mt = 0; mt < 4; mt++) {
        #pragma unroll
        for (int h2 = 0; h2 < 2; h2++) {
            int r = wm * 64 + mt * 16 + lr + h2 * 8;
            if (r < va) {
                size_t grow = (size_t)(m0 + bm + r);
                float scale = g_w_of_row[grow];
                float* C = g_y + grow * ND + bn;
                #pragma unroll
                for (int nt = 0; nt < 4; nt++) {
                    int col = wn * 32 + nt * 8 + lc;
                    *(float2*)(C + col) = make_float2(acc[mt][nt][h2 * 2] * scale,
                                                      acc[mt][nt][h2 * 2 + 1] * scale);
                }
            }
        }
    }
}

// ---------------- combine ----------------
__global__ void combine_kernel(float* __restrict__ out) {
    int t  = blockIdx.x;
    int r0 = g_rows_of_token[2 * t];
    int r1 = g_rows_of_token[2 * t + 1];
    const float4* y0 = (const float4*)(g_y + (size_t)r0 * H_DIM);
    const float4* y1 = (const float4*)(g_y + (size_t)r1 * H_DIM);
    float4* o = (float4*)(out + (size_t)t * H_DIM);
    for (int i = threadIdx.x; i < H_DIM / 4; i += blockDim.x) {
        float4 a = y0[i], b = y1[i];
        o[i] = make_float4(a.x + b.x, a.y + b.y, a.z + b.z, a.w + b.w);
    }
}

// ---------------- launch ----------------
extern "C" void kernel_launch(void* const* d_in, const int* in_sizes, int n_in,
                              void* d_out, int out_size) {
    const float* x   = (const float*)d_in[0];
    const float* wg  = (const float*)d_in[1];
    const float* wgp = (const float*)d_in[2];
    const float* wup = (const float*)d_in[3];
    const float* wdp = (const float*)d_in[4];
    float* out = (float*)d_out;

    cudaFuncSetAttribute(moe_gateup_kernel, cudaFuncAttributeMaxDynamicSharedMemorySize, SMEM_F);
    cudaFuncSetAttribute(moe_down_kernel,   cudaFuncAttributeMaxDynamicSharedMemorySize, SMEM_D);

    zero_kernel<<<1, 32>>>();
    router_kernel<<<T_TOK / 8, 256>>>(x, wg);
    scan_kernel<<<1, 1>>>();
    assign_kernel<<<T_TOK / 256, 256>>>();
    gather_kernel<<<NROWS, 128>>>(x);

    const int n4 = N_EXP * H_DIM * I_DIM / 4;
    split_w_all<<<dim3(2048, 1, 3), 256>>>((const float4*)wgp, (const float4*)wup,
                                           (const float4*)wdp, n4);

    moe_gateup_kernel<<<dim3(I_DIM / 128, 272), 256, SMEM_F>>>();
    moe_down_kernel<<<dim3(H_DIM / 128, 272), 256, SMEM_D>>>();

    combine_kernel<<<T_TOK, 256>>>(out);
}

// round 15
// speedup vs baseline: 3.2415x; 1.0040x over previous
#include <cuda_runtime.h>
#include <cuda_bf16.h>
#include <cstdint>

#define T_TOK 16384
#define H_DIM 1024
#define I_DIM 2048
#define N_EXP 16
#define NROWS (T_TOK * 2)
#define MAXTILES 288

// ---------------- routing scratch ----------------
__device__ int   g_count[N_EXP];
__device__ int   g_cursor[N_EXP];
__device__ int   g_offset[N_EXP + 1];
__device__ int   g_ntiles;
__device__ int   g_tile_e[MAXTILES];
__device__ int   g_tile_bm[MAXTILES];
__device__ int   g_e0[T_TOK];
__device__ int   g_e1[T_TOK];
__device__ float g_w0[T_TOK];
__device__ float g_w1[T_TOK];
__device__ int   g_token_of_row[NROWS];
__device__ float g_w_of_row[NROWS];
__device__ int   g_rows_of_token[NROWS];

// ---------------- data buffers ----------------
// weights kept in NATIVE [E][K][N] layout, split hi/lo (no transpose)
__device__ __nv_bfloat16 g_xh[(size_t)NROWS * H_DIM];
__device__ __nv_bfloat16 g_xl[(size_t)NROWS * H_DIM];
__device__ __nv_bfloat16 g_wgh[(size_t)N_EXP * H_DIM * I_DIM];
__device__ __nv_bfloat16 g_wgl[(size_t)N_EXP * H_DIM * I_DIM];
__device__ __nv_bfloat16 g_wuh[(size_t)N_EXP * H_DIM * I_DIM];
__device__ __nv_bfloat16 g_wul[(size_t)N_EXP * H_DIM * I_DIM];
__device__ __nv_bfloat16 g_wdh[(size_t)N_EXP * I_DIM * H_DIM];
__device__ __nv_bfloat16 g_wdl[(size_t)N_EXP * I_DIM * H_DIM];
__device__ __nv_bfloat16 g_hh[(size_t)NROWS * I_DIM];
__device__ __nv_bfloat16 g_hl[(size_t)NROWS * I_DIM];
__device__ float         g_y[(size_t)NROWS * H_DIM];

// ---------------- ptx helpers ----------------
__device__ __forceinline__ uint32_t smem_u32(const void* p) {
    uint32_t a;
    asm("{ .reg .u64 t; cvta.to.shared.u64 t, %1; cvt.u32.u64 %0, t; }" : "=r"(a) : "l"(p));
    return a;
}
__device__ __forceinline__ void cp16(uint32_t dst, const void* src, uint32_t sz) {
    asm volatile("cp.async.cg.shared.global [%0], [%1], 16, %2;"
                 :: "r"(dst), "l"(src), "r"(sz));
}
__device__ __forceinline__ void ldm_x4(uint32_t a, uint32_t r[4]) {
    asm volatile("ldmatrix.sync.aligned.m8n8.x4.shared.b16 {%0,%1,%2,%3}, [%4];"
                 : "=r"(r[0]), "=r"(r[1]), "=r"(r[2]), "=r"(r[3]) : "r"(a));
}
__device__ __forceinline__ void ldm_x4t(uint32_t a, uint32_t r[4]) {
    asm volatile("ldmatrix.sync.aligned.m8n8.x4.trans.shared.b16 {%0,%1,%2,%3}, [%4];"
                 : "=r"(r[0]), "=r"(r[1]), "=r"(r[2]), "=r"(r[3]) : "r"(a));
}
__device__ __forceinline__ void mma_bf16(float* c, const uint32_t* a, const uint32_t* b) {
    asm volatile(
        "mma.sync.aligned.m16n8k16.row.col.f32.bf16.bf16.f32 "
        "{%0,%1,%2,%3}, {%4,%5,%6,%7}, {%8,%9}, {%0,%1,%2,%3};"
        : "+f"(c[0]), "+f"(c[1]), "+f"(c[2]), "+f"(c[3])
        : "r"(a[0]), "r"(a[1]), "r"(a[2]), "r"(a[3]), "r"(b[0]), "r"(b[1]));
}

// ---------------- small kernels (routing path) ----------------
__global__ void zero_kernel() {
    int i = threadIdx.x;
    if (i < N_EXP) { g_count[i] = 0; g_cursor[i] = 0; }
}

__global__ void router_kernel(const float* __restrict__ x, const float* __restrict__ wg) {
    int warp = (blockIdx.x * blockDim.x + threadIdx.x) >> 5;
    int lane = threadIdx.x & 31;
    if (warp >= T_TOK) return;
    int t = warp;
    const float* xr = x + (size_t)t * H_DIM;
    int e  = lane & 15;
    int k0 = (lane >> 4) * (H_DIM / 2);

    float acc = 0.f;
    for (int k = k0; k < k0 + H_DIM / 2; k++)
        acc = fmaf(xr[k], wg[k * N_EXP + e], acc);
    acc += __shfl_xor_sync(0xffffffffu, acc, 16);

    float v = acc; int idx = e;
    #pragma unroll
    for (int s = 16; s; s >>= 1) {
        float ov = __shfl_xor_sync(0xffffffffu, v, s);
        int   oi = __shfl_xor_sync(0xffffffffu, idx, s);
        if (ov > v || (ov == v && oi < idx)) { v = ov; idx = oi; }
    }
    float l1 = v; int i1 = idx;

    v = (e == i1) ? -1e30f : acc; idx = e;
    #pragma unroll
    for (int s = 16; s; s >>= 1) {
        float ov = __shfl_xor_sync(0xffffffffu, v, s);
        int   oi = __shfl_xor_sync(0xffffffffu, idx, s);
        if (ov > v || (ov == v && oi < idx)) { v = ov; idx = oi; }
    }
    float l2 = v; int i2 = idx;

    if (lane == 0) {
        float r  = __expf(l2 - l1);
        float w0 = 1.f / (1.f + r);
        g_e0[t] = i1; g_e1[t] = i2;
        g_w0[t] = w0; g_w1[t] = 1.f - w0;
        atomicAdd(&g_count[i1], 1);
        atomicAdd(&g_count[i2], 1);
    }
}

// scan + build exact tile map (<= 272 live m-tiles)
__global__ void scan_kernel() {
    if (threadIdx.x == 0) {
        int o = 0, tt = 0;
        for (int e = 0; e < N_EXP; e++) {
            g_offset[e] = o;
            int cnt = g_count[e];
            for (int bm = 0; bm < cnt; bm += 128) {
                g_tile_e[tt] = e; g_tile_bm[tt] = bm; tt++;
            }
            o += cnt;
        }
        g_offset[N_EXP] = o;
        g_ntiles = tt;
    }
}

__global__ void assign_kernel() {
    int t = blockIdx.x * blockDim.x + threadIdx.x;
    if (t >= T_TOK) return;
    int e0 = g_e0[t];
    int r0 = g_offset[e0] + atomicAdd(&g_cursor[e0], 1);
    g_token_of_row[r0] = t; g_w_of_row[r0] = g_w0[t]; g_rows_of_token[2 * t] = r0;
    int e1 = g_e1[t];
    int r1 = g_offset[e1] + atomicAdd(&g_cursor[e1], 1);
    g_token_of_row[r1] = t; g_w_of_row[r1] = g_w1[t]; g_rows_of_token[2 * t + 1] = r1;
}

__global__ void gather_kernel(const float* __restrict__ x) {
    int row = blockIdx.x;
    int t = g_token_of_row[row];
    const float4* src = (const float4*)(x + (size_t)t * H_DIM);
    __nv_bfloat16* dh = g_xh + (size_t)row * H_DIM;
    __nv_bfloat16* dl = g_xl + (size_t)row * H_DIM;
    for (int i = threadIdx.x; i < H_DIM / 4; i += 128) {
        float4 v = src[i];
        __nv_bfloat16 h0 = __float2bfloat16(v.x);
        __nv_bfloat16 h1 = __float2bfloat16(v.y);
        __nv_bfloat16 h2 = __float2bfloat16(v.z);
        __nv_bfloat16 h3 = __float2bfloat16(v.w);
        __nv_bfloat16 l0 = __float2bfloat16(v.x - __bfloat162float(h0));
        __nv_bfloat16 l1 = __float2bfloat16(v.y - __bfloat162float(h1));
        __nv_bfloat16 l2 = __float2bfloat16(v.z - __bfloat162float(h2));
        __nv_bfloat16 l3 = __float2bfloat16(v.w - __bfloat162float(h3));
        __nv_bfloat162* ph = (__nv_bfloat162*)(dh + i * 4);
        __nv_bfloat162* pl = (__nv_bfloat162*)(dl + i * 4);
        ph[0] = __nv_bfloat162(h0, h1); ph[1] = __nv_bfloat162(h2, h3);
        pl[0] = __nv_bfloat162(l0, l1); pl[1] = __nv_bfloat162(l2, l3);
    }
}

// streaming hi/lo split helpers
__device__ __forceinline__ void split4(float4 v, uint2& uh, uint2& ul) {
    __nv_bfloat16 h0 = __float2bfloat16(v.x);
    __nv_bfloat16 h1 = __float2bfloat16(v.y);
    __nv_bfloat16 h2 = __float2bfloat16(v.z);
    __nv_bfloat16 h3 = __float2bfloat16(v.w);
    __nv_bfloat162 ph0(h0, h1), ph1(h2, h3);
    __nv_bfloat162 pl0(__float2bfloat16(v.x - __bfloat162float(h0)),
                       __float2bfloat16(v.y - __bfloat162float(h1)));
    __nv_bfloat162 pl1(__float2bfloat16(v.z - __bfloat162float(h2)),
                       __float2bfloat16(v.w - __bfloat162float(h3)));
    uh.x = *(uint32_t*)&ph0; uh.y = *(uint32_t*)&ph1;
    ul.x = *(uint32_t*)&pl0; ul.y = *(uint32_t*)&pl1;
}

// gate+up weight split (stream s1; feeds gateup GEMM)
__global__ void split_w_gu(const float4* __restrict__ w0, const float4* __restrict__ w1, int n4) {
    int z = blockIdx.z;
    const float4* src = (z == 0) ? w0 : w1;
    uint2* dh = (z == 0) ? (uint2*)g_wgh : (uint2*)g_wuh;
    uint2* dl = (z == 0) ? (uint2*)g_wgl : (uint2*)g_wul;
    int i = blockIdx.x * blockDim.x + threadIdx.x;
    int stride = gridDim.x * blockDim.x;
    for (; i < n4; i += stride) {
        uint2 uh, ul;
        split4(src[i], uh, ul);
        dh[i] = uh; dl[i] = ul;
    }
}

// down weight split (stream s2; feeds down GEMM — overlaps with gateup)
__global__ void split_w_d(const float4* __restrict__ w2, int n4) {
    int i = blockIdx.x * blockDim.x + threadIdx.x;
    int stride = gridDim.x * blockDim.x;
    uint2* dh = (uint2*)g_wdh;
    uint2* dl = (uint2*)g_wdl;
    for (; i < n4; i += stride) {
        uint2 uh, ul;
        split4(w2[i], uh, ul);
        dh[i] = uh; dl[i] = ul;
    }
}

// ============================================================================
// bf16x3 grouped GEMMs on mma.sync. Flattened tile-map grid.
// A tiles: 128B rows, swizzle: chunk c of row r at r*128+((c^(r&7))<<4)
// B tiles: 256B rows, swizzle: chunk c of row r at r*256+((c^(r&7))<<4)
// B consumed with ldmatrix.x4.trans (weights in native [K][N] layout).
// ============================================================================
#define STAGE_F  98304   // gateup BK=64: Ah,Al (16K) + Gh,Gl,Uh,Ul (16K); 2 stages, occ 1
#define STAGE_D  49152   // down  BK=32: Ah,Al (16K, half-filled rows) + Bh,Bl (8K); 2 stages, occ 2
#define SMEM_F   (2 * STAGE_F)
#define SMEM_D   (2 * STAGE_D)

__device__ __forceinline__ void load_A(uint32_t sb, int tid, const __nv_bfloat16* src,
                                       size_t rstride, int k0, int valid) {
    #pragma unroll
    for (int j = 0; j < 4; j++) {
        int u = tid + j * 256;              // 0..1023
        int r = u >> 3, c = u & 7;
        uint32_t off = (uint32_t)(r * 128 + ((c ^ (r & 7)) << 4));
        cp16(sb + off, src + (size_t)r * rstride + k0 + c * 8, (r < valid) ? 16u : 0u);
    }
}
// BK=32 A loader: 128B rows, only chunks 0..3 live (k 0..31)
__device__ __forceinline__ void load_A32(uint32_t sb, int tid, const __nv_bfloat16* src,
                                         size_t rstride, int k0, int valid) {
    #pragma unroll
    for (int j = 0; j < 2; j++) {
        int u = tid + j * 256;              // 0..511
        int r = u >> 2, c = u & 3;
        uint32_t off = (uint32_t)(r * 128 + ((c ^ (r & 7)) << 4));
        cp16(sb + off, src + (size_t)r * rstride + k0 + c * 8, (r < valid) ? 16u : 0u);
    }
}
__device__ __forceinline__ void load_B(uint32_t sb, int tid, const __nv_bfloat16* src,
                                       size_t N, int k0) {
    #pragma unroll
    for (int j = 0; j < 4; j++) {
        int u = tid + j * 256;
        int r = u >> 4, c = u & 15;         // r: 0..63 (k), c: 16B n-chunk
        uint32_t off = (uint32_t)(r * 256 + ((c ^ (r & 7)) << 4));
        cp16(sb + off, src + (size_t)(k0 + r) * N + c * 8, 16u);
    }
}
// BK=32 B loader: 32 k-rows
__device__ __forceinline__ void load_B32(uint32_t sb, int tid, const __nv_bfloat16* src,
                                         size_t N, int k0) {
    #pragma unroll
    for (int j = 0; j < 2; j++) {
        int u = tid + j * 256;              // 0..511
        int r = u >> 4, c = u & 15;         // r: 0..31
        uint32_t off = (uint32_t)(r * 256 + ((c ^ (r & 7)) << 4));
        cp16(sb + off, src + (size_t)(k0 + r) * N + c * 8, 16u);
    }
}

// load hi+lo B fragments for 4 n8-tiles via 4 x ldmatrix.x4.trans
__device__ __forceinline__ void load_bfrags(uint32_t sb, uint32_t boff, uint32_t lo_delta,
                                            int wn, uint32_t broff, uint32_t bxor,
                                            int lane, uint32_t bh[4][2], uint32_t bl[4][2]) {
    #pragma unroll
    for (int ntp = 0; ntp < 2; ntp++) {
        uint32_t ch = (uint32_t)(wn * 4 + ntp * 2 + (lane >> 4)) ^ bxor;
        uint32_t ad = sb + boff + broff + (ch << 4);
        uint32_t r4[4];
        ldm_x4t(ad, r4);
        bh[2 * ntp][0] = r4[0]; bh[2 * ntp][1] = r4[1];
        bh[2 * ntp + 1][0] = r4[2]; bh[2 * ntp + 1][1] = r4[3];
        ldm_x4t(ad + lo_delta, r4);
        bl[2 * ntp][0] = r4[0]; bl[2 * ntp][1] = r4[1];
        bl[2 * ntp + 1][0] = r4[2]; bl[2 * ntp + 1][1] = r4[3];
    }
}

// ---------------- fused gate+up: h = up(x) * silu(gate(x)) -> bf16 hi/lo ----------------
__global__ __launch_bounds__(256, 1) void moe_gateup_kernel() {
    constexpr int KD = H_DIM, NCH = KD / 64;

    const int tile = blockIdx.y;
    if (tile >= g_ntiles) return;
    const int e    = g_tile_e[tile];
    const int bm   = g_tile_bm[tile];
    const int m0   = g_offset[e];
    const int rows = g_offset[e + 1] - m0;
    const int bn   = blockIdx.x * 128;
    const int va   = min(rows - bm, 128);

    extern __shared__ char smem[];
    const uint32_t sbase = smem_u32(smem);
    const int tid = threadIdx.x;
    const int lane = tid & 31, wid = tid >> 5;
    const int wm = wid >> 2, wn = wid & 3;

    const __nv_bfloat16* Ah = g_xh + (size_t)(m0 + bm) * KD;
    const __nv_bfloat16* Al = g_xl + (size_t)(m0 + bm) * KD;
    const __nv_bfloat16* Gh = g_wgh + (size_t)e * KD * I_DIM + bn;
    const __nv_bfloat16* Gl = g_wgl + (size_t)e * KD * I_DIM + bn;
    const __nv_bfloat16* Uh = g_wuh + (size_t)e * KD * I_DIM + bn;
    const __nv_bfloat16* Ul = g_wul + (size_t)e * KD * I_DIM + bn;

    float accg[4][4][4], accu[4][4][4];
    #pragma unroll
    for (int i = 0; i < 4; i++)
        #pragma unroll
        for (int j = 0; j < 4; j++)
            #pragma unroll
            for (int k = 0; k < 4; k++) { accg[i][j][k] = 0.f; accu[i][j][k] = 0.f; }

    auto issue = [&](int c) {
        uint32_t sb = sbase + (uint32_t)(c & 1) * STAGE_F;
        int k0 = c * 64;
        load_A(sb,         tid, Ah, KD, k0, va);
        load_A(sb + 16384, tid, Al, KD, k0, va);
        load_B(sb + 32768, tid, Gh, I_DIM, k0);
        load_B(sb + 49152, tid, Gl, I_DIM, k0);
        load_B(sb + 65536, tid, Uh, I_DIM, k0);
        load_B(sb + 81920, tid, Ul, I_DIM, k0);
        asm volatile("cp.async.commit_group;");
    };

    issue(0);

    for (int c = 0; c < NCH; c++) {
        asm volatile("cp.async.wait_group 0;");
        __syncthreads();
        if (c + 1 < NCH) issue(c + 1);

        const uint32_t sb = sbase + (uint32_t)(c & 1) * STAGE_F;
        #pragma unroll
        for (int s16 = 0; s16 < 4; s16++) {
            // A fragments (hi, lo)
            uint32_t af[2][4][4];
            #pragma unroll
            for (int mt = 0; mt < 4; mt++) {
                int row = wm * 64 + mt * 16 + (lane & 15);
                uint32_t ch = (uint32_t)(2 * s16 + (lane >> 4)) ^ (uint32_t)(row & 7);
                uint32_t ad = sb + (uint32_t)(row * 128) + (ch << 4);
                ldm_x4(ad,         af[0][mt]);
                ldm_x4(ad + 16384, af[1][mt]);
            }
            const int rowb = s16 * 16 + (lane & 15);
            const uint32_t broff = (uint32_t)(rowb * 256);
            const uint32_t bxor  = (uint32_t)(rowb & 7);

            uint32_t bh[4][2], bl[4][2];
            // ---- gate ----
            load_bfrags(sb, 32768, 16384, wn, broff, bxor, lane, bh, bl);
            #pragma unroll
            for (int mt = 0; mt < 4; mt++)
                #pragma unroll
                for (int nt = 0; nt < 4; nt++) mma_bf16(accg[mt][nt], af[0][mt], bh[nt]);
            #pragma unroll
            for (int mt = 0; mt < 4; mt++)
                #pragma unroll
                for (int nt = 0; nt < 4; nt++) mma_bf16(accg[mt][nt], af[0][mt], bl[nt]);
            #pragma unroll
            for (int mt = 0; mt < 4; mt++)
                #pragma unroll
                for (int nt = 0; nt < 4; nt++) mma_bf16(accg[mt][nt], af[1][mt], bh[nt]);
            // ---- up ----
            load_bfrags(sb, 65536, 16384, wn, broff, bxor, lane, bh, bl);
            #pragma unroll
            for (int mt = 0; mt < 4; mt++)
                #pragma unroll
                for (int nt = 0; nt < 4; nt++) mma_bf16(accu[mt][nt], af[0][mt], bh[nt]);
            #pragma unroll
            for (int mt = 0; mt < 4; mt++)
                #pragma unroll
                for (int nt = 0; nt < 4; nt++) mma_bf16(accu[mt][nt], af[0][mt], bl[nt]);
            #pragma unroll
            for (int mt = 0; mt < 4; mt++)
                #pragma unroll
                for (int nt = 0; nt < 4; nt++) mma_bf16(accu[mt][nt], af[1][mt], bh[nt]);
        }
    }

    // epilogue: h = u*silu(g) in registers -> bf16 hi/lo
    const int lr = lane >> 2;
    const int lc = (lane & 3) * 2;
    #pragma unroll
    for (int mt = 0; mt < 4; mt++) {
        #pragma unroll
        for (int h2 = 0; h2 < 2; h2++) {
            int r = wm * 64 + mt * 16 + lr + h2 * 8;
            if (r < va) {
                size_t grow = (size_t)(m0 + bm + r);
                #pragma unroll
                for (int nt = 0; nt < 4; nt++) {
                    int col = wn * 32 + nt * 8 + lc;
                    float g0 = accg[mt][nt][h2 * 2], g1 = accg[mt][nt][h2 * 2 + 1];
                    float u0 = accu[mt][nt][h2 * 2], u1 = accu[mt][nt][h2 * 2 + 1];
                    float hv0 = u0 * g0 * __frcp_rn(1.f + __expf(-g0));
                    float hv1 = u1 * g1 * __frcp_rn(1.f + __expf(-g1));
                    __nv_bfloat16 hh0 = __float2bfloat16(hv0);
                    __nv_bfloat16 hh1 = __float2bfloat16(hv1);
                    __nv_bfloat16 hl0 = __float2bfloat16(hv0 - __bfloat162float(hh0));
                    __nv_bfloat16 hl1 = __float2bfloat16(hv1 - __bfloat162float(hh1));
                    *(__nv_bfloat162*)(g_hh + grow * I_DIM + bn + col) = __nv_bfloat162(hh0, hh1);
                    *(__nv_bfloat162*)(g_hl + grow * I_DIM + bn + col) = __nv_bfloat162(hl0, hl1);
                }
            }
        }
    }
}

// ---------------- down-proj: y = (h @ wd) * routing_weight  [BK=32, occ 2] ----------------
__global__ __launch_bounds__(256, 2) void moe_down_kernel() {
    constexpr int KD = I_DIM, ND = H_DIM, NCH = KD / 32;

    const int tile = blockIdx.y;
    if (tile >= g_ntiles) return;
    const int e    = g_tile_e[tile];
    const int bm   = g_tile_bm[tile];
    const int m0   = g_offset[e];
    const int rows = g_offset[e + 1] - m0;
    const int bn   = blockIdx.x * 128;
    const int va   = min(rows - bm, 128);

    extern __shared__ char smem[];
    const uint32_t sbase = smem_u32(smem);
    const int tid = threadIdx.x;
    const int lane = tid & 31, wid = tid >> 5;
    const int wm = wid >> 2, wn = wid & 3;

    const __nv_bfloat16* Ah = g_hh + (size_t)(m0 + bm) * KD;
    const __nv_bfloat16* Al = g_hl + (size_t)(m0 + bm) * KD;
    const __nv_bfloat16* Bh = g_wdh + (size_t)e * KD * ND + bn;
    const __nv_bfloat16* Bl = g_wdl + (size_t)e * KD * ND + bn;

    float acc[4][4][4];
    #pragma unroll
    for (int i = 0; i < 4; i++)
        #pragma unroll
        for (int j = 0; j < 4; j++)
            #pragma unroll
            for (int k = 0; k < 4; k++) acc[i][j][k] = 0.f;

    auto issue = [&](int c) {
        uint32_t sb = sbase + (uint32_t)(c & 1) * STAGE_D;
        int k0 = c * 32;
        load_A32(sb,         tid, Ah, KD, k0, va);
        load_A32(sb + 16384, tid, Al, KD, k0, va);
        load_B32(sb + 32768, tid, Bh, ND, k0);
        load_B32(sb + 40960, tid, Bl, ND, k0);
        asm volatile("cp.async.commit_group;");
    };

    issue(0);

    for (int c = 0; c < NCH; c++) {
        asm volatile("cp.async.wait_group 0;");
        __syncthreads();
        if (c + 1 < NCH) issue(c + 1);

        const uint32_t sb = sbase + (uint32_t)(c & 1) * STAGE_D;
        #pragma unroll
        for (int s16 = 0; s16 < 2; s16++) {
            // single A-frag buffer, reused hi -> lo (register diet for occ 2)
            uint32_t af[4][4];
            #pragma unroll
            for (int mt = 0; mt < 4; mt++) {
                int row = wm * 64 + mt * 16 + (lane & 15);
                uint32_t ch = (uint32_t)(2 * s16 + (lane >> 4)) ^ (uint32_t)(row & 7);
                ldm_x4(sb + (uint32_t)(row * 128) + (ch << 4), af[mt]);
            }
            const int rowb = s16 * 16 + (lane & 15);
            const uint32_t broff = (uint32_t)(rowb * 256);
            const uint32_t bxor  = (uint32_t)(rowb & 7);

            uint32_t bh[4][2], bl[4][2];
            load_bfrags(sb, 32768, 8192, wn, broff, bxor, lane, bh, bl);
            #pragma unroll
            for (int mt = 0; mt < 4; mt++)
                #pragma unroll
                for (int nt = 0; nt < 4; nt++) mma_bf16(acc[mt][nt], af[mt], bh[nt]);
            #pragma unroll
            for (int mt = 0; mt < 4; mt++)
                #pragma unroll
                for (int nt = 0; nt < 4; nt++) mma_bf16(acc[mt][nt], af[mt], bl[nt]);
            // overwrite A-frags with lo
            #pragma unroll
            for (int mt = 0; mt < 4; mt++) {
                int row = wm * 64 + mt * 16 + (lane & 15);
                uint32_t ch = (uint32_t)(2 * s16 + (lane >> 4)) ^ (uint32_t)(row & 7);
                ldm_x4(sb + 16384 + (uint32_t)(row * 128) + (ch << 4), af[mt]);
            }
            #pragma unroll
            for (int mt = 0; mt < 4; mt++)
                #pragma unroll
                for (int nt = 0; nt < 4; nt++) mma_bf16(acc[mt][nt], af[mt], bh[nt]);
        }
    }

    const int lr = lane >> 2;
    const int lc = (lane & 3) * 2;
    #pragma unroll
    for (int mt = 0; mt < 4; mt++) {
        #pragma unroll
        for (int h2 = 0; h2 < 2; h2++) {
            int r = wm * 64 + mt * 16 + lr + h2 * 8;
            if (r < va) {
                size_t grow = (size_t)(m0 + bm + r);
                float scale = g_w_of_row[grow];
                float* C = g_y + grow * ND + bn;
                #pragma unroll
                for (int nt = 0; nt < 4; nt++) {
                    int col = wn * 32 + nt * 8 + lc;
                    *(float2*)(C + col) = make_float2(acc[mt][nt][h2 * 2] * scale,
                                                      acc[mt][nt][h2 * 2 + 1] * scale);
                }
            }
        }
    }
}

// ---------------- combine ----------------
__global__ void combine_kernel(float* __restrict__ out) {
    int t  = blockIdx.x;
    int r0 = g_rows_of_token[2 * t];
    int r1 = g_rows_of_token[2 * t + 1];
    const float4* y0 = (const float4*)(g_y + (size_t)r0 * H_DIM);
    const float4* y1 = (const float4*)(g_y + (size_t)r1 * H_DIM);
    float4* o = (float4*)(out + (size_t)t * H_DIM);
    for (int i = threadIdx.x; i < H_DIM / 4; i += blockDim.x) {
        float4 a = y0[i], b = y1[i];
        o[i] = make_float4(a.x + b.x, a.y + b.y, a.z + b.z, a.w + b.w);
    }
}

// ---------------- launch ----------------
extern "C" void kernel_launch(void* const* d_in, const int* in_sizes, int n_in,
                              void* d_out, int out_size) {
    const float* x   = (const float*)d_in[0];
    const float* wg  = (const float*)d_in[1];
    const float* wgp = (const float*)d_in[2];
    const float* wup = (const float*)d_in[3];
    const float* wdp = (const float*)d_in[4];
    float* out = (float*)d_out;

    // lazy host-side stream/event setup (no device allocations; created on the
    // uncaptured correctness call, reused identically on every call thereafter)
    static cudaStream_t s1 = nullptr, s2 = nullptr;
    static cudaEvent_t  ev0 = nullptr, ev1 = nullptr, ev2 = nullptr;
    if (s1 == nullptr) {
        cudaStreamCreateWithFlags(&s1, cudaStreamNonBlocking);
        cudaStreamCreateWithFlags(&s2, cudaStreamNonBlocking);
        cudaEventCreateWithFlags(&ev0, cudaEventDisableTiming);
        cudaEventCreateWithFlags(&ev1, cudaEventDisableTiming);
        cudaEventCreateWithFlags(&ev2, cudaEventDisableTiming);
    }

    cudaFuncSetAttribute(moe_gateup_kernel, cudaFuncAttributeMaxDynamicSharedMemorySize, SMEM_F);
    cudaFuncSetAttribute(moe_down_kernel,   cudaFuncAttributeMaxDynamicSharedMemorySize, SMEM_D);

    const int n4 = N_EXP * H_DIM * I_DIM / 4;

    // fork: weight splits run concurrently with the routing chain
    cudaEventRecord(ev0, 0);
    cudaStreamWaitEvent(s1, ev0, 0);
    split_w_gu<<<dim3(2048, 1, 2), 256, 0, s1>>>((const float4*)wgp, (const float4*)wup, n4);
    cudaEventRecord(ev1, s1);
    cudaStreamWaitEvent(s2, ev0, 0);
    split_w_d<<<2048, 256, 0, s2>>>((const float4*)wdp, n4);
    cudaEventRecord(ev2, s2);

    // routing chain on the main stream
    zero_kernel<<<1, 32>>>();
    router_kernel<<<T_TOK / 8, 256>>>(x, wg);
    scan_kernel<<<1, 1>>>();
    assign_kernel<<<T_TOK / 256, 256>>>();
    gather_kernel<<<NROWS, 128>>>(x);

    // join gate/up weights before gateup GEMM
    cudaStreamWaitEvent(0, ev1, 0);
    moe_gateup_kernel<<<dim3(I_DIM / 128, 272), 256, SMEM_F>>>();

    // join down weights before down GEMM (overlapped with gateup above)
    cudaStreamWaitEvent(0, ev2, 0);
    moe_down_kernel<<<dim3(H_DIM / 128, 272), 256, SMEM_D>>>();

    combine_kernel<<<T_TOK, 256>>>(out);
}

// round 16
// speedup vs baseline: 3.3172x; 1.0234x over previous
#include <cuda_runtime.h>
#include <cuda_bf16.h>
#include <cstdint>

#define T_TOK 16384
#define H_DIM 1024
#define I_DIM 2048
#define N_EXP 16
#define NROWS (T_TOK * 2)
#define MAXTILES 288

// ---------------- routing scratch ----------------
__device__ int   g_count[N_EXP];
__device__ int   g_cursor[N_EXP];
__device__ int   g_offset[N_EXP + 1];
__device__ int   g_ntiles;
__device__ int   g_tile_e[MAXTILES];
__device__ int   g_tile_bm[MAXTILES];
__device__ int   g_e0[T_TOK];
__device__ int   g_e1[T_TOK];
__device__ float g_w0[T_TOK];
__device__ float g_w1[T_TOK];
__device__ int   g_token_of_row[NROWS];
__device__ float g_w_of_row[NROWS];
__device__ int   g_rows_of_token[NROWS];

// ---------------- data buffers ----------------
// weights kept in NATIVE [E][K][N] layout, split hi/lo (no transpose)
__device__ __nv_bfloat16 g_xh[(size_t)NROWS * H_DIM];
__device__ __nv_bfloat16 g_xl[(size_t)NROWS * H_DIM];
__device__ __nv_bfloat16 g_wgh[(size_t)N_EXP * H_DIM * I_DIM];
__device__ __nv_bfloat16 g_wgl[(size_t)N_EXP * H_DIM * I_DIM];
__device__ __nv_bfloat16 g_wuh[(size_t)N_EXP * H_DIM * I_DIM];
__device__ __nv_bfloat16 g_wul[(size_t)N_EXP * H_DIM * I_DIM];
__device__ __nv_bfloat16 g_wdh[(size_t)N_EXP * I_DIM * H_DIM];
__device__ __nv_bfloat16 g_wdl[(size_t)N_EXP * I_DIM * H_DIM];
__device__ __nv_bfloat16 g_hh[(size_t)NROWS * I_DIM];
__device__ __nv_bfloat16 g_hl[(size_t)NROWS * I_DIM];
__device__ float         g_y[(size_t)NROWS * H_DIM];

// ---------------- ptx helpers ----------------
__device__ __forceinline__ uint32_t smem_u32(const void* p) {
    uint32_t a;
    asm("{ .reg .u64 t; cvta.to.shared.u64 t, %1; cvt.u32.u64 %0, t; }" : "=r"(a) : "l"(p));
    return a;
}
__device__ __forceinline__ void cp16(uint32_t dst, const void* src, uint32_t sz) {
    asm volatile("cp.async.cg.shared.global [%0], [%1], 16, %2;"
                 :: "r"(dst), "l"(src), "r"(sz));
}
__device__ __forceinline__ void ldm_x4(uint32_t a, uint32_t r[4]) {
    asm volatile("ldmatrix.sync.aligned.m8n8.x4.shared.b16 {%0,%1,%2,%3}, [%4];"
                 : "=r"(r[0]), "=r"(r[1]), "=r"(r[2]), "=r"(r[3]) : "r"(a));
}
__device__ __forceinline__ void ldm_x4t(uint32_t a, uint32_t r[4]) {
    asm volatile("ldmatrix.sync.aligned.m8n8.x4.trans.shared.b16 {%0,%1,%2,%3}, [%4];"
                 : "=r"(r[0]), "=r"(r[1]), "=r"(r[2]), "=r"(r[3]) : "r"(a));
}
__device__ __forceinline__ void mma_bf16(float* c, const uint32_t* a, const uint32_t* b) {
    asm volatile(
        "mma.sync.aligned.m16n8k16.row.col.f32.bf16.bf16.f32 "
        "{%0,%1,%2,%3}, {%4,%5,%6,%7}, {%8,%9}, {%0,%1,%2,%3};"
        : "+f"(c[0]), "+f"(c[1]), "+f"(c[2]), "+f"(c[3])
        : "r"(a[0]), "r"(a[1]), "r"(a[2]), "r"(a[3]), "r"(b[0]), "r"(b[1]));
}

// ---------------- small kernels (routing path) ----------------
__global__ void zero_kernel() {
    int i = threadIdx.x;
    if (i < N_EXP) { g_count[i] = 0; g_cursor[i] = 0; }
}

// router v2: lane = (k-octant kk, expert-quad eq); float4 loads, 16 FMA/step;
// butterfly over kk, shuffle-gather quads, per-lane top-2 (strict > = lowest-index ties)
__global__ void router_kernel(const float* __restrict__ x, const float* __restrict__ wg) {
    int warp = (blockIdx.x * blockDim.x + threadIdx.x) >> 5;
    int lane = threadIdx.x & 31;
    if (warp >= T_TOK) return;
    const int t  = warp;
    const int kk = lane >> 2;      // 0..7
    const int eq = lane & 3;       // 0..3  (experts eq*4 .. eq*4+3)

    const float4* xr = (const float4*)(x + (size_t)t * H_DIM);
    float4 acc = make_float4(0.f, 0.f, 0.f, 0.f);

    #pragma unroll 4
    for (int j = 0; j < 32; j++) {
        int k4 = j * 32 + kk * 4;
        float4 xv = xr[k4 >> 2];
        const float4* wp = (const float4*)(wg + (size_t)k4 * N_EXP + eq * 4);
        float4 w0 = wp[0];          // wg[k4+0][eq*4..+3]
        float4 w1 = wp[4];          // wg[k4+1][...]   (stride 16 floats = 4 float4)
        float4 w2 = wp[8];
        float4 w3 = wp[12];
        acc.x += xv.x * w0.x + xv.y * w1.x + xv.z * w2.x + xv.w * w3.x;
        acc.y += xv.x * w0.y + xv.y * w1.y + xv.z * w2.y + xv.w * w3.y;
        acc.z += xv.x * w0.z + xv.y * w1.z + xv.z * w2.z + xv.w * w3.z;
        acc.w += xv.x * w0.w + xv.y * w1.w + xv.z * w2.w + xv.w * w3.w;
    }

    // reduce over kk (lanes with same eq, xor 4/8/16)
    #pragma unroll
    for (int s = 4; s < 32; s <<= 1) {
        acc.x += __shfl_xor_sync(0xffffffffu, acc.x, s);
        acc.y += __shfl_xor_sync(0xffffffffu, acc.y, s);
        acc.z += __shfl_xor_sync(0xffffffffu, acc.z, s);
        acc.w += __shfl_xor_sync(0xffffffffu, acc.w, s);
    }

    // gather all 16 logits to every lane (quad q lives on lane q)
    float lg[16];
    #pragma unroll
    for (int q = 0; q < 4; q++) {
        lg[q * 4 + 0] = __shfl_sync(0xffffffffu, acc.x, q);
        lg[q * 4 + 1] = __shfl_sync(0xffffffffu, acc.y, q);
        lg[q * 4 + 2] = __shfl_sync(0xffffffffu, acc.z, q);
        lg[q * 4 + 3] = __shfl_sync(0xffffffffu, acc.w, q);
    }

    if (lane == 0) {
        float l1 = -1e30f; int i1 = 0;
        #pragma unroll
        for (int e = 0; e < N_EXP; e++)
            if (lg[e] > l1) { l1 = lg[e]; i1 = e; }
        float l2 = -1e30f; int i2 = 0;
        #pragma unroll
        for (int e = 0; e < N_EXP; e++)
            if (e != i1 && lg[e] > l2) { l2 = lg[e]; i2 = e; }

        float r  = __expf(l2 - l1);
        float w0 = 1.f / (1.f + r);
        g_e0[t] = i1; g_e1[t] = i2;
        g_w0[t] = w0; g_w1[t] = 1.f - w0;
        atomicAdd(&g_count[i1], 1);
        atomicAdd(&g_count[i2], 1);
    }
}

// scan + build exact tile map (<= 272 live m-tiles)
__global__ void scan_kernel() {
    if (threadIdx.x == 0) {
        int o = 0, tt = 0;
        for (int e = 0; e < N_EXP; e++) {
            g_offset[e] = o;
            int cnt = g_count[e];
            for (int bm = 0; bm < cnt; bm += 128) {
                g_tile_e[tt] = e; g_tile_bm[tt] = bm; tt++;
            }
            o += cnt;
        }
        g_offset[N_EXP] = o;
        g_ntiles = tt;
    }
}

__global__ void assign_kernel() {
    int t = blockIdx.x * blockDim.x + threadIdx.x;
    if (t >= T_TOK) return;
    int e0 = g_e0[t];
    int r0 = g_offset[e0] + atomicAdd(&g_cursor[e0], 1);
    g_token_of_row[r0] = t; g_w_of_row[r0] = g_w0[t]; g_rows_of_token[2 * t] = r0;
    int e1 = g_e1[t];
    int r1 = g_offset[e1] + atomicAdd(&g_cursor[e1], 1);
    g_token_of_row[r1] = t; g_w_of_row[r1] = g_w1[t]; g_rows_of_token[2 * t + 1] = r1;
}

__global__ void gather_kernel(const float* __restrict__ x) {
    int row = blockIdx.x;
    int t = g_token_of_row[row];
    const float4* src = (const float4*)(x + (size_t)t * H_DIM);
    __nv_bfloat16* dh = g_xh + (size_t)row * H_DIM;
    __nv_bfloat16* dl = g_xl + (size_t)row * H_DIM;
    for (int i = threadIdx.x; i < H_DIM / 4; i += 128) {
        float4 v = src[i];
        __nv_bfloat16 h0 = __float2bfloat16(v.x);
        __nv_bfloat16 h1 = __float2bfloat16(v.y);
        __nv_bfloat16 h2 = __float2bfloat16(v.z);
        __nv_bfloat16 h3 = __float2bfloat16(v.w);
        __nv_bfloat16 l0 = __float2bfloat16(v.x - __bfloat162float(h0));
        __nv_bfloat16 l1 = __float2bfloat16(v.y - __bfloat162float(h1));
        __nv_bfloat16 l2 = __float2bfloat16(v.z - __bfloat162float(h2));
        __nv_bfloat16 l3 = __float2bfloat16(v.w - __bfloat162float(h3));
        __nv_bfloat162* ph = (__nv_bfloat162*)(dh + i * 4);
        __nv_bfloat162* pl = (__nv_bfloat162*)(dl + i * 4);
        ph[0] = __nv_bfloat162(h0, h1); ph[1] = __nv_bfloat162(h2, h3);
        pl[0] = __nv_bfloat162(l0, l1); pl[1] = __nv_bfloat162(l2, l3);
    }
}

// streaming hi/lo split helpers
__device__ __forceinline__ void split4(float4 v, uint2& uh, uint2& ul) {
    __nv_bfloat16 h0 = __float2bfloat16(v.x);
    __nv_bfloat16 h1 = __float2bfloat16(v.y);
    __nv_bfloat16 h2 = __float2bfloat16(v.z);
    __nv_bfloat16 h3 = __float2bfloat16(v.w);
    __nv_bfloat162 ph0(h0, h1), ph1(h2, h3);
    __nv_bfloat162 pl0(__float2bfloat16(v.x - __bfloat162float(h0)),
                       __float2bfloat16(v.y - __bfloat162float(h1)));
    __nv_bfloat162 pl1(__float2bfloat16(v.z - __bfloat162float(h2)),
                       __float2bfloat16(v.w - __bfloat162float(h3)));
    uh.x = *(uint32_t*)&ph0; uh.y = *(uint32_t*)&ph1;
    ul.x = *(uint32_t*)&pl0; ul.y = *(uint32_t*)&pl1;
}

// gate+up weight split (stream s1; feeds gateup GEMM)
__global__ void split_w_gu(const float4* __restrict__ w0, const float4* __restrict__ w1, int n4) {
    int z = blockIdx.z;
    const float4* src = (z == 0) ? w0 : w1;
    uint2* dh = (z == 0) ? (uint2*)g_wgh : (uint2*)g_wuh;
    uint2* dl = (z == 0) ? (uint2*)g_wgl : (uint2*)g_wul;
    int i = blockIdx.x * blockDim.x + threadIdx.x;
    int stride = gridDim.x * blockDim.x;
    for (; i < n4; i += stride) {
        uint2 uh, ul;
        split4(src[i], uh, ul);
        dh[i] = uh; dl[i] = ul;
    }
}

// down weight split (stream s2; feeds down GEMM — overlaps with gateup)
__global__ void split_w_d(const float4* __restrict__ w2, int n4) {
    int i = blockIdx.x * blockDim.x + threadIdx.x;
    int stride = gridDim.x * blockDim.x;
    uint2* dh = (uint2*)g_wdh;
    uint2* dl = (uint2*)g_wdl;
    for (; i < n4; i += stride) {
        uint2 uh, ul;
        split4(w2[i], uh, ul);
        dh[i] = uh; dl[i] = ul;
    }
}

// ============================================================================
// bf16x3 grouped GEMMs on mma.sync. Flattened tile-map grid.
// A tiles: 128B rows, swizzle: chunk c of row r at r*128+((c^(r&7))<<4)
// B tiles: 256B rows, swizzle: chunk c of row r at r*256+((c^(r&7))<<4)
// B consumed with ldmatrix.x4.trans (weights in native [K][N] layout).
// ============================================================================
#define STAGE_F  98304   // gateup BK=64: Ah,Al (16K) + Gh,Gl,Uh,Ul (16K); 2 stages, occ 1
#define STAGE_D  49152   // down  BK=32: Ah,Al (16K, half-filled rows) + Bh,Bl (8K); 2 stages, occ 2
#define SMEM_F   (2 * STAGE_F)
#define SMEM_D   (2 * STAGE_D)

__device__ __forceinline__ void load_A(uint32_t sb, int tid, const __nv_bfloat16* src,
                                       size_t rstride, int k0, int valid) {
    #pragma unroll
    for (int j = 0; j < 4; j++) {
        int u = tid + j * 256;              // 0..1023
        int r = u >> 3, c = u & 7;
        uint32_t off = (uint32_t)(r * 128 + ((c ^ (r & 7)) << 4));
        cp16(sb + off, src + (size_t)r * rstride + k0 + c * 8, (r < valid) ? 16u : 0u);
    }
}
// BK=32 A loader: 128B rows, only chunks 0..3 live (k 0..31)
__device__ __forceinline__ void load_A32(uint32_t sb, int tid, const __nv_bfloat16* src,
                                         size_t rstride, int k0, int valid) {
    #pragma unroll
    for (int j = 0; j < 2; j++) {
        int u = tid + j * 256;              // 0..511
        int r = u >> 2, c = u & 3;
        uint32_t off = (uint32_t)(r * 128 + ((c ^ (r & 7)) << 4));
        cp16(sb + off, src + (size_t)r * rstride + k0 + c * 8, (r < valid) ? 16u : 0u);
    }
}
__device__ __forceinline__ void load_B(uint32_t sb, int tid, const __nv_bfloat16* src,
                                       size_t N, int k0) {
    #pragma unroll
    for (int j = 0; j < 4; j++) {
        int u = tid + j * 256;
        int r = u >> 4, c = u & 15;         // r: 0..63 (k), c: 16B n-chunk
        uint32_t off = (uint32_t)(r * 256 + ((c ^ (r & 7)) << 4));
        cp16(sb + off, src + (size_t)(k0 + r) * N + c * 8, 16u);
    }
}
// BK=32 B loader: 32 k-rows
__device__ __forceinline__ void load_B32(uint32_t sb, int tid, const __nv_bfloat16* src,
                                         size_t N, int k0) {
    #pragma unroll
    for (int j = 0; j < 2; j++) {
        int u = tid + j * 256;              // 0..511
        int r = u >> 4, c = u & 15;         // r: 0..31
        uint32_t off = (uint32_t)(r * 256 + ((c ^ (r & 7)) << 4));
        cp16(sb + off, src + (size_t)(k0 + r) * N + c * 8, 16u);
    }
}

// load hi+lo B fragments for 4 n8-tiles via 4 x ldmatrix.x4.trans
__device__ __forceinline__ void load_bfrags(uint32_t sb, uint32_t boff, uint32_t lo_delta,
                                            int wn, uint32_t broff, uint32_t bxor,
                                            int lane, uint32_t bh[4][2], uint32_t bl[4][2]) {
    #pragma unroll
    for (int ntp = 0; ntp < 2; ntp++) {
        uint32_t ch = (uint32_t)(wn * 4 + ntp * 2 + (lane >> 4)) ^ bxor;
        uint32_t ad = sb + boff + broff + (ch << 4);
        uint32_t r4[4];
        ldm_x4t(ad, r4);
        bh[2 * ntp][0] = r4[0]; bh[2 * ntp][1] = r4[1];
        bh[2 * ntp + 1][0] = r4[2]; bh[2 * ntp + 1][1] = r4[3];
        ldm_x4t(ad + lo_delta, r4);
        bl[2 * ntp][0] = r4[0]; bl[2 * ntp][1] = r4[1];
        bl[2 * ntp + 1][0] = r4[2]; bl[2 * ntp + 1][1] = r4[3];
    }
}

// ---------------- fused gate+up: h = up(x) * silu(gate(x)) -> bf16 hi/lo ----------------
__global__ __launch_bounds__(256, 1) void moe_gateup_kernel() {
    constexpr int KD = H_DIM, NCH = KD / 64;

    const int tile = blockIdx.y;
    if (tile >= g_ntiles) return;
    const int e    = g_tile_e[tile];
    const int bm   = g_tile_bm[tile];
    const int m0   = g_offset[e];
    const int rows = g_offset[e + 1] - m0;
    const int bn   = blockIdx.x * 128;
    const int va   = min(rows - bm, 128);

    extern __shared__ char smem[];
    const uint32_t sbase = smem_u32(smem);
    const int tid = threadIdx.x;
    const int lane = tid & 31, wid = tid >> 5;
    const int wm = wid >> 2, wn = wid & 3;

    const __nv_bfloat16* Ah = g_xh + (size_t)(m0 + bm) * KD;
    const __nv_bfloat16* Al = g_xl + (size_t)(m0 + bm) * KD;
    const __nv_bfloat16* Gh = g_wgh + (size_t)e * KD * I_DIM + bn;
    const __nv_bfloat16* Gl = g_wgl + (size_t)e * KD * I_DIM + bn;
    const __nv_bfloat16* Uh = g_wuh + (size_t)e * KD * I_DIM + bn;
    const __nv_bfloat16* Ul = g_wul + (size_t)e * KD * I_DIM + bn;

    float accg[4][4][4], accu[4][4][4];
    #pragma unroll
    for (int i = 0; i < 4; i++)
        #pragma unroll
        for (int j = 0; j < 4; j++)
            #pragma unroll
            for (int k = 0; k < 4; k++) { accg[i][j][k] = 0.f; accu[i][j][k] = 0.f; }

    auto issue = [&](int c) {
        uint32_t sb = sbase + (uint32_t)(c & 1) * STAGE_F;
        int k0 = c * 64;
        load_A(sb,         tid, Ah, KD, k0, va);
        load_A(sb + 16384, tid, Al, KD, k0, va);
        load_B(sb + 32768, tid, Gh, I_DIM, k0);
        load_B(sb + 49152, tid, Gl, I_DIM, k0);
        load_B(sb + 65536, tid, Uh, I_DIM, k0);
        load_B(sb + 81920, tid, Ul, I_DIM, k0);
        asm volatile("cp.async.commit_group;");
    };

    issue(0);

    for (int c = 0; c < NCH; c++) {
        asm volatile("cp.async.wait_group 0;");
        __syncthreads();
        if (c + 1 < NCH) issue(c + 1);

        const uint32_t sb = sbase + (uint32_t)(c & 1) * STAGE_F;
        #pragma unroll
        for (int s16 = 0; s16 < 4; s16++) {
            // A fragments (hi, lo)
            uint32_t af[2][4][4];
            #pragma unroll
            for (int mt = 0; mt < 4; mt++) {
                int row = wm * 64 + mt * 16 + (lane & 15);
                uint32_t ch = (uint32_t)(2 * s16 + (lane >> 4)) ^ (uint32_t)(row & 7);
                uint32_t ad = sb + (uint32_t)(row * 128) + (ch << 4);
                ldm_x4(ad,         af[0][mt]);
                ldm_x4(ad + 16384, af[1][mt]);
            }
            const int rowb = s16 * 16 + (lane & 15);
            const uint32_t broff = (uint32_t)(rowb * 256);
            const uint32_t bxor  = (uint32_t)(rowb & 7);

            uint32_t bh[4][2], bl[4][2];
            // ---- gate ----
            load_bfrags(sb, 32768, 16384, wn, broff, bxor, lane, bh, bl);
            #pragma unroll
            for (int mt = 0; mt < 4; mt++)
                #pragma unroll
                for (int nt = 0; nt < 4; nt++) mma_bf16(accg[mt][nt], af[0][mt], bh[nt]);
            #pragma unroll
            for (int mt = 0; mt < 4; mt++)
                #pragma unroll
                for (int nt = 0; nt < 4; nt++) mma_bf16(accg[mt][nt], af[0][mt], bl[nt]);
            #pragma unroll
            for (int mt = 0; mt < 4; mt++)
                #pragma unroll
                for (int nt = 0; nt < 4; nt++) mma_bf16(accg[mt][nt], af[1][mt], bh[nt]);
            // ---- up ----
            load_bfrags(sb, 65536, 16384, wn, broff, bxor, lane, bh, bl);
            #pragma unroll
            for (int mt = 0; mt < 4; mt++)
                #pragma unroll
                for (int nt = 0; nt < 4; nt++) mma_bf16(accu[mt][nt], af[0][mt], bh[nt]);
            #pragma unroll
            for (int mt = 0; mt < 4; mt++)
                #pragma unroll
                for (int nt = 0; nt < 4; nt++) mma_bf16(accu[mt][nt], af[0][mt], bl[nt]);
            #pragma unroll
            for (int mt = 0; mt < 4; mt++)
                #pragma unroll
                for (int nt = 0; nt < 4; nt++) mma_bf16(accu[mt][nt], af[1][mt], bh[nt]);
        }
    }

    // epilogue: h = u*silu(g) in registers -> bf16 hi/lo
    const int lr = lane >> 2;
    const int lc = (lane & 3) * 2;
    #pragma unroll
    for (int mt = 0; mt < 4; mt++) {
        #pragma unroll
        for (int h2 = 0; h2 < 2; h2++) {
            int r = wm * 64 + mt * 16 + lr + h2 * 8;
            if (r < va) {
                size_t grow = (size_t)(m0 + bm + r);
                #pragma unroll
                for (int nt = 0; nt < 4; nt++) {
                    int col = wn * 32 + nt * 8 + lc;
                    float g0 = accg[mt][nt][h2 * 2], g1 = accg[mt][nt][h2 * 2 + 1];
                    float u0 = accu[mt][nt][h2 * 2], u1 = accu[mt][nt][h2 * 2 + 1];
                    float hv0 = u0 * g0 * __frcp_rn(1.f + __expf(-g0));
                    float hv1 = u1 * g1 * __frcp_rn(1.f + __expf(-g1));
                    __nv_bfloat16 hh0 = __float2bfloat16(hv0);
                    __nv_bfloat16 hh1 = __float2bfloat16(hv1);
                    __nv_bfloat16 hl0 = __float2bfloat16(hv0 - __bfloat162float(hh0));
                    __nv_bfloat16 hl1 = __float2bfloat16(hv1 - __bfloat162float(hh1));
                    *(__nv_bfloat162*)(g_hh + grow * I_DIM + bn + col) = __nv_bfloat162(hh0, hh1);
                    *(__nv_bfloat162*)(g_hl + grow * I_DIM + bn + col) = __nv_bfloat162(hl0, hl1);
                }
            }
        }
    }
}

// ---------------- down-proj: y = (h @ wd) * routing_weight  [BK=32, occ 2] ----------------
__global__ __launch_bounds__(256, 2) void moe_down_kernel() {
    constexpr int KD = I_DIM, ND = H_DIM, NCH = KD / 32;

    const int tile = blockIdx.y;
    if (tile >= g_ntiles) return;
    const int e    = g_tile_e[tile];
    const int bm   = g_tile_bm[tile];
    const int m0   = g_offset[e];
    const int rows = g_offset[e + 1] - m0;
    const int bn   = blockIdx.x * 128;
    const int va   = min(rows - bm, 128);

    extern __shared__ char smem[];
    const uint32_t sbase = smem_u32(smem);
    const int tid = threadIdx.x;
    const int lane = tid & 31, wid = tid >> 5;
    const int wm = wid >> 2, wn = wid & 3;

    const __nv_bfloat16* Ah = g_hh + (size_t)(m0 + bm) * KD;
    const __nv_bfloat16* Al = g_hl + (size_t)(m0 + bm) * KD;
    const __nv_bfloat16* Bh = g_wdh + (size_t)e * KD * ND + bn;
    const __nv_bfloat16* Bl = g_wdl + (size_t)e * KD * ND + bn;

    float acc[4][4][4];
    #pragma unroll
    for (int i = 0; i < 4; i++)
        #pragma unroll
        for (int j = 0; j < 4; j++)
            #pragma unroll
            for (int k = 0; k < 4; k++) acc[i][j][k] = 0.f;

    auto issue = [&](int c) {
        uint32_t sb = sbase + (uint32_t)(c & 1) * STAGE_D;
        int k0 = c * 32;
        load_A32(sb,         tid, Ah, KD, k0, va);
        load_A32(sb + 16384, tid, Al, KD, k0, va);
        load_B32(sb + 32768, tid, Bh, ND, k0);
        load_B32(sb + 40960, tid, Bl, ND, k0);
        asm volatile("cp.async.commit_group;");
    };

    issue(0);

    for (int c = 0; c < NCH; c++) {
        asm volatile("cp.async.wait_group 0;");
        __syncthreads();
        if (c + 1 < NCH) issue(c + 1);

        const uint32_t sb = sbase + (uint32_t)(c & 1) * STAGE_D;
        #pragma unroll
        for (int s16 = 0; s16 < 2; s16++) {
            // single A-frag buffer, reused hi -> lo (register diet for occ 2)
            uint32_t af[4][4];
            #pragma unroll
            for (int mt = 0; mt < 4; mt++) {
                int row = wm * 64 + mt * 16 + (lane & 15);
                uint32_t ch = (uint32_t)(2 * s16 + (lane >> 4)) ^ (uint32_t)(row & 7);
                ldm_x4(sb + (uint32_t)(row * 128) + (ch << 4), af[mt]);
            }
            const int rowb = s16 * 16 + (lane & 15);
            const uint32_t broff = (uint32_t)(rowb * 256);
            const uint32_t bxor  = (uint32_t)(rowb & 7);

            uint32_t bh[4][2], bl[4][2];
            load_bfrags(sb, 32768, 8192, wn, broff, bxor, lane, bh, bl);
            #pragma unroll
            for (int mt = 0; mt < 4; mt++)
                #pragma unroll
                for (int nt = 0; nt < 4; nt++) mma_bf16(acc[mt][nt], af[mt], bh[nt]);
            #pragma unroll
            for (int mt = 0; mt < 4; mt++)
                #pragma unroll
                for (int nt = 0; nt < 4; nt++) mma_bf16(acc[mt][nt], af[mt], bl[nt]);
            // overwrite A-frags with lo
            #pragma unroll
            for (int mt = 0; mt < 4; mt++) {
                int row = wm * 64 + mt * 16 + (lane & 15);
                uint32_t ch = (uint32_t)(2 * s16 + (lane >> 4)) ^ (uint32_t)(row & 7);
                ldm_x4(sb + 16384 + (uint32_t)(row * 128) + (ch << 4), af[mt]);
            }
            #pragma unroll
            for (int mt = 0; mt < 4; mt++)
                #pragma unroll
                for (int nt = 0; nt < 4; nt++) mma_bf16(acc[mt][nt], af[mt], bh[nt]);
        }
    }

    const int lr = lane >> 2;
    const int lc = (lane & 3) * 2;
    #pragma unroll
    for (int mt = 0; mt < 4; mt++) {
        #pragma unroll
        for (int h2 = 0; h2 < 2; h2++) {
            int r = wm * 64 + mt * 16 + lr + h2 * 8;
            if (r < va) {
                size_t grow = (size_t)(m0 + bm + r);
                float scale = g_w_of_row[grow];
                float* C = g_y + grow * ND + bn;
                #pragma unroll
                for (int nt = 0; nt < 4; nt++) {
                    int col = wn * 32 + nt * 8 + lc;
                    *(float2*)(C + col) = make_float2(acc[mt][nt][h2 * 2] * scale,
                                                      acc[mt][nt][h2 * 2 + 1] * scale);
                }
            }
        }
    }
}

// ---------------- combine ----------------
__global__ void combine_kernel(float* __restrict__ out) {
    int t  = blockIdx.x;
    int r0 = g_rows_of_token[2 * t];
    int r1 = g_rows_of_token[2 * t + 1];
    const float4* y0 = (const float4*)(g_y + (size_t)r0 * H_DIM);
    const float4* y1 = (const float4*)(g_y + (size_t)r1 * H_DIM);
    float4* o = (float4*)(out + (size_t)t * H_DIM);
    for (int i = threadIdx.x; i < H_DIM / 4; i += blockDim.x) {
        float4 a = y0[i], b = y1[i];
        o[i] = make_float4(a.x + b.x, a.y + b.y, a.z + b.z, a.w + b.w);
    }
}

// ---------------- launch ----------------
extern "C" void kernel_launch(void* const* d_in, const int* in_sizes, int n_in,
                              void* d_out, int out_size) {
    const float* x   = (const float*)d_in[0];
    const float* wg  = (const float*)d_in[1];
    const float* wgp = (const float*)d_in[2];
    const float* wup = (const float*)d_in[3];
    const float* wdp = (const float*)d_in[4];
    float* out = (float*)d_out;

    // lazy host-side stream/event setup (no device allocations; created on the
    // uncaptured correctness call, reused identically on every call thereafter)
    static cudaStream_t s1 = nullptr, s2 = nullptr;
    static cudaEvent_t  ev0 = nullptr, ev1 = nullptr, ev2 = nullptr;
    if (s1 == nullptr) {
        int lo = 0, hi = 0;
        cudaDeviceGetStreamPriorityRange(&lo, &hi);   // lo = LOWEST priority value
        cudaStreamCreateWithPriority(&s1, cudaStreamNonBlocking, lo);
        cudaStreamCreateWithPriority(&s2, cudaStreamNonBlocking, lo);
        cudaEventCreateWithFlags(&ev0, cudaEventDisableTiming);
        cudaEventCreateWithFlags(&ev1, cudaEventDisableTiming);
        cudaEventCreateWithFlags(&ev2, cudaEventDisableTiming);
    }

    cudaFuncSetAttribute(moe_gateup_kernel, cudaFuncAttributeMaxDynamicSharedMemorySize, SMEM_F);
    cudaFuncSetAttribute(moe_down_kernel,   cudaFuncAttributeMaxDynamicSharedMemorySize, SMEM_D);

    const int n4 = N_EXP * H_DIM * I_DIM / 4;

    // fork point (recorded first so split streams depend only on capture start)
    cudaEventRecord(ev0, 0);

    // routing chain on the main stream — SUBMITTED FIRST so its graph nodes
    // launch ahead of the grid-filling splits (R14 had the order inverted)
    zero_kernel<<<1, 32>>>();
    router_kernel<<<T_TOK / 8, 256>>>(x, wg);
    scan_kernel<<<1, 1>>>();
    assign_kernel<<<T_TOK / 256, 256>>>();
    gather_kernel<<<NROWS, 128>>>(x);

    // weight splits on low-priority streams (backfill around the chain)
    cudaStreamWaitEvent(s1, ev0, 0);
    split_w_gu<<<dim3(2048, 1, 2), 256, 0, s1>>>((const float4*)wgp, (const float4*)wup, n4);
    cudaEventRecord(ev1, s1);
    cudaStreamWaitEvent(s2, ev0, 0);
    split_w_d<<<2048, 256, 0, s2>>>((const float4*)wdp, n4);
    cudaEventRecord(ev2, s2);

    // join gate/up weights before gateup GEMM
    cudaStreamWaitEvent(0, ev1, 0);
    moe_gateup_kernel<<<dim3(I_DIM / 128, 272), 256, SMEM_F>>>();

    // join down weights before down GEMM (overlapped with gateup above)
    cudaStreamWaitEvent(0, ev2, 0);
    moe_down_kernel<<<dim3(H_DIM / 128, 272), 256, SMEM_D>>>();

    combine_kernel<<<T_TOK, 256>>>(out);
}